// round 1
// baseline (speedup 1.0000x reference)
#include <cuda_runtime.h>

// Problem constants
#define NB 2
#define NS 2048
#define NE 1024
#define NH 16
#define NHD 64
#define NM (NB * NS)      // 4096 rows
#define NQKV (3 * NE)     // 3072

// Scratch buffers (allocation-free rule: __device__ globals)
__device__ float g_qkv[(size_t)NM * NQKV];   // 48 MB
__device__ float g_ctx[(size_t)NM * NE];     // 16 MB

// ---------------------------------------------------------------------------
// NT SGEMM + bias: C[m][n] = sum_k A[m][k] * W[n][k] + bias[n]
// A: [Mdim, Kdim] row-major, W: [Ndim, Kdim] row-major.
// 128x128 tile, BK=8, 256 threads, 8x8 microtile per thread.
// Requires Mdim%128==0, Ndim%128==0, Kdim%8==0 (true for all our shapes).
// ---------------------------------------------------------------------------
__global__ __launch_bounds__(256) void sgemm_nt_bias(
    const float* __restrict__ A, const float* __restrict__ W,
    const float* __restrict__ bias, float* __restrict__ C,
    int Mdim, int Ndim, int Kdim)
{
    __shared__ __align__(16) float As[8][132];
    __shared__ __align__(16) float Bs[8][132];

    const int tid = threadIdx.x;
    const int tx  = tid & 15;      // 0..15
    const int ty  = tid >> 4;      // 0..15
    const int bm  = blockIdx.y * 128;
    const int bn  = blockIdx.x * 128;

    const int lrow = tid >> 1;          // 0..127
    const int lseg = (tid & 1) * 4;     // 0 or 4

    float acc[8][8] = {};

    for (int kt = 0; kt < Kdim; kt += 8) {
        float4 av = *(const float4*)&A[(size_t)(bm + lrow) * Kdim + kt + lseg];
        float4 wv = *(const float4*)&W[(size_t)(bn + lrow) * Kdim + kt + lseg];
        As[lseg + 0][lrow] = av.x;
        As[lseg + 1][lrow] = av.y;
        As[lseg + 2][lrow] = av.z;
        As[lseg + 3][lrow] = av.w;
        Bs[lseg + 0][lrow] = wv.x;
        Bs[lseg + 1][lrow] = wv.y;
        Bs[lseg + 2][lrow] = wv.z;
        Bs[lseg + 3][lrow] = wv.w;
        __syncthreads();

        #pragma unroll
        for (int kk = 0; kk < 8; kk++) {
            float a[8], b[8];
            *(float4*)&a[0] = *(const float4*)&As[kk][ty * 8];
            *(float4*)&a[4] = *(const float4*)&As[kk][ty * 8 + 4];
            *(float4*)&b[0] = *(const float4*)&Bs[kk][tx * 8];
            *(float4*)&b[4] = *(const float4*)&Bs[kk][tx * 8 + 4];
            #pragma unroll
            for (int i = 0; i < 8; i++)
                #pragma unroll
                for (int j = 0; j < 8; j++)
                    acc[i][j] = fmaf(a[i], b[j], acc[i][j]);
        }
        __syncthreads();
    }

    #pragma unroll
    for (int i = 0; i < 8; i++) {
        const int row = bm + ty * 8 + i;
        #pragma unroll
        for (int j = 0; j < 8; j += 4) {
            const int col = bn + tx * 8 + j;
            float4 v;
            v.x = acc[i][j + 0] + bias[col + 0];
            v.y = acc[i][j + 1] + bias[col + 1];
            v.z = acc[i][j + 2] + bias[col + 2];
            v.w = acc[i][j + 3] + bias[col + 3];
            *(float4*)&C[(size_t)row * Ndim + col] = v;
        }
    }
}

// ---------------------------------------------------------------------------
// Flash attention (non-causal), fp32.
// Block: 256 threads, handles one (b, h, 64-row q tile).
// Tiles of 64 keys; online softmax; P routed through SMEM for the PV GEMM.
// Layouts: Qt/Kt are d-major [64][68] (transposed), Vs/Ps row-major [64][68].
// ---------------------------------------------------------------------------
#define SMEM_TILE (64 * 68)
#define ATTN_SMEM (4 * SMEM_TILE * 4)   // 69632 bytes

__global__ __launch_bounds__(256) void attn_kernel(
    const float* __restrict__ qkv, float* __restrict__ ctx)
{
    extern __shared__ __align__(16) float sm[];
    float* Qt = sm;                  // [d][m]
    float* Kt = sm + SMEM_TILE;      // [d][n]
    float* Vs = sm + 2 * SMEM_TILE;  // [key][d]
    float* Ps = sm + 3 * SMEM_TILE;  // [m][key]

    const int tid = threadIdx.x;
    const int tx  = tid & 15;
    const int ty  = tid >> 4;
    const int bq  = blockIdx.x * 64;
    const int h   = blockIdx.y;
    const int b   = blockIdx.z;

    const float* base = qkv + (size_t)b * NS * NQKV + h * (3 * NHD);

    // Load Q tile transposed, pre-scaled by 1/sqrt(HD) = 0.125
    #pragma unroll
    for (int it = 0; it < 4; it++) {
        int idx = it * 256 + tid;
        int row = idx >> 4;
        int c4  = idx & 15;
        float4 v = *(const float4*)(base + (size_t)(bq + row) * NQKV + c4 * 4);
        Qt[(c4 * 4 + 0) * 68 + row] = v.x * 0.125f;
        Qt[(c4 * 4 + 1) * 68 + row] = v.y * 0.125f;
        Qt[(c4 * 4 + 2) * 68 + row] = v.z * 0.125f;
        Qt[(c4 * 4 + 3) * 68 + row] = v.w * 0.125f;
    }

    float m_run[4] = {-1e30f, -1e30f, -1e30f, -1e30f};
    float l_run[4] = {0.f, 0.f, 0.f, 0.f};
    float o[4][4] = {};

    const float* kbase = base + NHD;
    const float* vbase = base + 2 * NHD;

    for (int t = 0; t < NS / 64; t++) {
        __syncthreads();  // previous iteration done reading Kt/Vs/Ps

        // Load K tile (transposed) and V tile (natural)
        #pragma unroll
        for (int it = 0; it < 4; it++) {
            int idx = it * 256 + tid;
            int row = idx >> 4;
            int c4  = idx & 15;
            float4 kv = *(const float4*)(kbase + (size_t)(t * 64 + row) * NQKV + c4 * 4);
            Kt[(c4 * 4 + 0) * 68 + row] = kv.x;
            Kt[(c4 * 4 + 1) * 68 + row] = kv.y;
            Kt[(c4 * 4 + 2) * 68 + row] = kv.z;
            Kt[(c4 * 4 + 3) * 68 + row] = kv.w;
            float4 vv = *(const float4*)(vbase + (size_t)(t * 64 + row) * NQKV + c4 * 4);
            *(float4*)(Vs + row * 68 + c4 * 4) = vv;
        }
        __syncthreads();

        // Score GEMM: s[m][n] = sum_d Qt[d][m] * Kt[d][n]
        float s[4][4] = {};
        #pragma unroll 8
        for (int d = 0; d < 64; d++) {
            float a[4], k4[4];
            *(float4*)a  = *(const float4*)(Qt + d * 68 + ty * 4);
            *(float4*)k4 = *(const float4*)(Kt + d * 68 + tx * 4);
            #pragma unroll
            for (int i = 0; i < 4; i++)
                #pragma unroll
                for (int j = 0; j < 4; j++)
                    s[i][j] = fmaf(a[i], k4[j], s[i][j]);
        }

        // Online softmax per row (16-lane row groups = half-warps)
        #pragma unroll
        for (int i = 0; i < 4; i++) {
            float tmax = fmaxf(fmaxf(s[i][0], s[i][1]), fmaxf(s[i][2], s[i][3]));
            #pragma unroll
            for (int off = 8; off; off >>= 1)
                tmax = fmaxf(tmax, __shfl_xor_sync(0xffffffffu, tmax, off));
            float m_new = fmaxf(m_run[i], tmax);
            float corr  = __expf(m_run[i] - m_new);
            float rs = 0.f;
            #pragma unroll
            for (int j = 0; j < 4; j++) {
                s[i][j] = __expf(s[i][j] - m_new);
                rs += s[i][j];
            }
            #pragma unroll
            for (int off = 8; off; off >>= 1)
                rs += __shfl_xor_sync(0xffffffffu, rs, off);
            l_run[i] = l_run[i] * corr + rs;
            m_run[i] = m_new;
            #pragma unroll
            for (int j = 0; j < 4; j++) o[i][j] *= corr;
            *(float4*)(Ps + (ty * 4 + i) * 68 + tx * 4) =
                make_float4(s[i][0], s[i][1], s[i][2], s[i][3]);
        }
        __syncthreads();  // Ps visible to all

        // PV GEMM: o[m][d] += sum_key Ps[m][key] * Vs[key][d]
        #pragma unroll 8
        for (int kk = 0; kk < 64; kk++) {
            float bv[4];
            *(float4*)bv = *(const float4*)(Vs + kk * 68 + tx * 4);
            #pragma unroll
            for (int i = 0; i < 4; i++) {
                float a = Ps[(ty * 4 + i) * 68 + kk];
                #pragma unroll
                for (int j = 0; j < 4; j++)
                    o[i][j] = fmaf(a, bv[j], o[i][j]);
            }
        }
    }

    // Epilogue: normalize and write ctx[(b*S+row)*E + h*64 + d]
    #pragma unroll
    for (int i = 0; i < 4; i++) {
        float inv = 1.0f / l_run[i];
        int row = bq + ty * 4 + i;
        float4 v = make_float4(o[i][0] * inv, o[i][1] * inv,
                               o[i][2] * inv, o[i][3] * inv);
        *(float4*)(ctx + ((size_t)b * NS + row) * NE + h * NHD + tx * 4) = v;
    }
}

// ---------------------------------------------------------------------------
extern "C" void kernel_launch(void* const* d_in, const int* in_sizes, int n_in,
                              void* d_out, int out_size)
{
    const float* x     = (const float*)d_in[0];
    const float* W_qkv = (const float*)d_in[1];
    const float* b_qkv = (const float*)d_in[2];
    const float* W_out = (const float*)d_in[3];
    const float* b_out = (const float*)d_in[4];
    float* out = (float*)d_out;

    float* qkv = nullptr;
    float* ctx = nullptr;
    cudaGetSymbolAddress((void**)&qkv, g_qkv);
    cudaGetSymbolAddress((void**)&ctx, g_ctx);

    cudaFuncSetAttribute(attn_kernel,
                         cudaFuncAttributeMaxDynamicSharedMemorySize, ATTN_SMEM);

    // 1) QKV projection: [4096,1024] x [3072,1024]^T -> [4096,3072]
    dim3 g1(NQKV / 128, NM / 128);
    sgemm_nt_bias<<<g1, 256>>>(x, W_qkv, b_qkv, qkv, NM, NQKV, NE);

    // 2) Flash attention per (q-tile, head, batch)
    dim3 g2(NS / 64, NH, NB);
    attn_kernel<<<g2, 256, ATTN_SMEM>>>(qkv, ctx);

    // 3) Output projection: [4096,1024] x [1024,1024]^T -> [4096,1024]
    dim3 g3(NE / 128, NM / 128);
    sgemm_nt_bias<<<g3, 256>>>(ctx, W_out, b_out, out, NM, NE, NE);
}

// round 2
// speedup vs baseline: 2.7757x; 2.7757x over previous
#include <cuda_runtime.h>
#include <cuda_bf16.h>

// Problem constants
#define NB 2
#define NS 2048
#define NE 1024
#define NH 16
#define NHD 64
#define NM (NB * NS)      // 4096
#define NQKV (3 * NE)     // 3072

// Scratch (allocation-free rule: __device__ globals)
__device__ float g_qkv[(size_t)NM * NQKV];   // 48 MB
__device__ float g_ctx[(size_t)NM * NE];     // 16 MB

// ---------------------------------------------------------------------------
// helpers
// ---------------------------------------------------------------------------
__device__ __forceinline__ unsigned f2tf32(float x) {
    unsigned u;
    asm("cvt.rna.tf32.f32 %0, %1;" : "=r"(u) : "f"(x));
    return u;
}

__device__ __forceinline__ void mma_tf32(float* d, const unsigned* a,
                                         const unsigned* b, const float* c) {
    asm volatile(
        "mma.sync.aligned.m16n8k8.row.col.f32.tf32.tf32.f32 "
        "{%0,%1,%2,%3}, {%4,%5,%6,%7}, {%8,%9}, {%10,%11,%12,%13};"
        : "=f"(d[0]), "=f"(d[1]), "=f"(d[2]), "=f"(d[3])
        : "r"(a[0]), "r"(a[1]), "r"(a[2]), "r"(a[3]),
          "r"(b[0]), "r"(b[1]),
          "f"(c[0]), "f"(c[1]), "f"(c[2]), "f"(c[3]));
}

__device__ __forceinline__ void mma_bf16(float* d, const unsigned* a,
                                         const unsigned* b, const float* c) {
    asm volatile(
        "mma.sync.aligned.m16n8k16.row.col.f32.bf16.bf16.f32 "
        "{%0,%1,%2,%3}, {%4,%5,%6,%7}, {%8,%9}, {%10,%11,%12,%13};"
        : "=f"(d[0]), "=f"(d[1]), "=f"(d[2]), "=f"(d[3])
        : "r"(a[0]), "r"(a[1]), "r"(a[2]), "r"(a[3]),
          "r"(b[0]), "r"(b[1]),
          "f"(c[0]), "f"(c[1]), "f"(c[2]), "f"(c[3]));
}

__device__ __forceinline__ unsigned pack_bf16(float e0, float e1) {
    // e0 -> low 16 bits (k even), e1 -> high 16 bits (k odd)
    __nv_bfloat162 t = __floats2bfloat162_rn(e0, e1);
    return *reinterpret_cast<unsigned*>(&t);
}

// ---------------------------------------------------------------------------
// TF32 NT GEMM + bias: C[m][n] = sum_k A[m][k]*W[n][k] + bias[n]
// 128x128 block tile, BK=32, 256 threads, warp grid 2x4, warp tile 64x32.
// ---------------------------------------------------------------------------
__global__ __launch_bounds__(256) void gemm_tf32_nt_bias(
    const float* __restrict__ A, const float* __restrict__ W,
    const float* __restrict__ bias, float* __restrict__ C,
    int Mdim, int Ndim, int Kdim)
{
    __shared__ unsigned As[128][36];   // stride 36: (36 mod 32)=4 -> conflict-free frags
    __shared__ unsigned Ws[128][36];

    const int tid  = threadIdx.x;
    const int wid  = tid >> 5;
    const int lane = tid & 31;
    const int mg   = wid >> 2;        // 0..1
    const int ng   = wid & 3;         // 0..3
    const int bm   = blockIdx.y * 128;
    const int bn   = blockIdx.x * 128;
    const int lq   = lane >> 2;       // 0..7
    const int lr   = lane & 3;        // 0..3

    float acc[4][4][4] = {};          // [mt][nt][frag]

    for (int kt = 0; kt < Kdim; kt += 32) {
        #pragma unroll
        for (int i = 0; i < 4; i++) {
            int idx = i * 256 + tid;          // 0..1023 = 128 rows x 8 segs
            int row = idx >> 3;
            int seg = idx & 7;
            float4 va = *(const float4*)&A[(size_t)(bm + row) * Kdim + kt + seg * 4];
            As[row][seg * 4 + 0] = f2tf32(va.x);
            As[row][seg * 4 + 1] = f2tf32(va.y);
            As[row][seg * 4 + 2] = f2tf32(va.z);
            As[row][seg * 4 + 3] = f2tf32(va.w);
            float4 vw = *(const float4*)&W[(size_t)(bn + row) * Kdim + kt + seg * 4];
            Ws[row][seg * 4 + 0] = f2tf32(vw.x);
            Ws[row][seg * 4 + 1] = f2tf32(vw.y);
            Ws[row][seg * 4 + 2] = f2tf32(vw.z);
            Ws[row][seg * 4 + 3] = f2tf32(vw.w);
        }
        __syncthreads();

        #pragma unroll
        for (int k8 = 0; k8 < 4; k8++) {
            unsigned a[4][4], b[4][2];
            const int kk = k8 * 8 + lr;
            #pragma unroll
            for (int mt = 0; mt < 4; mt++) {
                int r = mg * 64 + mt * 16 + lq;
                a[mt][0] = As[r][kk];
                a[mt][1] = As[r + 8][kk];
                a[mt][2] = As[r][kk + 4];
                a[mt][3] = As[r + 8][kk + 4];
            }
            #pragma unroll
            for (int nt = 0; nt < 4; nt++) {
                int n = ng * 32 + nt * 8 + lq;
                b[nt][0] = Ws[n][kk];
                b[nt][1] = Ws[n][kk + 4];
            }
            #pragma unroll
            for (int mt = 0; mt < 4; mt++)
                #pragma unroll
                for (int nt = 0; nt < 4; nt++)
                    mma_tf32(acc[mt][nt], a[mt], b[nt], acc[mt][nt]);
        }
        __syncthreads();
    }

    // epilogue
    #pragma unroll
    for (int mt = 0; mt < 4; mt++) {
        int r0 = bm + mg * 64 + mt * 16 + lq;
        #pragma unroll
        for (int nt = 0; nt < 4; nt++) {
            int col = bn + ng * 32 + nt * 8 + lr * 2;
            float2 bv = *(const float2*)&bias[col];
            float2 v0 = make_float2(acc[mt][nt][0] + bv.x, acc[mt][nt][1] + bv.y);
            float2 v1 = make_float2(acc[mt][nt][2] + bv.x, acc[mt][nt][3] + bv.y);
            *(float2*)&C[(size_t)r0 * Ndim + col]       = v0;
            *(float2*)&C[(size_t)(r0 + 8) * Ndim + col] = v1;
        }
    }
}

// ---------------------------------------------------------------------------
// Flash attention, tensor-core version.
// Block = one (b, h, 128-q-row tile), 256 threads = 8 warps.
// Warp grid 4x2: mg=wid>>1 (32 q-rows each), ng=wid&1 (64-key slice).
// QK^T in tf32 (Q,K tf32 in smem); softmax in fp32 registers;
// PV in bf16 split-3 (P fragments built in registers from QK C-frags,
// V split hi/lo transposed in smem). Key-block = 128.
// ---------------------------------------------------------------------------
// smem layout (u32 offsets)
#define OFF_Q   0                    // [128][68] u32 (tf32)
#define OFF_K   8704                 // [128][68] u32 (tf32)
#define OFF_VHI 17408                // [64][68] u32 = bf16 [64][136]
#define OFF_VLO 21760                // [64][68]
#define OFF_RMX 26112                // float [2][128]
#define OFF_RSM 26368                // float [2][128]
#define ATTN_SMEM_WORDS 26624
#define ATTN_SMEM_BYTES (ATTN_SMEM_WORDS * 4)

__global__ __launch_bounds__(256) void attn_tc(
    const float* __restrict__ qkv, float* __restrict__ ctx)
{
    extern __shared__ __align__(16) unsigned sm[];
    unsigned* Qs  = sm + OFF_Q;      // stride 68
    unsigned* Ks  = sm + OFF_K;      // stride 68
    __nv_bfloat16* Vhi = (__nv_bfloat16*)(sm + OFF_VHI);  // [d][key], stride 136
    __nv_bfloat16* Vlo = (__nv_bfloat16*)(sm + OFF_VLO);
    float* rmax = (float*)(sm + OFF_RMX);                 // [ng][row]
    float* rsum = (float*)(sm + OFF_RSM);

    const int tid  = threadIdx.x;
    const int wid  = tid >> 5;
    const int lane = tid & 31;
    const int mg   = wid >> 1;       // 0..3
    const int ng   = wid & 1;        // 0..1
    const int lq   = lane >> 2;
    const int lr   = lane & 3;
    const int q0   = blockIdx.x * 128;
    const int h    = blockIdx.y;
    const int b    = blockIdx.z;

    const float* base  = qkv + (size_t)b * NS * NQKV + h * (3 * NHD);
    const float* kbase = base + NHD;
    const float* vbase = base + 2 * NHD;

    // Load Q tile (pre-scaled) as tf32
    #pragma unroll
    for (int i = 0; i < 8; i++) {
        int idx = i * 256 + tid;         // 2048 = 128 rows x 16 segs
        int row = idx >> 4;
        int seg = idx & 15;
        float4 v = *(const float4*)(base + (size_t)(q0 + row) * NQKV + seg * 4);
        Qs[row * 68 + seg * 4 + 0] = f2tf32(v.x * 0.125f);
        Qs[row * 68 + seg * 4 + 1] = f2tf32(v.y * 0.125f);
        Qs[row * 68 + seg * 4 + 2] = f2tf32(v.z * 0.125f);
        Qs[row * 68 + seg * 4 + 3] = f2tf32(v.w * 0.125f);
    }

    float o[2][8][4] = {};
    float m_run[2][2] = {{-1e30f, -1e30f}, {-1e30f, -1e30f}};
    float l_run[2][2] = {};

    for (int t = 0; t < NS / 128; t++) {
        __syncthreads();   // previous iter done reading K/V smem

        // Load K (tf32 [key][d]) and V (bf16 split, transposed [d][key])
        #pragma unroll
        for (int i = 0; i < 8; i++) {
            int idx = i * 256 + tid;
            int key = idx >> 4;
            int seg = idx & 15;
            float4 kv = *(const float4*)(kbase + (size_t)(t * 128 + key) * NQKV + seg * 4);
            Ks[key * 68 + seg * 4 + 0] = f2tf32(kv.x);
            Ks[key * 68 + seg * 4 + 1] = f2tf32(kv.y);
            Ks[key * 68 + seg * 4 + 2] = f2tf32(kv.z);
            Ks[key * 68 + seg * 4 + 3] = f2tf32(kv.w);
            float4 vv = *(const float4*)(vbase + (size_t)(t * 128 + key) * NQKV + seg * 4);
            float vf[4] = {vv.x, vv.y, vv.z, vv.w};
            #pragma unroll
            for (int j = 0; j < 4; j++) {
                int d = seg * 4 + j;
                __nv_bfloat16 hi = __float2bfloat16_rn(vf[j]);
                float lo = vf[j] - __bfloat162float(hi);
                Vhi[d * 136 + key] = hi;
                Vlo[d * 136 + key] = __float2bfloat16_rn(lo);
            }
        }
        __syncthreads();

        // ---- QK^T (tf32): s[mt][nt][4], 32 rows x 64 keys per warp ----
        float s[2][8][4] = {};
        #pragma unroll
        for (int k8 = 0; k8 < 8; k8++) {
            const int kk = k8 * 8 + lr;
            unsigned a[2][4], kb[8][2];
            #pragma unroll
            for (int mt = 0; mt < 2; mt++) {
                int r = mg * 32 + mt * 16 + lq;
                a[mt][0] = Qs[r * 68 + kk];
                a[mt][1] = Qs[(r + 8) * 68 + kk];
                a[mt][2] = Qs[r * 68 + kk + 4];
                a[mt][3] = Qs[(r + 8) * 68 + kk + 4];
            }
            #pragma unroll
            for (int nt = 0; nt < 8; nt++) {
                int n = ng * 64 + nt * 8 + lq;
                kb[nt][0] = Ks[n * 68 + kk];
                kb[nt][1] = Ks[n * 68 + kk + 4];
            }
            #pragma unroll
            for (int mt = 0; mt < 2; mt++)
                #pragma unroll
                for (int nt = 0; nt < 8; nt++)
                    mma_tf32(s[mt][nt], a[mt], kb[nt], s[mt][nt]);
        }

        // ---- online softmax ----
        float mloc[2][2];
        #pragma unroll
        for (int mt = 0; mt < 2; mt++) {
            #pragma unroll
            for (int hf = 0; hf < 2; hf++) {
                float v = -1e30f;
                #pragma unroll
                for (int nt = 0; nt < 8; nt++) {
                    v = fmaxf(v, s[mt][nt][hf * 2 + 0]);
                    v = fmaxf(v, s[mt][nt][hf * 2 + 1]);
                }
                v = fmaxf(v, __shfl_xor_sync(0xffffffffu, v, 1));
                v = fmaxf(v, __shfl_xor_sync(0xffffffffu, v, 2));
                mloc[mt][hf] = v;
                if (lr == 0)
                    rmax[ng * 128 + mg * 32 + mt * 16 + hf * 8 + lq] = v;
            }
        }
        __syncthreads();

        float corr[2][2];
        #pragma unroll
        for (int mt = 0; mt < 2; mt++) {
            #pragma unroll
            for (int hf = 0; hf < 2; hf++) {
                int row = mg * 32 + mt * 16 + hf * 8 + lq;
                float m_blk = fmaxf(rmax[row], rmax[128 + row]);
                float m_new = fmaxf(m_run[mt][hf], m_blk);
                corr[mt][hf] = __expf(m_run[mt][hf] - m_new);
                m_run[mt][hf] = m_new;
                float rs = 0.f;
                #pragma unroll
                for (int nt = 0; nt < 8; nt++) {
                    float p0 = __expf(s[mt][nt][hf * 2 + 0] - m_new);
                    float p1 = __expf(s[mt][nt][hf * 2 + 1] - m_new);
                    s[mt][nt][hf * 2 + 0] = p0;
                    s[mt][nt][hf * 2 + 1] = p1;
                    rs += p0 + p1;
                }
                rs += __shfl_xor_sync(0xffffffffu, rs, 1);
                rs += __shfl_xor_sync(0xffffffffu, rs, 2);
                if (lr == 0)
                    rsum[ng * 128 + row] = rs;
                // rescale running output
                #pragma unroll
                for (int nt = 0; nt < 8; nt++) {
                    o[mt][nt][hf * 2 + 0] *= corr[mt][hf];
                    o[mt][nt][hf * 2 + 1] *= corr[mt][hf];
                }
            }
        }
        __syncthreads();

        #pragma unroll
        for (int mt = 0; mt < 2; mt++)
            #pragma unroll
            for (int hf = 0; hf < 2; hf++) {
                int row = mg * 32 + mt * 16 + hf * 8 + lq;
                l_run[mt][hf] = l_run[mt][hf] * corr[mt][hf]
                              + rsum[row] + rsum[128 + row];
            }

        // ---- PV (bf16 split-3): keys = ng*64 .. +64, out d = 64 ----
        #pragma unroll
        for (int kc = 0; kc < 4; kc++) {           // k16 chunks
            unsigned ahi[2][4], alo[2][4];
            #pragma unroll
            for (int mt = 0; mt < 2; mt++) {
                #pragma unroll
                for (int half = 0; half < 2; half++) {     // which C n-tile of the pair
                    int ct = kc * 2 + half;
                    #pragma unroll
                    for (int rh = 0; rh < 2; rh++) {        // row / row+8
                        float p0 = s[mt][ct][rh * 2 + 0];
                        float p1 = s[mt][ct][rh * 2 + 1];
                        __nv_bfloat16 h0 = __float2bfloat16_rn(p0);
                        __nv_bfloat16 h1 = __float2bfloat16_rn(p1);
                        float l0 = p0 - __bfloat162float(h0);
                        float l1 = p1 - __bfloat162float(h1);
                        __nv_bfloat162 hp;
                        hp.x = h0; hp.y = h1;
                        ahi[mt][half * 2 + rh] = *reinterpret_cast<unsigned*>(&hp);
                        alo[mt][half * 2 + rh] = pack_bf16(l0, l1);
                    }
                }
            }
            #pragma unroll
            for (int nt = 0; nt < 8; nt++) {
                int d = nt * 8 + lq;
                int u = d * 68 + ng * 32 + kc * 8 + lr;   // u32 index, pairs along key
                unsigned bhi[2], blo[2];
                bhi[0] = ((unsigned*)Vhi)[u];
                bhi[1] = ((unsigned*)Vhi)[u + 4];
                blo[0] = ((unsigned*)Vlo)[u];
                blo[1] = ((unsigned*)Vlo)[u + 4];
                #pragma unroll
                for (int mt = 0; mt < 2; mt++) {
                    mma_bf16(o[mt][nt], ahi[mt], bhi, o[mt][nt]);
                    mma_bf16(o[mt][nt], ahi[mt], blo, o[mt][nt]);
                    mma_bf16(o[mt][nt], alo[mt], bhi, o[mt][nt]);
                }
            }
        }
    }

    // ---- epilogue: cross-warp (ng) reduction, normalize, store ----
    __syncthreads();
    float* Os = (float*)(sm + OFF_K);   // reuse K region: [128][68] floats
    if (ng == 1) {
        #pragma unroll
        for (int mt = 0; mt < 2; mt++) {
            int r = mg * 32 + mt * 16 + lq;
            #pragma unroll
            for (int nt = 0; nt < 8; nt++) {
                int d = nt * 8 + lr * 2;
                *(float2*)&Os[r * 68 + d] =
                    make_float2(o[mt][nt][0], o[mt][nt][1]);
                *(float2*)&Os[(r + 8) * 68 + d] =
                    make_float2(o[mt][nt][2], o[mt][nt][3]);
            }
        }
    }
    __syncthreads();
    if (ng == 0) {
        #pragma unroll
        for (int mt = 0; mt < 2; mt++) {
            int r = mg * 32 + mt * 16 + lq;
            float inv0 = 1.0f / l_run[mt][0];
            float inv1 = 1.0f / l_run[mt][1];
            #pragma unroll
            for (int nt = 0; nt < 8; nt++) {
                int d = nt * 8 + lr * 2;
                float2 p0 = *(const float2*)&Os[r * 68 + d];
                float2 p1 = *(const float2*)&Os[(r + 8) * 68 + d];
                float2 v0 = make_float2((o[mt][nt][0] + p0.x) * inv0,
                                        (o[mt][nt][1] + p0.y) * inv0);
                float2 v1 = make_float2((o[mt][nt][2] + p1.x) * inv1,
                                        (o[mt][nt][3] + p1.y) * inv1);
                size_t g0 = ((size_t)b * NS + q0 + r) * NE + h * NHD + d;
                size_t g1 = ((size_t)b * NS + q0 + r + 8) * NE + h * NHD + d;
                *(float2*)&ctx[g0] = v0;
                *(float2*)&ctx[g1] = v1;
            }
        }
    }
}

// ---------------------------------------------------------------------------
extern "C" void kernel_launch(void* const* d_in, const int* in_sizes, int n_in,
                              void* d_out, int out_size)
{
    const float* x     = (const float*)d_in[0];
    const float* W_qkv = (const float*)d_in[1];
    const float* b_qkv = (const float*)d_in[2];
    const float* W_out = (const float*)d_in[3];
    const float* b_out = (const float*)d_in[4];
    float* out = (float*)d_out;

    float* qkv = nullptr;
    float* ctx = nullptr;
    cudaGetSymbolAddress((void**)&qkv, g_qkv);
    cudaGetSymbolAddress((void**)&ctx, g_ctx);

    cudaFuncSetAttribute(attn_tc,
                         cudaFuncAttributeMaxDynamicSharedMemorySize,
                         ATTN_SMEM_BYTES);

    // 1) QKV projection
    dim3 g1(NQKV / 128, NM / 128);
    gemm_tf32_nt_bias<<<g1, 256>>>(x, W_qkv, b_qkv, qkv, NM, NQKV, NE);

    // 2) Flash attention
    dim3 g2(NS / 128, NH, NB);
    attn_tc<<<g2, 256, ATTN_SMEM_BYTES>>>(qkv, ctx);

    // 3) Output projection
    dim3 g3(NE / 128, NM / 128);
    gemm_tf32_nt_bias<<<g3, 256>>>(ctx, W_out, b_out, out, NM, NE, NE);
}

// round 3
// speedup vs baseline: 3.7827x; 1.3628x over previous
#include <cuda_runtime.h>

// Problem constants
#define NB 2
#define NS 2048
#define NE 1024
#define NH 16
#define NHD 64
#define NM (NB * NS)      // 4096
#define NQKV (3 * NE)     // 3072

// Scratch (allocation-free rule: __device__ globals). All tf32-in-u32.
__device__ unsigned g_qkv[(size_t)NM * NQKV];    // 48 MB
__device__ unsigned g_ctx[(size_t)NM * NE];      // 16 MB
__device__ unsigned g_xt[(size_t)NM * NE];       // 16 MB
__device__ unsigned g_wqkvt[(size_t)NQKV * NE];  // 12 MB
__device__ unsigned g_wot[(size_t)NE * NE];      // 4 MB

// ---------------------------------------------------------------------------
// helpers
// ---------------------------------------------------------------------------
__device__ __forceinline__ unsigned f2tf32(float x) {
    unsigned u;
    asm("cvt.rna.tf32.f32 %0, %1;" : "=r"(u) : "f"(x));
    return u;
}

__device__ __forceinline__ void mma_tf32(float* d, const unsigned* a,
                                         const unsigned* b, const float* c) {
    asm volatile(
        "mma.sync.aligned.m16n8k8.row.col.f32.tf32.tf32.f32 "
        "{%0,%1,%2,%3}, {%4,%5,%6,%7}, {%8,%9}, {%10,%11,%12,%13};"
        : "=f"(d[0]), "=f"(d[1]), "=f"(d[2]), "=f"(d[3])
        : "r"(a[0]), "r"(a[1]), "r"(a[2]), "r"(a[3]),
          "r"(b[0]), "r"(b[1]),
          "f"(c[0]), "f"(c[1]), "f"(c[2]), "f"(c[3]));
}

__device__ __forceinline__ unsigned sptr(const void* p) {
    return (unsigned)__cvta_generic_to_shared(p);
}
#define CP16(dst_s, src_g) \
    asm volatile("cp.async.cg.shared.global [%0], [%1], 16;" \
                 :: "r"(dst_s), "l"(src_g))
#define CPCOMMIT() asm volatile("cp.async.commit_group;")
#define CPWAIT0()  asm volatile("cp.async.wait_group 0;")

// ---------------------------------------------------------------------------
// Elementwise fp32 -> tf32 (RNA) pre-conversion
// ---------------------------------------------------------------------------
__global__ __launch_bounds__(256) void cvt_tf32(
    const float4* __restrict__ src, uint4* __restrict__ dst)
{
    int i = blockIdx.x * 256 + threadIdx.x;
    float4 v = src[i];
    uint4 u;
    u.x = f2tf32(v.x); u.y = f2tf32(v.y);
    u.z = f2tf32(v.z); u.w = f2tf32(v.w);
    dst[i] = u;
}

// ---------------------------------------------------------------------------
// TF32 NT GEMM + bias, pre-converted tf32 inputs, cp.async double-buffered.
// C[m][n] = sum_k A[m][k]*W[n][k] + bias[n]
// 128x128 tile, BK=32, 256 threads, warp grid 2x4, warp tile 64x32.
// OUT_TF32: store tf32-u32 (intermediates); else fp32.
// ---------------------------------------------------------------------------
#define GEMM_SMEM_WORDS (4 * 128 * 36)
#define GEMM_SMEM_BYTES (GEMM_SMEM_WORDS * 4)

template <bool OUT_TF32>
__global__ __launch_bounds__(256) void gemm_tt(
    const unsigned* __restrict__ A, const unsigned* __restrict__ W,
    const float* __restrict__ bias, void* __restrict__ Cv,
    int Mdim, int Ndim, int Kdim)
{
    extern __shared__ unsigned smg[];
    unsigned* Asm = smg;                 // [2][128*36]
    unsigned* Wsm = smg + 2 * 128 * 36;  // [2][128*36]

    const int tid  = threadIdx.x;
    const int wid  = tid >> 5;
    const int lane = tid & 31;
    const int mg   = wid >> 2;
    const int ng   = wid & 3;
    const int bm   = blockIdx.y * 128;
    const int bn   = blockIdx.x * 128;
    const int lq   = lane >> 2;
    const int lr   = lane & 3;

    const int frow = tid >> 3;           // 0..31 within 4-round fill -> rows
    const int fseg = (tid & 7) * 4;

    float acc[4][4][4] = {};

    // fill one k-tile into buffer `buf`
    auto fill = [&](int kt, int buf) {
        unsigned* Ad = Asm + buf * 4608;
        unsigned* Wd = Wsm + buf * 4608;
        #pragma unroll
        for (int i = 0; i < 4; i++) {
            int row = i * 32 + frow;
            CP16(sptr(Ad + row * 36 + fseg),
                 A + (size_t)(bm + row) * Kdim + kt + fseg);
            CP16(sptr(Wd + row * 36 + fseg),
                 W + (size_t)(bn + row) * Kdim + kt + fseg);
        }
        CPCOMMIT();
    };

    fill(0, 0);
    int buf = 0;
    for (int kt = 0; kt < Kdim; kt += 32) {
        CPWAIT0();
        __syncthreads();
        if (kt + 32 < Kdim) fill(kt + 32, buf ^ 1);

        const unsigned* Ab = Asm + buf * 4608;
        const unsigned* Wb = Wsm + buf * 4608;
        #pragma unroll
        for (int k8 = 0; k8 < 4; k8++) {
            const int kk = k8 * 8 + lr;
            unsigned a[4][4], b[4][2];
            #pragma unroll
            for (int mt = 0; mt < 4; mt++) {
                int r = mg * 64 + mt * 16 + lq;
                a[mt][0] = Ab[r * 36 + kk];
                a[mt][1] = Ab[(r + 8) * 36 + kk];
                a[mt][2] = Ab[r * 36 + kk + 4];
                a[mt][3] = Ab[(r + 8) * 36 + kk + 4];
            }
            #pragma unroll
            for (int nt = 0; nt < 4; nt++) {
                int n = ng * 32 + nt * 8 + lq;
                b[nt][0] = Wb[n * 36 + kk];
                b[nt][1] = Wb[n * 36 + kk + 4];
            }
            #pragma unroll
            for (int mt = 0; mt < 4; mt++)
                #pragma unroll
                for (int nt = 0; nt < 4; nt++)
                    mma_tf32(acc[mt][nt], a[mt], b[nt], acc[mt][nt]);
        }
        buf ^= 1;
    }

    // epilogue
    #pragma unroll
    for (int mt = 0; mt < 4; mt++) {
        int r0 = bm + mg * 64 + mt * 16 + lq;
        #pragma unroll
        for (int nt = 0; nt < 4; nt++) {
            int col = bn + ng * 32 + nt * 8 + lr * 2;
            float2 bv = *(const float2*)&bias[col];
            float v00 = acc[mt][nt][0] + bv.x;
            float v01 = acc[mt][nt][1] + bv.y;
            float v10 = acc[mt][nt][2] + bv.x;
            float v11 = acc[mt][nt][3] + bv.y;
            if (OUT_TF32) {
                unsigned* C = (unsigned*)Cv;
                uint2 u0 = make_uint2(f2tf32(v00), f2tf32(v01));
                uint2 u1 = make_uint2(f2tf32(v10), f2tf32(v11));
                *(uint2*)&C[(size_t)r0 * Ndim + col]       = u0;
                *(uint2*)&C[(size_t)(r0 + 8) * Ndim + col] = u1;
            } else {
                float* C = (float*)Cv;
                *(float2*)&C[(size_t)r0 * Ndim + col]       = make_float2(v00, v01);
                *(float2*)&C[(size_t)(r0 + 8) * Ndim + col] = make_float2(v10, v11);
            }
        }
    }
}

// ---------------------------------------------------------------------------
// Flash attention, all-TF32 tensor cores, cp.async double-buffered K/V.
// Block = one (b, h, 128-q-row tile), 256 threads = 8 warps (4x2 warp grid).
// QK^T tf32; softmax fp32; PV tf32 using the k-permutation trick:
//   QK C-frag (c0,c2,c1,c3) is a valid A-frag if V's B-frag loads keys
//   {lr*2, lr*2+1} instead of {lr, lr+4} (same sum, permuted k order).
// ctx written as tf32.
// ---------------------------------------------------------------------------
#define AQ  0                    // Q   [128][68] u32
#define AK  8704                 // K   [2][128][68]
#define AV  26112                // V   [2][128][68]
#define ARM 43520                // rmax float [2][128]
#define ARS 43776                // rsum float [2][128]
#define ATTN_SMEM_BYTES (44032 * 4)

__global__ __launch_bounds__(256, 1) void attn_tc(
    const unsigned* __restrict__ qkv, unsigned* __restrict__ ctx)
{
    extern __shared__ __align__(16) unsigned sm[];
    unsigned* Qs = sm + AQ;
    float* rmax = (float*)(sm + ARM);
    float* rsum = (float*)(sm + ARS);

    const int tid  = threadIdx.x;
    const int wid  = tid >> 5;
    const int lane = tid & 31;
    const int mg   = wid >> 1;       // 0..3
    const int ng   = wid & 1;        // 0..1
    const int lq   = lane >> 2;
    const int lr   = lane & 3;
    const int q0   = blockIdx.x * 128;
    const int h    = blockIdx.y;
    const int b    = blockIdx.z;

    const unsigned* base  = qkv + (size_t)b * NS * NQKV + h * (3 * NHD);
    const unsigned* kbase = base + NHD;
    const unsigned* vbase = base + 2 * NHD;

    const int frow = tid >> 4;       // fill row base
    const int fseg = (tid & 15) * 4;

    // K/V tile fill via cp.async
    auto fillKV = [&](int t, int buf) {
        unsigned* Kd = sm + AK + buf * 8704;
        unsigned* Vd = sm + AV + buf * 8704;
        #pragma unroll
        for (int i = 0; i < 8; i++) {
            int key = i * 16 + frow;
            CP16(sptr(Kd + key * 68 + fseg),
                 kbase + (size_t)(t * 128 + key) * NQKV + fseg);
            CP16(sptr(Vd + key * 68 + fseg),
                 vbase + (size_t)(t * 128 + key) * NQKV + fseg);
        }
        CPCOMMIT();
    };

    fillKV(0, 0);

    // Q fill (tf32 in gmem already; scale by 0.125 = exact, stays tf32)
    #pragma unroll
    for (int i = 0; i < 8; i++) {
        int row = i * 16 + frow;
        uint4 v = *(const uint4*)(base + (size_t)(q0 + row) * NQKV + fseg);
        Qs[row * 68 + fseg + 0] = __float_as_uint(__uint_as_float(v.x) * 0.125f);
        Qs[row * 68 + fseg + 1] = __float_as_uint(__uint_as_float(v.y) * 0.125f);
        Qs[row * 68 + fseg + 2] = __float_as_uint(__uint_as_float(v.z) * 0.125f);
        Qs[row * 68 + fseg + 3] = __float_as_uint(__uint_as_float(v.w) * 0.125f);
    }

    float o[2][8][4] = {};
    float m_run[2][2] = {{-1e30f, -1e30f}, {-1e30f, -1e30f}};
    float l_run[2][2] = {};

    int buf = 0;
    for (int t = 0; t < NS / 128; t++) {
        CPWAIT0();
        __syncthreads();
        if (t + 1 < NS / 128) fillKV(t + 1, buf ^ 1);

        const unsigned* Ks = sm + AK + buf * 8704;
        const unsigned* Vs = sm + AV + buf * 8704;

        // ---- QK^T (tf32): 32 q-rows x 64 keys per warp ----
        float s[2][8][4] = {};
        #pragma unroll
        for (int k8 = 0; k8 < 8; k8++) {
            const int kk = k8 * 8 + lr;
            unsigned a[2][4], kb[8][2];
            #pragma unroll
            for (int mt = 0; mt < 2; mt++) {
                int r = mg * 32 + mt * 16 + lq;
                a[mt][0] = Qs[r * 68 + kk];
                a[mt][1] = Qs[(r + 8) * 68 + kk];
                a[mt][2] = Qs[r * 68 + kk + 4];
                a[mt][3] = Qs[(r + 8) * 68 + kk + 4];
            }
            #pragma unroll
            for (int nt = 0; nt < 8; nt++) {
                int n = ng * 64 + nt * 8 + lq;
                kb[nt][0] = Ks[n * 68 + kk];
                kb[nt][1] = Ks[n * 68 + kk + 4];
            }
            #pragma unroll
            for (int mt = 0; mt < 2; mt++)
                #pragma unroll
                for (int nt = 0; nt < 8; nt++)
                    mma_tf32(s[mt][nt], a[mt], kb[nt], s[mt][nt]);
        }

        // ---- online softmax ----
        #pragma unroll
        for (int mt = 0; mt < 2; mt++) {
            #pragma unroll
            for (int hf = 0; hf < 2; hf++) {
                float v = -1e30f;
                #pragma unroll
                for (int nt = 0; nt < 8; nt++) {
                    v = fmaxf(v, s[mt][nt][hf * 2 + 0]);
                    v = fmaxf(v, s[mt][nt][hf * 2 + 1]);
                }
                v = fmaxf(v, __shfl_xor_sync(0xffffffffu, v, 1));
                v = fmaxf(v, __shfl_xor_sync(0xffffffffu, v, 2));
                if (lr == 0)
                    rmax[ng * 128 + mg * 32 + mt * 16 + hf * 8 + lq] = v;
            }
        }
        __syncthreads();

        float corr[2][2];
        #pragma unroll
        for (int mt = 0; mt < 2; mt++) {
            #pragma unroll
            for (int hf = 0; hf < 2; hf++) {
                int row = mg * 32 + mt * 16 + hf * 8 + lq;
                float m_blk = fmaxf(rmax[row], rmax[128 + row]);
                float m_new = fmaxf(m_run[mt][hf], m_blk);
                corr[mt][hf] = __expf(m_run[mt][hf] - m_new);
                m_run[mt][hf] = m_new;
                float rs = 0.f;
                #pragma unroll
                for (int nt = 0; nt < 8; nt++) {
                    float p0 = __expf(s[mt][nt][hf * 2 + 0] - m_new);
                    float p1 = __expf(s[mt][nt][hf * 2 + 1] - m_new);
                    s[mt][nt][hf * 2 + 0] = p0;
                    s[mt][nt][hf * 2 + 1] = p1;
                    rs += p0 + p1;
                }
                rs += __shfl_xor_sync(0xffffffffu, rs, 1);
                rs += __shfl_xor_sync(0xffffffffu, rs, 2);
                if (lr == 0) rsum[ng * 128 + row] = rs;
                #pragma unroll
                for (int nt = 0; nt < 8; nt++) {
                    o[mt][nt][hf * 2 + 0] *= corr[mt][hf];
                    o[mt][nt][hf * 2 + 1] *= corr[mt][hf];
                }
            }
        }
        __syncthreads();

        #pragma unroll
        for (int mt = 0; mt < 2; mt++)
            #pragma unroll
            for (int hf = 0; hf < 2; hf++) {
                int row = mg * 32 + mt * 16 + hf * 8 + lq;
                l_run[mt][hf] = l_run[mt][hf] * corr[mt][hf]
                              + rsum[row] + rsum[128 + row];
            }

        // ---- PV (tf32, k-permuted): warp keys = ng*64..+64, d = 0..63 ----
        #pragma unroll
        for (int kc = 0; kc < 8; kc++) {
            const int kb0 = ng * 64 + kc * 8;
            #pragma unroll
            for (int mt = 0; mt < 2; mt++) {
                unsigned a[4];
                a[0] = f2tf32(s[mt][kc][0]);
                a[1] = f2tf32(s[mt][kc][2]);
                a[2] = f2tf32(s[mt][kc][1]);
                a[3] = f2tf32(s[mt][kc][3]);
                #pragma unroll
                for (int nt = 0; nt < 8; nt++) {
                    int d = nt * 8 + lq;
                    unsigned bb[2];
                    bb[0] = Vs[(kb0 + lr * 2) * 68 + d];
                    bb[1] = Vs[(kb0 + lr * 2 + 1) * 68 + d];
                    mma_tf32(o[mt][nt], a, bb, o[mt][nt]);
                }
            }
        }
        buf ^= 1;
    }

    // ---- epilogue: cross-warp (ng) reduction, normalize, store tf32 ----
    __syncthreads();
    float* Os = (float*)(sm + AK);   // reuse K buf0: [128][68] floats
    if (ng == 1) {
        #pragma unroll
        for (int mt = 0; mt < 2; mt++) {
            int r = mg * 32 + mt * 16 + lq;
            #pragma unroll
            for (int nt = 0; nt < 8; nt++) {
                int d = nt * 8 + lr * 2;
                *(float2*)&Os[r * 68 + d] =
                    make_float2(o[mt][nt][0], o[mt][nt][1]);
                *(float2*)&Os[(r + 8) * 68 + d] =
                    make_float2(o[mt][nt][2], o[mt][nt][3]);
            }
        }
    }
    __syncthreads();
    if (ng == 0) {
        #pragma unroll
        for (int mt = 0; mt < 2; mt++) {
            int r = mg * 32 + mt * 16 + lq;
            float inv0 = 1.0f / l_run[mt][0];
            float inv1 = 1.0f / l_run[mt][1];
            #pragma unroll
            for (int nt = 0; nt < 8; nt++) {
                int d = nt * 8 + lr * 2;
                float2 p0 = *(const float2*)&Os[r * 68 + d];
                float2 p1 = *(const float2*)&Os[(r + 8) * 68 + d];
                uint2 u0 = make_uint2(f2tf32((o[mt][nt][0] + p0.x) * inv0),
                                      f2tf32((o[mt][nt][1] + p0.y) * inv0));
                uint2 u1 = make_uint2(f2tf32((o[mt][nt][2] + p1.x) * inv1),
                                      f2tf32((o[mt][nt][3] + p1.y) * inv1));
                size_t g0 = ((size_t)b * NS + q0 + r) * NE + h * NHD + d;
                size_t g1 = ((size_t)b * NS + q0 + r + 8) * NE + h * NHD + d;
                *(uint2*)&ctx[g0] = u0;
                *(uint2*)&ctx[g1] = u1;
            }
        }
    }
}

// ---------------------------------------------------------------------------
extern "C" void kernel_launch(void* const* d_in, const int* in_sizes, int n_in,
                              void* d_out, int out_size)
{
    const float* x     = (const float*)d_in[0];
    const float* W_qkv = (const float*)d_in[1];
    const float* b_qkv = (const float*)d_in[2];
    const float* W_out = (const float*)d_in[3];
    const float* b_out = (const float*)d_in[4];
    float* out = (float*)d_out;

    unsigned *qkv, *ctx, *xt, *wqkvt, *wot;
    cudaGetSymbolAddress((void**)&qkv,   g_qkv);
    cudaGetSymbolAddress((void**)&ctx,   g_ctx);
    cudaGetSymbolAddress((void**)&xt,    g_xt);
    cudaGetSymbolAddress((void**)&wqkvt, g_wqkvt);
    cudaGetSymbolAddress((void**)&wot,   g_wot);

    cudaFuncSetAttribute(gemm_tt<true>,
                         cudaFuncAttributeMaxDynamicSharedMemorySize,
                         GEMM_SMEM_BYTES);
    cudaFuncSetAttribute(gemm_tt<false>,
                         cudaFuncAttributeMaxDynamicSharedMemorySize,
                         GEMM_SMEM_BYTES);
    cudaFuncSetAttribute(attn_tc,
                         cudaFuncAttributeMaxDynamicSharedMemorySize,
                         ATTN_SMEM_BYTES);

    // 0) pre-convert inputs to tf32
    cvt_tf32<<<(NM * NE) / 1024, 256>>>((const float4*)x, (uint4*)xt);
    cvt_tf32<<<(NQKV * NE) / 1024, 256>>>((const float4*)W_qkv, (uint4*)wqkvt);
    cvt_tf32<<<(NE * NE) / 1024, 256>>>((const float4*)W_out, (uint4*)wot);

    // 1) QKV projection (tf32 in, tf32 out)
    dim3 g1(NQKV / 128, NM / 128);
    gemm_tt<true><<<g1, 256, GEMM_SMEM_BYTES>>>(xt, wqkvt, b_qkv, qkv,
                                                NM, NQKV, NE);

    // 2) Flash attention (tf32 in, tf32 ctx out)
    dim3 g2(NS / 128, NH, NB);
    attn_tc<<<g2, 256, ATTN_SMEM_BYTES>>>(qkv, ctx);

    // 3) Output projection (tf32 in, fp32 out)
    dim3 g3(NE / 128, NM / 128);
    gemm_tt<false><<<g3, 256, GEMM_SMEM_BYTES>>>(ctx, wot, b_out, out,
                                                 NM, NE, NE);
}

// round 5
// speedup vs baseline: 3.9599x; 1.0468x over previous
#include <cuda_runtime.h>

// Problem constants
#define NB 2
#define NS 2048
#define NE 1024
#define NH 16
#define NHD 64
#define NM (NB * NS)      // 4096
#define NQKV (3 * NE)     // 3072

// Scratch (allocation-free rule: __device__ globals). All tf32-in-u32.
__device__ unsigned g_qkv[(size_t)NM * NQKV];    // 48 MB
__device__ unsigned g_ctx[(size_t)NM * NE];      // 16 MB
__device__ unsigned g_xt[(size_t)NM * NE];       // 16 MB
__device__ unsigned g_wqkvt[(size_t)NQKV * NE];  // 12 MB
__device__ unsigned g_wot[(size_t)NE * NE];      // 4 MB

// ---------------------------------------------------------------------------
// helpers
// ---------------------------------------------------------------------------
__device__ __forceinline__ unsigned f2tf32(float x) {
    unsigned u;
    asm("cvt.rna.tf32.f32 %0, %1;" : "=r"(u) : "f"(x));
    return u;
}

__device__ __forceinline__ void mma_tf32(float* d, const unsigned* a,
                                         const unsigned* b, const float* c) {
    asm volatile(
        "mma.sync.aligned.m16n8k8.row.col.f32.tf32.tf32.f32 "
        "{%0,%1,%2,%3}, {%4,%5,%6,%7}, {%8,%9}, {%10,%11,%12,%13};"
        : "=f"(d[0]), "=f"(d[1]), "=f"(d[2]), "=f"(d[3])
        : "r"(a[0]), "r"(a[1]), "r"(a[2]), "r"(a[3]),
          "r"(b[0]), "r"(b[1]),
          "f"(c[0]), "f"(c[1]), "f"(c[2]), "f"(c[3]));
}

// ldmatrix: tf32 fragments as 8x8 b16 tiles (4-byte words = b16 pairs).
#define LDSM4(r, addr) \
    asm volatile("ldmatrix.sync.aligned.m8n8.x4.shared.b16 " \
                 "{%0,%1,%2,%3}, [%4];" \
                 : "=r"((r)[0]), "=r"((r)[1]), "=r"((r)[2]), "=r"((r)[3]) \
                 : "r"(addr))
#define LDSM2(r, addr) \
    asm volatile("ldmatrix.sync.aligned.m8n8.x2.shared.b16 " \
                 "{%0,%1}, [%2];" \
                 : "=r"((r)[0]), "=r"((r)[1]) : "r"(addr))

__device__ __forceinline__ unsigned sptr(const void* p) {
    return (unsigned)__cvta_generic_to_shared(p);
}
#define CP16(dst_s, src_g) \
    asm volatile("cp.async.cg.shared.global [%0], [%1], 16;" \
                 :: "r"(dst_s), "l"(src_g))
#define CPCOMMIT() asm volatile("cp.async.commit_group;")
#define CPWAIT0()  asm volatile("cp.async.wait_group 0;")

// ---------------------------------------------------------------------------
// Elementwise fp32 -> tf32 (RNA) pre-conversion
// ---------------------------------------------------------------------------
__global__ __launch_bounds__(256) void cvt_tf32(
    const float4* __restrict__ src, uint4* __restrict__ dst)
{
    int i = blockIdx.x * 256 + threadIdx.x;
    float4 v = src[i];
    uint4 u;
    u.x = f2tf32(v.x); u.y = f2tf32(v.y);
    u.z = f2tf32(v.z); u.w = f2tf32(v.w);
    dst[i] = u;
}

// ---------------------------------------------------------------------------
// TF32 NT GEMM + bias, pre-converted tf32 inputs, cp.async double-buffered,
// ldmatrix fragment loads.
// C[m][n] = sum_k A[m][k]*W[n][k] + bias[n]
// 128x128 tile, BK=32, 256 threads, warp grid 2x4, warp tile 64x32.
// smem rows stride 36 words (144B): ldmatrix phases conflict-free.
// ---------------------------------------------------------------------------
#define GEMM_SMEM_WORDS (4 * 128 * 36)
#define GEMM_SMEM_BYTES (GEMM_SMEM_WORDS * 4)

template <bool OUT_TF32>
__global__ __launch_bounds__(256) void gemm_tt(
    const unsigned* __restrict__ A, const unsigned* __restrict__ W,
    const float* __restrict__ bias, void* __restrict__ Cv,
    int Mdim, int Ndim, int Kdim)
{
    extern __shared__ unsigned smg[];
    unsigned* Asm = smg;                 // [2][128*36]
    unsigned* Wsm = smg + 2 * 128 * 36;  // [2][128*36]
    const unsigned smem_u = sptr(smg);

    const int tid  = threadIdx.x;
    const int wid  = tid >> 5;
    const int lane = tid & 31;
    const int mg   = wid >> 2;
    const int ng   = wid & 3;
    const int bm   = blockIdx.y * 128;
    const int bn   = blockIdx.x * 128;
    const int lq   = lane >> 2;
    const int lr   = lane & 3;

    const int frow = tid >> 3;
    const int fseg = (tid & 7) * 4;

    // per-thread ldmatrix byte offsets (within a buffer)
    const unsigned offA = ((mg * 64 + (lane & 15)) * 36 + ((lane >> 4) << 2)) * 4;
    const unsigned offW = ((ng * 32 + (lane & 7)) * 36 + (((lane >> 3) & 1) << 2)) * 4;

    float acc[4][4][4] = {};

    auto fill = [&](int kt, int buf) {
        unsigned* Ad = Asm + buf * 4608;
        unsigned* Wd = Wsm + buf * 4608;
        #pragma unroll
        for (int i = 0; i < 4; i++) {
            int row = i * 32 + frow;
            CP16(sptr(Ad + row * 36 + fseg),
                 A + (size_t)(bm + row) * Kdim + kt + fseg);
            CP16(sptr(Wd + row * 36 + fseg),
                 W + (size_t)(bn + row) * Kdim + kt + fseg);
        }
        CPCOMMIT();
    };

    fill(0, 0);
    int buf = 0;
    for (int kt = 0; kt < Kdim; kt += 32) {
        CPWAIT0();
        __syncthreads();
        if (kt + 32 < Kdim) fill(kt + 32, buf ^ 1);

        const unsigned abase = smem_u + buf * 4608 * 4 + offA;
        const unsigned wbase = smem_u + (9216 + buf * 4608) * 4 + offW;
        #pragma unroll
        for (int k8 = 0; k8 < 4; k8++) {
            unsigned a[4][4], b[4][2];
            #pragma unroll
            for (int mt = 0; mt < 4; mt++)
                LDSM4(a[mt], abase + mt * 2304 + k8 * 32);
            #pragma unroll
            for (int nt = 0; nt < 4; nt++)
                LDSM2(b[nt], wbase + nt * 1152 + k8 * 32);
            #pragma unroll
            for (int mt = 0; mt < 4; mt++)
                #pragma unroll
                for (int nt = 0; nt < 4; nt++)
                    mma_tf32(acc[mt][nt], a[mt], b[nt], acc[mt][nt]);
        }
        buf ^= 1;
    }

    // epilogue
    #pragma unroll
    for (int mt = 0; mt < 4; mt++) {
        int r0 = bm + mg * 64 + mt * 16 + lq;
        #pragma unroll
        for (int nt = 0; nt < 4; nt++) {
            int col = bn + ng * 32 + nt * 8 + lr * 2;
            float2 bv = *(const float2*)&bias[col];
            float v00 = acc[mt][nt][0] + bv.x;
            float v01 = acc[mt][nt][1] + bv.y;
            float v10 = acc[mt][nt][2] + bv.x;
            float v11 = acc[mt][nt][3] + bv.y;
            if (OUT_TF32) {
                unsigned* C = (unsigned*)Cv;
                uint2 u0 = make_uint2(f2tf32(v00), f2tf32(v01));
                uint2 u1 = make_uint2(f2tf32(v10), f2tf32(v11));
                *(uint2*)&C[(size_t)r0 * Ndim + col]       = u0;
                *(uint2*)&C[(size_t)(r0 + 8) * Ndim + col] = u1;
            } else {
                float* C = (float*)Cv;
                *(float2*)&C[(size_t)r0 * Ndim + col]       = make_float2(v00, v01);
                *(float2*)&C[(size_t)(r0 + 8) * Ndim + col] = make_float2(v10, v11);
            }
        }
    }
}

// ---------------------------------------------------------------------------
// Flash attention, all-TF32 mma.sync, cp.async double-buffered K/V,
// ldmatrix QK fragment loads, PV with hoisted V fragments + k-permutation.
// Block = one (b, h, 128-q-row tile), 256 threads = 8 warps (4x2 warp grid).
// ---------------------------------------------------------------------------
#define AQ  0                    // Q   [128][68] u32
#define AK  8704                 // K   [2][128][68]
#define AV  26112                // V   [2][128][68]
#define ARM 43520                // rmax float [2][128]
#define ARS 43776                // rsum float [2][128]
#define ATTN_SMEM_BYTES (44032 * 4)

__global__ __launch_bounds__(256, 1) void attn_tc(
    const unsigned* __restrict__ qkv, unsigned* __restrict__ ctx)
{
    extern __shared__ __align__(16) unsigned sm[];
    unsigned* Qs = sm + AQ;
    float* rmax = (float*)(sm + ARM);
    float* rsum = (float*)(sm + ARS);
    const unsigned smem_u = sptr(sm);

    const int tid  = threadIdx.x;
    const int wid  = tid >> 5;
    const int lane = tid & 31;
    const int mg   = wid >> 1;       // 0..3
    const int ng   = wid & 1;        // 0..1
    const int lq   = lane >> 2;
    const int lr   = lane & 3;
    const int q0   = blockIdx.x * 128;
    const int h    = blockIdx.y;
    const int b    = blockIdx.z;

    const unsigned* base  = qkv + (size_t)b * NS * NQKV + h * (3 * NHD);
    const unsigned* kbase = base + NHD;
    const unsigned* vbase = base + 2 * NHD;

    const int frow = tid >> 4;
    const int fseg = (tid & 15) * 4;

    // ldmatrix per-thread byte offsets
    const unsigned offQ = ((mg * 32 + (lane & 15)) * 68 + ((lane >> 4) << 2)) * 4;
    const unsigned offK = ((ng * 64 + (lane & 7)) * 68 + (((lane >> 3) & 1) << 2)) * 4;

    auto fillKV = [&](int t, int buf) {
        unsigned* Kd = sm + AK + buf * 8704;
        unsigned* Vd = sm + AV + buf * 8704;
        #pragma unroll
        for (int i = 0; i < 8; i++) {
            int key = i * 16 + frow;
            CP16(sptr(Kd + key * 68 + fseg),
                 kbase + (size_t)(t * 128 + key) * NQKV + fseg);
            CP16(sptr(Vd + key * 68 + fseg),
                 vbase + (size_t)(t * 128 + key) * NQKV + fseg);
        }
        CPCOMMIT();
    };

    fillKV(0, 0);

    // Q fill (tf32 in gmem; 0.125 scale is exact in tf32)
    #pragma unroll
    for (int i = 0; i < 8; i++) {
        int row = i * 16 + frow;
        uint4 v = *(const uint4*)(base + (size_t)(q0 + row) * NQKV + fseg);
        Qs[row * 68 + fseg + 0] = __float_as_uint(__uint_as_float(v.x) * 0.125f);
        Qs[row * 68 + fseg + 1] = __float_as_uint(__uint_as_float(v.y) * 0.125f);
        Qs[row * 68 + fseg + 2] = __float_as_uint(__uint_as_float(v.z) * 0.125f);
        Qs[row * 68 + fseg + 3] = __float_as_uint(__uint_as_float(v.w) * 0.125f);
    }

    float o[2][8][4] = {};
    float m_run[2][2] = {{-1e30f, -1e30f}, {-1e30f, -1e30f}};
    float l_run[2][2] = {};

    int buf = 0;
    for (int t = 0; t < NS / 128; t++) {
        CPWAIT0();
        __syncthreads();
        if (t + 1 < NS / 128) fillKV(t + 1, buf ^ 1);

        const unsigned* Vs = sm + AV + buf * 8704;
        const unsigned qbase = smem_u + offQ;                       // Q at word 0
        const unsigned kbase_s = smem_u + (AK + buf * 8704) * 4 + offK;

        // ---- QK^T (tf32, ldmatrix frags): 32 q-rows x 64 keys / warp ----
        float s[2][8][4] = {};
        #pragma unroll
        for (int k8 = 0; k8 < 8; k8++) {
            unsigned a[2][4], kb[8][2];
            #pragma unroll
            for (int mt = 0; mt < 2; mt++)
                LDSM4(a[mt], qbase + mt * 4352 + k8 * 32);
            #pragma unroll
            for (int nt = 0; nt < 8; nt++)
                LDSM2(kb[nt], kbase_s + nt * 2176 + k8 * 32);
            #pragma unroll
            for (int mt = 0; mt < 2; mt++)
                #pragma unroll
                for (int nt = 0; nt < 8; nt++)
                    mma_tf32(s[mt][nt], a[mt], kb[nt], s[mt][nt]);
        }

        // ---- online softmax ----
        #pragma unroll
        for (int mt = 0; mt < 2; mt++) {
            #pragma unroll
            for (int hf = 0; hf < 2; hf++) {
                float v = -1e30f;
                #pragma unroll
                for (int nt = 0; nt < 8; nt++) {
                    v = fmaxf(v, s[mt][nt][hf * 2 + 0]);
                    v = fmaxf(v, s[mt][nt][hf * 2 + 1]);
                }
                v = fmaxf(v, __shfl_xor_sync(0xffffffffu, v, 1));
                v = fmaxf(v, __shfl_xor_sync(0xffffffffu, v, 2));
                if (lr == 0)
                    rmax[ng * 128 + mg * 32 + mt * 16 + hf * 8 + lq] = v;
            }
        }
        __syncthreads();

        float corr[2][2];
        #pragma unroll
        for (int mt = 0; mt < 2; mt++) {
            #pragma unroll
            for (int hf = 0; hf < 2; hf++) {
                int row = mg * 32 + mt * 16 + hf * 8 + lq;
                float m_blk = fmaxf(rmax[row], rmax[128 + row]);
                float m_new = fmaxf(m_run[mt][hf], m_blk);
                corr[mt][hf] = __expf(m_run[mt][hf] - m_new);
                m_run[mt][hf] = m_new;
                float rs = 0.f;
                #pragma unroll
                for (int nt = 0; nt < 8; nt++) {
                    float p0 = __expf(s[mt][nt][hf * 2 + 0] - m_new);
                    float p1 = __expf(s[mt][nt][hf * 2 + 1] - m_new);
                    s[mt][nt][hf * 2 + 0] = p0;
                    s[mt][nt][hf * 2 + 1] = p1;
                    rs += p0 + p1;
                }
                rs += __shfl_xor_sync(0xffffffffu, rs, 1);
                rs += __shfl_xor_sync(0xffffffffu, rs, 2);
                if (lr == 0) rsum[ng * 128 + row] = rs;
                #pragma unroll
                for (int nt = 0; nt < 8; nt++) {
                    o[mt][nt][hf * 2 + 0] *= corr[mt][hf];
                    o[mt][nt][hf * 2 + 1] *= corr[mt][hf];
                }
            }
        }
        __syncthreads();

        #pragma unroll
        for (int mt = 0; mt < 2; mt++)
            #pragma unroll
            for (int hf = 0; hf < 2; hf++) {
                int row = mg * 32 + mt * 16 + hf * 8 + lq;
                l_run[mt][hf] = l_run[mt][hf] * corr[mt][hf]
                              + rsum[row] + rsum[128 + row];
            }

        // ---- PV (tf32, k-permuted, hoisted V frags) ----
        #pragma unroll
        for (int kc = 0; kc < 8; kc++) {
            const int kb0 = ng * 64 + kc * 8;
            unsigned a0[4], a1[4];
            a0[0] = f2tf32(s[0][kc][0]);
            a0[1] = f2tf32(s[0][kc][2]);
            a0[2] = f2tf32(s[0][kc][1]);
            a0[3] = f2tf32(s[0][kc][3]);
            a1[0] = f2tf32(s[1][kc][0]);
            a1[1] = f2tf32(s[1][kc][2]);
            a1[2] = f2tf32(s[1][kc][1]);
            a1[3] = f2tf32(s[1][kc][3]);
            const unsigned* vrow0 = Vs + (kb0 + lr * 2) * 68;
            const unsigned* vrow1 = vrow0 + 68;
            #pragma unroll
            for (int nt = 0; nt < 8; nt++) {
                int d = nt * 8 + lq;
                unsigned bb[2];
                bb[0] = vrow0[d];
                bb[1] = vrow1[d];
                mma_tf32(o[0][nt], a0, bb, o[0][nt]);
                mma_tf32(o[1][nt], a1, bb, o[1][nt]);
            }
        }
        buf ^= 1;
    }

    // ---- epilogue: cross-warp (ng) reduction, normalize, store tf32 ----
    __syncthreads();
    float* Os = (float*)(sm + AK);
    if (ng == 1) {
        #pragma unroll
        for (int mt = 0; mt < 2; mt++) {
            int r = mg * 32 + mt * 16 + lq;
            #pragma unroll
            for (int nt = 0; nt < 8; nt++) {
                int d = nt * 8 + lr * 2;
                *(float2*)&Os[r * 68 + d] =
                    make_float2(o[mt][nt][0], o[mt][nt][1]);
                *(float2*)&Os[(r + 8) * 68 + d] =
                    make_float2(o[mt][nt][2], o[mt][nt][3]);
            }
        }
    }
    __syncthreads();
    if (ng == 0) {
        #pragma unroll
        for (int mt = 0; mt < 2; mt++) {
            int r = mg * 32 + mt * 16 + lq;
            float inv0 = 1.0f / l_run[mt][0];
            float inv1 = 1.0f / l_run[mt][1];
            #pragma unroll
            for (int nt = 0; nt < 8; nt++) {
                int d = nt * 8 + lr * 2;
                float2 p0 = *(const float2*)&Os[r * 68 + d];
                float2 p1 = *(const float2*)&Os[(r + 8) * 68 + d];
                uint2 u0 = make_uint2(f2tf32((o[mt][nt][0] + p0.x) * inv0),
                                      f2tf32((o[mt][nt][1] + p0.y) * inv0));
                uint2 u1 = make_uint2(f2tf32((o[mt][nt][2] + p1.x) * inv1),
                                      f2tf32((o[mt][nt][3] + p1.y) * inv1));
                size_t g0 = ((size_t)b * NS + q0 + r) * NE + h * NHD + d;
                size_t g1 = ((size_t)b * NS + q0 + r + 8) * NE + h * NHD + d;
                *(uint2*)&ctx[g0] = u0;
                *(uint2*)&ctx[g1] = u1;
            }
        }
    }
}

// ---------------------------------------------------------------------------
extern "C" void kernel_launch(void* const* d_in, const int* in_sizes, int n_in,
                              void* d_out, int out_size)
{
    const float* x     = (const float*)d_in[0];
    const float* W_qkv = (const float*)d_in[1];
    const float* b_qkv = (const float*)d_in[2];
    const float* W_out = (const float*)d_in[3];
    const float* b_out = (const float*)d_in[4];
    float* out = (float*)d_out;

    unsigned *qkv, *ctx, *xt, *wqkvt, *wot;
    cudaGetSymbolAddress((void**)&qkv,   g_qkv);
    cudaGetSymbolAddress((void**)&ctx,   g_ctx);
    cudaGetSymbolAddress((void**)&xt,    g_xt);
    cudaGetSymbolAddress((void**)&wqkvt, g_wqkvt);
    cudaGetSymbolAddress((void**)&wot,   g_wot);

    cudaFuncSetAttribute(gemm_tt<true>,
                         cudaFuncAttributeMaxDynamicSharedMemorySize,
                         GEMM_SMEM_BYTES);
    cudaFuncSetAttribute(gemm_tt<false>,
                         cudaFuncAttributeMaxDynamicSharedMemorySize,
                         GEMM_SMEM_BYTES);
    cudaFuncSetAttribute(attn_tc,
                         cudaFuncAttributeMaxDynamicSharedMemorySize,
                         ATTN_SMEM_BYTES);

    // 0) pre-convert inputs to tf32 (RNA)
    cvt_tf32<<<(NM * NE) / 1024, 256>>>((const float4*)x, (uint4*)xt);
    cvt_tf32<<<(NQKV * NE) / 1024, 256>>>((const float4*)W_qkv, (uint4*)wqkvt);
    cvt_tf32<<<(NE * NE) / 1024, 256>>>((const float4*)W_out, (uint4*)wot);

    // 1) QKV projection (tf32 in, tf32 out)
    dim3 g1(NQKV / 128, NM / 128);
    gemm_tt<true><<<g1, 256, GEMM_SMEM_BYTES>>>(xt, wqkvt, b_qkv, qkv,
                                                NM, NQKV, NE);

    // 2) Flash attention (tf32 in, tf32 ctx out)
    dim3 g2(NS / 128, NH, NB);
    attn_tc<<<g2, 256, ATTN_SMEM_BYTES>>>(qkv, ctx);

    // 3) Output projection (tf32 in, fp32 out)
    dim3 g3(NE / 128, NM / 128);
    gemm_tt<false><<<g3, 256, GEMM_SMEM_BYTES>>>(ctx, wot, b_out, out,
                                                 NM, NE, NE);
}

// round 6
// speedup vs baseline: 3.9832x; 1.0059x over previous
#include <cuda_runtime.h>

// Problem constants
#define NB 2
#define NS 2048
#define NE 1024
#define NH 16
#define NHD 64
#define NM (NB * NS)      // 4096
#define NQKV (3 * NE)     // 3072

// Scratch (allocation-free rule: __device__ globals). All tf32-in-u32.
__device__ unsigned g_qkv[(size_t)NM * NQKV];    // 48 MB
__device__ unsigned g_ctx[(size_t)NM * NE];      // 16 MB
__device__ unsigned g_xt[(size_t)NM * NE];       // 16 MB
__device__ unsigned g_wqkvt[(size_t)NQKV * NE];  // 12 MB
__device__ unsigned g_wot[(size_t)NE * NE];      // 4 MB

// ---------------------------------------------------------------------------
// helpers
// ---------------------------------------------------------------------------
__device__ __forceinline__ unsigned f2tf32(float x) {
    unsigned u;
    asm("cvt.rna.tf32.f32 %0, %1;" : "=r"(u) : "f"(x));
    return u;
}

__device__ __forceinline__ void mma_tf32(float* d, const unsigned* a,
                                         const unsigned* b, const float* c) {
    asm volatile(
        "mma.sync.aligned.m16n8k8.row.col.f32.tf32.tf32.f32 "
        "{%0,%1,%2,%3}, {%4,%5,%6,%7}, {%8,%9}, {%10,%11,%12,%13};"
        : "=f"(d[0]), "=f"(d[1]), "=f"(d[2]), "=f"(d[3])
        : "r"(a[0]), "r"(a[1]), "r"(a[2]), "r"(a[3]),
          "r"(b[0]), "r"(b[1]),
          "f"(c[0]), "f"(c[1]), "f"(c[2]), "f"(c[3]));
}

#define LDSM4(r, addr) \
    asm volatile("ldmatrix.sync.aligned.m8n8.x4.shared.b16 " \
                 "{%0,%1,%2,%3}, [%4];" \
                 : "=r"((r)[0]), "=r"((r)[1]), "=r"((r)[2]), "=r"((r)[3]) \
                 : "r"(addr))
#define LDSM2(r, addr) \
    asm volatile("ldmatrix.sync.aligned.m8n8.x2.shared.b16 " \
                 "{%0,%1}, [%2];" \
                 : "=r"((r)[0]), "=r"((r)[1]) : "r"(addr))

__device__ __forceinline__ unsigned sptr(const void* p) {
    return (unsigned)__cvta_generic_to_shared(p);
}
#define CP16(dst_s, src_g) \
    asm volatile("cp.async.cg.shared.global [%0], [%1], 16;" \
                 :: "r"(dst_s), "l"(src_g))
#define CPCOMMIT() asm volatile("cp.async.commit_group;")
#define CPWAIT(n)  asm volatile("cp.async.wait_group %0;" :: "n"(n))
#define CPWAIT0()  CPWAIT(0)

// ---------------------------------------------------------------------------
// Elementwise fp32 -> tf32 (RNA)
// ---------------------------------------------------------------------------
__global__ __launch_bounds__(256) void cvt_tf32(
    const float4* __restrict__ src, uint4* __restrict__ dst)
{
    int i = blockIdx.x * 256 + threadIdx.x;
    float4 v = src[i];
    uint4 u;
    u.x = f2tf32(v.x); u.y = f2tf32(v.y);
    u.z = f2tf32(v.z); u.w = f2tf32(v.w);
    dst[i] = u;
}

// ---------------------------------------------------------------------------
// TF32 NT GEMM + bias, 3-stage cp.async ring, ldmatrix fragment loads.
// 128x128 tile, BK=32, 256 threads, warp grid 2x4, warp tile 64x32.
// ---------------------------------------------------------------------------
#define GEMM_SMEM_WORDS (6 * 128 * 36)
#define GEMM_SMEM_BYTES (GEMM_SMEM_WORDS * 4)   // 110592

template <bool OUT_TF32>
__global__ __launch_bounds__(256) void gemm_tt(
    const unsigned* __restrict__ A, const unsigned* __restrict__ W,
    const float* __restrict__ bias, void* __restrict__ Cv,
    int Mdim, int Ndim, int Kdim)
{
    extern __shared__ unsigned smg[];
    unsigned* Asm = smg;                 // [3][128*36]
    unsigned* Wsm = smg + 3 * 4608;      // [3][128*36]
    const unsigned smem_u = sptr(smg);

    const int tid  = threadIdx.x;
    const int wid  = tid >> 5;
    const int lane = tid & 31;
    const int mg   = wid >> 2;
    const int ng   = wid & 3;
    const int bm   = blockIdx.y * 128;
    const int bn   = blockIdx.x * 128;
    const int lq   = lane >> 2;
    const int lr   = lane & 3;

    const int frow = tid >> 3;
    const int fseg = (tid & 7) * 4;

    const unsigned offA = ((mg * 64 + (lane & 15)) * 36 + ((lane >> 4) << 2)) * 4;
    const unsigned offW = ((ng * 32 + (lane & 7)) * 36 + (((lane >> 3) & 1) << 2)) * 4;

    float acc[4][4][4] = {};

    auto fill = [&](int kt, int buf) {
        unsigned* Ad = Asm + buf * 4608;
        unsigned* Wd = Wsm + buf * 4608;
        #pragma unroll
        for (int i = 0; i < 4; i++) {
            int row = i * 32 + frow;
            CP16(sptr(Ad + row * 36 + fseg),
                 A + (size_t)(bm + row) * Kdim + kt + fseg);
            CP16(sptr(Wd + row * 36 + fseg),
                 W + (size_t)(bn + row) * Kdim + kt + fseg);
        }
        CPCOMMIT();
    };

    fill(0, 0);
    fill(32, 1);
    int buf = 0;
    for (int kt = 0; kt < Kdim; kt += 32) {
        if (kt + 32 < Kdim) CPWAIT(1); else CPWAIT(0);
        __syncthreads();
        if (kt + 64 < Kdim) fill(kt + 64, (buf + 2) % 3);

        const unsigned abase = smem_u + buf * 4608 * 4 + offA;
        const unsigned wbase = smem_u + (3 * 4608 + buf * 4608) * 4 + offW;
        #pragma unroll
        for (int k8 = 0; k8 < 4; k8++) {
            unsigned a[4][4], b[4][2];
            #pragma unroll
            for (int mt = 0; mt < 4; mt++)
                LDSM4(a[mt], abase + mt * 2304 + k8 * 32);
            #pragma unroll
            for (int nt = 0; nt < 4; nt++)
                LDSM2(b[nt], wbase + nt * 1152 + k8 * 32);
            #pragma unroll
            for (int mt = 0; mt < 4; mt++)
                #pragma unroll
                for (int nt = 0; nt < 4; nt++)
                    mma_tf32(acc[mt][nt], a[mt], b[nt], acc[mt][nt]);
        }
        buf = (buf + 1) % 3;
    }

    // epilogue
    #pragma unroll
    for (int mt = 0; mt < 4; mt++) {
        int r0 = bm + mg * 64 + mt * 16 + lq;
        #pragma unroll
        for (int nt = 0; nt < 4; nt++) {
            int col = bn + ng * 32 + nt * 8 + lr * 2;
            float2 bv = *(const float2*)&bias[col];
            float v00 = acc[mt][nt][0] + bv.x;
            float v01 = acc[mt][nt][1] + bv.y;
            float v10 = acc[mt][nt][2] + bv.x;
            float v11 = acc[mt][nt][3] + bv.y;
            if (OUT_TF32) {
                unsigned* C = (unsigned*)Cv;
                *(uint2*)&C[(size_t)r0 * Ndim + col] =
                    make_uint2(f2tf32(v00), f2tf32(v01));
                *(uint2*)&C[(size_t)(r0 + 8) * Ndim + col] =
                    make_uint2(f2tf32(v10), f2tf32(v11));
            } else {
                float* C = (float*)Cv;
                *(float2*)&C[(size_t)r0 * Ndim + col]       = make_float2(v00, v01);
                *(float2*)&C[(size_t)(r0 + 8) * Ndim + col] = make_float2(v10, v11);
            }
        }
    }
}

// ---------------------------------------------------------------------------
// Flash attention, split-key private softmax, 512 threads = 16 warps.
// Warp grid 8(m) x 2(n): warp owns 16 q-rows x its 64-key slice.
// Each warp keeps private online (m,l); merged once in the epilogue.
// One __syncthreads per key tile.
// ---------------------------------------------------------------------------
#define AQ  0                    // Q   [128][68] u32
#define AK  8704                 // K   [2][128][68]
#define AV  26112                // V   [2][128][68]
#define ARM 43520                // m  float [2][128]
#define ARS 43776                // l  float [2][128]
#define ATTN_SMEM_BYTES (44032 * 4)
#define ATHREADS 512

__global__ __launch_bounds__(ATHREADS, 1) void attn_tc(
    const unsigned* __restrict__ qkv, unsigned* __restrict__ ctx)
{
    extern __shared__ __align__(16) unsigned sm[];
    unsigned* Qs = sm + AQ;
    const unsigned smem_u = sptr(sm);

    const int tid  = threadIdx.x;
    const int wid  = tid >> 5;
    const int lane = tid & 31;
    const int mg   = wid >> 1;       // 0..7 -> 16 q-rows each
    const int ng   = wid & 1;        // 0..1 -> 64-key slice
    const int lq   = lane >> 2;
    const int lr   = lane & 3;
    const int q0   = blockIdx.x * 128;
    const int h    = blockIdx.y;
    const int b    = blockIdx.z;

    const unsigned* base  = qkv + (size_t)b * NS * NQKV + h * (3 * NHD);
    const unsigned* kbase = base + NHD;
    const unsigned* vbase = base + 2 * NHD;

    const int frow = tid >> 4;       // 0..31
    const int fseg = (tid & 15) * 4;

    const unsigned offQ = ((mg * 16 + (lane & 15)) * 68 + ((lane >> 4) << 2)) * 4;
    const unsigned offK = ((ng * 64 + (lane & 7)) * 68 + (((lane >> 3) & 1) << 2)) * 4;

    auto fillKV = [&](int t, int buf) {
        unsigned* Kd = sm + AK + buf * 8704;
        unsigned* Vd = sm + AV + buf * 8704;
        #pragma unroll
        for (int i = 0; i < 4; i++) {
            int key = i * 32 + frow;
            CP16(sptr(Kd + key * 68 + fseg),
                 kbase + (size_t)(t * 128 + key) * NQKV + fseg);
            CP16(sptr(Vd + key * 68 + fseg),
                 vbase + (size_t)(t * 128 + key) * NQKV + fseg);
        }
        CPCOMMIT();
    };

    fillKV(0, 0);

    // Q fill (tf32 in gmem; 0.125 scale exact in tf32)
    #pragma unroll
    for (int i = 0; i < 4; i++) {
        int idx = i * ATHREADS + tid;
        int row = idx >> 4;
        int seg = (idx & 15) * 4;
        uint4 v = *(const uint4*)(base + (size_t)(q0 + row) * NQKV + seg);
        Qs[row * 68 + seg + 0] = __float_as_uint(__uint_as_float(v.x) * 0.125f);
        Qs[row * 68 + seg + 1] = __float_as_uint(__uint_as_float(v.y) * 0.125f);
        Qs[row * 68 + seg + 2] = __float_as_uint(__uint_as_float(v.z) * 0.125f);
        Qs[row * 68 + seg + 3] = __float_as_uint(__uint_as_float(v.w) * 0.125f);
    }

    float o[8][4] = {};
    float m_run[2] = {-1e30f, -1e30f};
    float l_run[2] = {0.f, 0.f};

    int buf = 0;
    for (int t = 0; t < NS / 128; t++) {
        CPWAIT0();
        __syncthreads();
        if (t + 1 < NS / 128) fillKV(t + 1, buf ^ 1);

        const unsigned* Vs = sm + AV + buf * 8704;
        const unsigned qbase   = smem_u + offQ;
        const unsigned kbase_s = smem_u + (AK + buf * 8704) * 4 + offK;

        // ---- QK^T: 16 q-rows x 64 keys per warp ----
        float s[8][4] = {};
        #pragma unroll
        for (int k8 = 0; k8 < 8; k8++) {
            unsigned a[4], kb[8][2];
            LDSM4(a, qbase + k8 * 32);
            #pragma unroll
            for (int nt = 0; nt < 8; nt++)
                LDSM2(kb[nt], kbase_s + nt * 2176 + k8 * 32);
            #pragma unroll
            for (int nt = 0; nt < 8; nt++)
                mma_tf32(s[nt], a, kb[nt], s[nt]);
        }

        // ---- private online softmax (per warp, its own key slice) ----
        #pragma unroll
        for (int hf = 0; hf < 2; hf++) {
            float v = -1e30f;
            #pragma unroll
            for (int nt = 0; nt < 8; nt++) {
                v = fmaxf(v, s[nt][hf * 2 + 0]);
                v = fmaxf(v, s[nt][hf * 2 + 1]);
            }
            v = fmaxf(v, __shfl_xor_sync(0xffffffffu, v, 1));
            v = fmaxf(v, __shfl_xor_sync(0xffffffffu, v, 2));
            float m_new = fmaxf(m_run[hf], v);
            float corr  = __expf(m_run[hf] - m_new);
            m_run[hf] = m_new;
            float rs = 0.f;
            #pragma unroll
            for (int nt = 0; nt < 8; nt++) {
                float p0 = __expf(s[nt][hf * 2 + 0] - m_new);
                float p1 = __expf(s[nt][hf * 2 + 1] - m_new);
                s[nt][hf * 2 + 0] = p0;
                s[nt][hf * 2 + 1] = p1;
                rs += p0 + p1;
            }
            rs += __shfl_xor_sync(0xffffffffu, rs, 1);
            rs += __shfl_xor_sync(0xffffffffu, rs, 2);
            l_run[hf] = l_run[hf] * corr + rs;
            #pragma unroll
            for (int nt = 0; nt < 8; nt++) {
                o[nt][hf * 2 + 0] *= corr;
                o[nt][hf * 2 + 1] *= corr;
            }
        }

        // ---- PV (tf32, k-permuted, hoisted V frags) ----
        #pragma unroll
        for (int kc = 0; kc < 8; kc++) {
            unsigned a[4];
            a[0] = f2tf32(s[kc][0]);
            a[1] = f2tf32(s[kc][2]);
            a[2] = f2tf32(s[kc][1]);
            a[3] = f2tf32(s[kc][3]);
            const unsigned* vrow0 = Vs + (ng * 64 + kc * 8 + lr * 2) * 68;
            const unsigned* vrow1 = vrow0 + 68;
            #pragma unroll
            for (int nt = 0; nt < 8; nt++) {
                int d = nt * 8 + lq;
                unsigned bb[2];
                bb[0] = vrow0[d];
                bb[1] = vrow1[d];
                mma_tf32(o[nt], a, bb, o[nt]);
            }
        }
        buf ^= 1;
    }

    // ---- epilogue: merge the two key-slices (exact rescale), store tf32 ----
    __syncthreads();
    float* rm = (float*)(sm + ARM);   // [ng][128]
    float* rl = (float*)(sm + ARS);
    if (lr == 0) {
        rm[ng * 128 + mg * 16 + lq]     = m_run[0];
        rm[ng * 128 + mg * 16 + 8 + lq] = m_run[1];
        rl[ng * 128 + mg * 16 + lq]     = l_run[0];
        rl[ng * 128 + mg * 16 + 8 + lq] = l_run[1];
    }
    __syncthreads();

    float fsc[2], linv[2];
    #pragma unroll
    for (int hf = 0; hf < 2; hf++) {
        int row = mg * 16 + hf * 8 + lq;
        float m0 = rm[row], m1 = rm[128 + row];
        float m_tot = fmaxf(m0, m1);
        float l_tot = rl[row] * __expf(m0 - m_tot)
                    + rl[128 + row] * __expf(m1 - m_tot);
        fsc[hf]  = __expf(m_run[hf] - m_tot);
        linv[hf] = 1.0f / l_tot;
    }

    float* Os = (float*)(sm + AK);    // [128][68] floats
    if (ng == 1) {
        int r = mg * 16 + lq;
        #pragma unroll
        for (int nt = 0; nt < 8; nt++) {
            int d = nt * 8 + lr * 2;
            *(float2*)&Os[r * 68 + d] =
                make_float2(o[nt][0] * fsc[0], o[nt][1] * fsc[0]);
            *(float2*)&Os[(r + 8) * 68 + d] =
                make_float2(o[nt][2] * fsc[1], o[nt][3] * fsc[1]);
        }
    }
    __syncthreads();
    if (ng == 0) {
        int r = mg * 16 + lq;
        #pragma unroll
        for (int nt = 0; nt < 8; nt++) {
            int d = nt * 8 + lr * 2;
            float2 p0 = *(const float2*)&Os[r * 68 + d];
            float2 p1 = *(const float2*)&Os[(r + 8) * 68 + d];
            uint2 u0 = make_uint2(
                f2tf32((o[nt][0] * fsc[0] + p0.x) * linv[0]),
                f2tf32((o[nt][1] * fsc[0] + p0.y) * linv[0]));
            uint2 u1 = make_uint2(
                f2tf32((o[nt][2] * fsc[1] + p1.x) * linv[1]),
                f2tf32((o[nt][3] * fsc[1] + p1.y) * linv[1]));
            size_t g0 = ((size_t)b * NS + q0 + r) * NE + h * NHD + d;
            size_t g1 = ((size_t)b * NS + q0 + r + 8) * NE + h * NHD + d;
            *(uint2*)&ctx[g0] = u0;
            *(uint2*)&ctx[g1] = u1;
        }
    }
}

// ---------------------------------------------------------------------------
extern "C" void kernel_launch(void* const* d_in, const int* in_sizes, int n_in,
                              void* d_out, int out_size)
{
    const float* x     = (const float*)d_in[0];
    const float* W_qkv = (const float*)d_in[1];
    const float* b_qkv = (const float*)d_in[2];
    const float* W_out = (const float*)d_in[3];
    const float* b_out = (const float*)d_in[4];
    float* out = (float*)d_out;

    unsigned *qkv, *ctx, *xt, *wqkvt, *wot;
    cudaGetSymbolAddress((void**)&qkv,   g_qkv);
    cudaGetSymbolAddress((void**)&ctx,   g_ctx);
    cudaGetSymbolAddress((void**)&xt,    g_xt);
    cudaGetSymbolAddress((void**)&wqkvt, g_wqkvt);
    cudaGetSymbolAddress((void**)&wot,   g_wot);

    cudaFuncSetAttribute(gemm_tt<true>,
                         cudaFuncAttributeMaxDynamicSharedMemorySize,
                         GEMM_SMEM_BYTES);
    cudaFuncSetAttribute(gemm_tt<false>,
                         cudaFuncAttributeMaxDynamicSharedMemorySize,
                         GEMM_SMEM_BYTES);
    cudaFuncSetAttribute(attn_tc,
                         cudaFuncAttributeMaxDynamicSharedMemorySize,
                         ATTN_SMEM_BYTES);

    // 0) pre-convert inputs to tf32 (RNA)
    cvt_tf32<<<(NM * NE) / 1024, 256>>>((const float4*)x, (uint4*)xt);
    cvt_tf32<<<(NQKV * NE) / 1024, 256>>>((const float4*)W_qkv, (uint4*)wqkvt);
    cvt_tf32<<<(NE * NE) / 1024, 256>>>((const float4*)W_out, (uint4*)wot);

    // 1) QKV projection (tf32 in, tf32 out)
    dim3 g1(NQKV / 128, NM / 128);
    gemm_tt<true><<<g1, 256, GEMM_SMEM_BYTES>>>(xt, wqkvt, b_qkv, qkv,
                                                NM, NQKV, NE);

    // 2) Flash attention (tf32 in, tf32 ctx out)
    dim3 g2(NS / 128, NH, NB);
    attn_tc<<<g2, ATHREADS, ATTN_SMEM_BYTES>>>(qkv, ctx);

    // 3) Output projection (tf32 in, fp32 out)
    dim3 g3(NE / 128, NM / 128);
    gemm_tt<false><<<g3, 256, GEMM_SMEM_BYTES>>>(ctx, wot, b_out, out,
                                                 NM, NE, NE);
}

// round 7
// speedup vs baseline: 5.1073x; 1.2822x over previous
#include <cuda_runtime.h>
#include <cuda_fp16.h>

// Problem constants
#define NB 2
#define NS 2048
#define NE 1024
#define NH 16
#define NHD 64
#define NM (NB * NS)      // 4096
#define NQKV (3 * NE)     // 3072

// Scratch (allocation-free rule: __device__ globals).
__device__ __half   g_qkv[(size_t)NM * NQKV];    // 24 MB (fp16)
__device__ unsigned g_ctx[(size_t)NM * NE];      // 16 MB (tf32)
__device__ unsigned g_xt[(size_t)NM * NE];       // 16 MB (tf32)
__device__ unsigned g_wqkvt[(size_t)NQKV * NE];  // 12 MB
__device__ unsigned g_wot[(size_t)NE * NE];      // 4 MB

// ---------------------------------------------------------------------------
// helpers
// ---------------------------------------------------------------------------
__device__ __forceinline__ unsigned f2tf32(float x) {
    unsigned u;
    asm("cvt.rna.tf32.f32 %0, %1;" : "=r"(u) : "f"(x));
    return u;
}

__device__ __forceinline__ void mma_tf32(float* d, const unsigned* a,
                                         const unsigned* b, const float* c) {
    asm volatile(
        "mma.sync.aligned.m16n8k8.row.col.f32.tf32.tf32.f32 "
        "{%0,%1,%2,%3}, {%4,%5,%6,%7}, {%8,%9}, {%10,%11,%12,%13};"
        : "=f"(d[0]), "=f"(d[1]), "=f"(d[2]), "=f"(d[3])
        : "r"(a[0]), "r"(a[1]), "r"(a[2]), "r"(a[3]),
          "r"(b[0]), "r"(b[1]),
          "f"(c[0]), "f"(c[1]), "f"(c[2]), "f"(c[3]));
}

__device__ __forceinline__ void mma_f16(float* d, const unsigned* a,
                                        const unsigned* b, const float* c) {
    asm volatile(
        "mma.sync.aligned.m16n8k16.row.col.f32.f16.f16.f32 "
        "{%0,%1,%2,%3}, {%4,%5,%6,%7}, {%8,%9}, {%10,%11,%12,%13};"
        : "=f"(d[0]), "=f"(d[1]), "=f"(d[2]), "=f"(d[3])
        : "r"(a[0]), "r"(a[1]), "r"(a[2]), "r"(a[3]),
          "r"(b[0]), "r"(b[1]),
          "f"(c[0]), "f"(c[1]), "f"(c[2]), "f"(c[3]));
}

#define LDSM4(r, addr) \
    asm volatile("ldmatrix.sync.aligned.m8n8.x4.shared.b16 " \
                 "{%0,%1,%2,%3}, [%4];" \
                 : "=r"((r)[0]), "=r"((r)[1]), "=r"((r)[2]), "=r"((r)[3]) \
                 : "r"(addr))
#define LDSM2(r, addr) \
    asm volatile("ldmatrix.sync.aligned.m8n8.x2.shared.b16 " \
                 "{%0,%1}, [%2];" \
                 : "=r"((r)[0]), "=r"((r)[1]) : "r"(addr))
#define LDSM4T(r, addr) \
    asm volatile("ldmatrix.sync.aligned.m8n8.x4.trans.shared.b16 " \
                 "{%0,%1,%2,%3}, [%4];" \
                 : "=r"((r)[0]), "=r"((r)[1]), "=r"((r)[2]), "=r"((r)[3]) \
                 : "r"(addr))

__device__ __forceinline__ unsigned sptr(const void* p) {
    return (unsigned)__cvta_generic_to_shared(p);
}
#define CP16(dst_s, src_g) \
    asm volatile("cp.async.cg.shared.global [%0], [%1], 16;" \
                 :: "r"(dst_s), "l"(src_g))
#define CPCOMMIT() asm volatile("cp.async.commit_group;")
#define CPWAIT0()  asm volatile("cp.async.wait_group 0;")

__device__ __forceinline__ unsigned packh2(float lo, float hi) {
    __half2 h = __floats2half2_rn(lo, hi);
    return *reinterpret_cast<unsigned*>(&h);
}

// ---------------------------------------------------------------------------
// Elementwise fp32 -> tf32 (RNA)
// ---------------------------------------------------------------------------
__global__ __launch_bounds__(256) void cvt_tf32(
    const float4* __restrict__ src, uint4* __restrict__ dst)
{
    int i = blockIdx.x * 256 + threadIdx.x;
    float4 v = src[i];
    uint4 u;
    u.x = f2tf32(v.x); u.y = f2tf32(v.y);
    u.z = f2tf32(v.z); u.w = f2tf32(v.w);
    dst[i] = u;
}

// ---------------------------------------------------------------------------
// TF32 NT GEMM + bias (round-5 proven config: 2-stage cp.async + ldmatrix).
// OUT: 0 = fp32, 2 = fp16.
// ---------------------------------------------------------------------------
#define GEMM_SMEM_WORDS (4 * 128 * 36)
#define GEMM_SMEM_BYTES (GEMM_SMEM_WORDS * 4)

template <int OUT>
__global__ __launch_bounds__(256) void gemm_tt(
    const unsigned* __restrict__ A, const unsigned* __restrict__ W,
    const float* __restrict__ bias, void* __restrict__ Cv,
    int Mdim, int Ndim, int Kdim)
{
    extern __shared__ unsigned smg[];
    unsigned* Asm = smg;
    unsigned* Wsm = smg + 2 * 4608;
    const unsigned smem_u = sptr(smg);

    const int tid  = threadIdx.x;
    const int wid  = tid >> 5;
    const int lane = tid & 31;
    const int mg   = wid >> 2;
    const int ng   = wid & 3;
    const int bm   = blockIdx.y * 128;
    const int bn   = blockIdx.x * 128;
    const int lq   = lane >> 2;
    const int lr   = lane & 3;

    const int frow = tid >> 3;
    const int fseg = (tid & 7) * 4;

    const unsigned offA = ((mg * 64 + (lane & 15)) * 36 + ((lane >> 4) << 2)) * 4;
    const unsigned offW = ((ng * 32 + (lane & 7)) * 36 + (((lane >> 3) & 1) << 2)) * 4;

    float acc[4][4][4] = {};

    auto fill = [&](int kt, int buf) {
        unsigned* Ad = Asm + buf * 4608;
        unsigned* Wd = Wsm + buf * 4608;
        #pragma unroll
        for (int i = 0; i < 4; i++) {
            int row = i * 32 + frow;
            CP16(sptr(Ad + row * 36 + fseg),
                 A + (size_t)(bm + row) * Kdim + kt + fseg);
            CP16(sptr(Wd + row * 36 + fseg),
                 W + (size_t)(bn + row) * Kdim + kt + fseg);
        }
        CPCOMMIT();
    };

    fill(0, 0);
    int buf = 0;
    for (int kt = 0; kt < Kdim; kt += 32) {
        CPWAIT0();
        __syncthreads();
        if (kt + 32 < Kdim) fill(kt + 32, buf ^ 1);

        const unsigned abase = smem_u + buf * 4608 * 4 + offA;
        const unsigned wbase = smem_u + (2 * 4608 + buf * 4608) * 4 + offW;
        #pragma unroll
        for (int k8 = 0; k8 < 4; k8++) {
            unsigned a[4][4], b[4][2];
            #pragma unroll
            for (int mt = 0; mt < 4; mt++)
                LDSM4(a[mt], abase + mt * 2304 + k8 * 32);
            #pragma unroll
            for (int nt = 0; nt < 4; nt++)
                LDSM2(b[nt], wbase + nt * 1152 + k8 * 32);
            #pragma unroll
            for (int mt = 0; mt < 4; mt++)
                #pragma unroll
                for (int nt = 0; nt < 4; nt++)
                    mma_tf32(acc[mt][nt], a[mt], b[nt], acc[mt][nt]);
        }
        buf ^= 1;
    }

    // epilogue
    #pragma unroll
    for (int mt = 0; mt < 4; mt++) {
        int r0 = bm + mg * 64 + mt * 16 + lq;
        #pragma unroll
        for (int nt = 0; nt < 4; nt++) {
            int col = bn + ng * 32 + nt * 8 + lr * 2;
            float2 bv = *(const float2*)&bias[col];
            float v00 = acc[mt][nt][0] + bv.x;
            float v01 = acc[mt][nt][1] + bv.y;
            float v10 = acc[mt][nt][2] + bv.x;
            float v11 = acc[mt][nt][3] + bv.y;
            if (OUT == 2) {
                __half* C = (__half*)Cv;
                *(unsigned*)&C[(size_t)r0 * Ndim + col]       = packh2(v00, v01);
                *(unsigned*)&C[(size_t)(r0 + 8) * Ndim + col] = packh2(v10, v11);
            } else {
                float* C = (float*)Cv;
                *(float2*)&C[(size_t)r0 * Ndim + col]       = make_float2(v00, v01);
                *(float2*)&C[(size_t)(r0 + 8) * Ndim + col] = make_float2(v10, v11);
            }
        }
    }
}

// ---------------------------------------------------------------------------
// Flash attention, fp16 tensor cores (m16n8k16), fp32 softmax/accum.
// 512 threads = 16 warps, warp grid 8(m) x 2(n); split-key private softmax.
// Q/K/V in fp16 smem, stride 72 halves (144B rows) -> conflict-free ldmatrix.
// ---------------------------------------------------------------------------
// byte offsets
#define AQ_B   0                       // Q [128][72] fp16 = 18432 B
#define AK_B   18432                   // K [2][128][72]   = 36864 B
#define AV_B   55296                   // V [2][128][72]   = 36864 B
#define ARM_B  92160                   // m float [2][128] = 1024 B
#define ARS_B  93184                   // l float [2][128] = 1024 B
#define ATTN_SMEM_BYTES 94208
#define ATHREADS 512

__global__ __launch_bounds__(ATHREADS, 1) void attn_f16(
    const __half* __restrict__ qkv, unsigned* __restrict__ ctx)
{
    extern __shared__ __align__(16) char smc[];
    const unsigned smem_u = sptr(smc);
    __half* Qs = (__half*)(smc + AQ_B);

    const int tid  = threadIdx.x;
    const int wid  = tid >> 5;
    const int lane = tid & 31;
    const int mg   = wid >> 1;       // 0..7 -> 16 q-rows
    const int ng   = wid & 1;        // 0..1 -> 64-key slice
    const int lq   = lane >> 2;
    const int lr   = lane & 3;
    const int q0   = blockIdx.x * 128;
    const int h    = blockIdx.y;
    const int b    = blockIdx.z;

    const __half* base  = qkv + (size_t)b * NS * NQKV + h * (3 * NHD);
    const __half* kbase = base + NHD;
    const __half* vbase = base + 2 * NHD;

    // ldmatrix per-thread byte offsets
    const unsigned offQ = AQ_B + (mg * 16 + (lane & 15)) * 144 + (lane >> 4) * 16;
    const unsigned offK = AK_B + (ng * 64 + (lane & 7)) * 144 + ((lane >> 3) & 1) * 16;
    const unsigned offV = AV_B + (ng * 64 + (lane & 15)) * 144 + (lane >> 4) * 16;

    // K/V fills: 128 rows x 8 chunks(16B) each
    auto fillKV = [&](int t, int buf) {
        const unsigned kd = smem_u + AK_B + buf * 18432;
        const unsigned vd = smem_u + AV_B + buf * 18432;
        #pragma unroll
        for (int i = 0; i < 2; i++) {
            int idx = i * ATHREADS + tid;
            int row = idx >> 3;
            int seg = idx & 7;
            CP16(kd + row * 144 + seg * 16,
                 kbase + (size_t)(t * 128 + row) * NQKV + seg * 8);
            CP16(vd + row * 144 + seg * 16,
                 vbase + (size_t)(t * 128 + row) * NQKV + seg * 8);
        }
        CPCOMMIT();
    };

    fillKV(0, 0);

    // Q fill with 0.125 scale (exact in fp16)
    {
        const __half2 sc = __floats2half2_rn(0.125f, 0.125f);
        #pragma unroll
        for (int i = 0; i < 2; i++) {
            int idx = i * ATHREADS + tid;
            int row = idx >> 3;
            int seg = idx & 7;
            uint4 v = *(const uint4*)(base + (size_t)(q0 + row) * NQKV + seg * 8);
            __half2* p = (__half2*)&v;
            p[0] = __hmul2(p[0], sc);
            p[1] = __hmul2(p[1], sc);
            p[2] = __hmul2(p[2], sc);
            p[3] = __hmul2(p[3], sc);
            *(uint4*)(Qs + row * 72 + seg * 8) = v;
        }
    }

    float o[8][4] = {};
    float m_run[2] = {-1e30f, -1e30f};
    float l_run[2] = {0.f, 0.f};

    int buf = 0;
    for (int t = 0; t < NS / 128; t++) {
        CPWAIT0();
        __syncthreads();
        if (t + 1 < NS / 128) fillKV(t + 1, buf ^ 1);

        const unsigned qb = smem_u + offQ;
        const unsigned kb = smem_u + offK + buf * 18432;
        const unsigned vb = smem_u + offV + buf * 18432;

        // ---- QK^T (fp16 k16): 16 q-rows x 64 keys per warp ----
        float s[8][4] = {};
        #pragma unroll
        for (int kc = 0; kc < 4; kc++) {          // k16 chunks over d=64
            unsigned a[4], kf[8][2];
            LDSM4(a, qb + kc * 32);
            #pragma unroll
            for (int nt = 0; nt < 8; nt++)
                LDSM2(kf[nt], kb + nt * 1152 + kc * 32);
            #pragma unroll
            for (int nt = 0; nt < 8; nt++)
                mma_f16(s[nt], a, kf[nt], s[nt]);
        }

        // ---- private online softmax ----
        #pragma unroll
        for (int hf = 0; hf < 2; hf++) {
            float v = -1e30f;
            #pragma unroll
            for (int nt = 0; nt < 8; nt++) {
                v = fmaxf(v, s[nt][hf * 2 + 0]);
                v = fmaxf(v, s[nt][hf * 2 + 1]);
            }
            v = fmaxf(v, __shfl_xor_sync(0xffffffffu, v, 1));
            v = fmaxf(v, __shfl_xor_sync(0xffffffffu, v, 2));
            float m_new = fmaxf(m_run[hf], v);
            float corr  = __expf(m_run[hf] - m_new);
            m_run[hf] = m_new;
            float rs = 0.f;
            #pragma unroll
            for (int nt = 0; nt < 8; nt++) {
                float p0 = __expf(s[nt][hf * 2 + 0] - m_new);
                float p1 = __expf(s[nt][hf * 2 + 1] - m_new);
                s[nt][hf * 2 + 0] = p0;
                s[nt][hf * 2 + 1] = p1;
                rs += p0 + p1;
            }
            rs += __shfl_xor_sync(0xffffffffu, rs, 1);
            rs += __shfl_xor_sync(0xffffffffu, rs, 2);
            l_run[hf] = l_run[hf] * corr + rs;
            #pragma unroll
            for (int nt = 0; nt < 8; nt++) {
                o[nt][hf * 2 + 0] *= corr;
                o[nt][hf * 2 + 1] *= corr;
            }
        }

        // ---- PV (fp16 k16): P frags direct from s; V via ldmatrix.trans ----
        #pragma unroll
        for (int kc = 0; kc < 4; kc++) {          // key16 chunks
            unsigned a[4];
            a[0] = packh2(s[2 * kc + 0][0], s[2 * kc + 0][1]);
            a[1] = packh2(s[2 * kc + 0][2], s[2 * kc + 0][3]);
            a[2] = packh2(s[2 * kc + 1][0], s[2 * kc + 1][1]);
            a[3] = packh2(s[2 * kc + 1][2], s[2 * kc + 1][3]);
            #pragma unroll
            for (int np = 0; np < 4; np++) {      // d-tile pairs (16 d)
                unsigned vf[4];
                LDSM4T(vf, vb + kc * 2304 + np * 32);
                mma_f16(o[2 * np + 0], a, &vf[0], o[2 * np + 0]);
                mma_f16(o[2 * np + 1], a, &vf[2], o[2 * np + 1]);
            }
        }
        buf ^= 1;
    }

    // ---- epilogue: merge the two key-slices, normalize, store tf32 ----
    __syncthreads();
    float* rm = (float*)(smc + ARM_B);
    float* rl = (float*)(smc + ARS_B);
    if (lr == 0) {
        rm[ng * 128 + mg * 16 + lq]     = m_run[0];
        rm[ng * 128 + mg * 16 + 8 + lq] = m_run[1];
        rl[ng * 128 + mg * 16 + lq]     = l_run[0];
        rl[ng * 128 + mg * 16 + 8 + lq] = l_run[1];
    }
    __syncthreads();

    float fsc[2], linv[2];
    #pragma unroll
    for (int hf = 0; hf < 2; hf++) {
        int row = mg * 16 + hf * 8 + lq;
        float m0 = rm[row], m1 = rm[128 + row];
        float m_tot = fmaxf(m0, m1);
        float l_tot = rl[row] * __expf(m0 - m_tot)
                    + rl[128 + row] * __expf(m1 - m_tot);
        fsc[hf]  = __expf(m_run[hf] - m_tot);
        linv[hf] = 1.0f / l_tot;
    }

    float* Os = (float*)(smc + AK_B);  // [128][68] floats, aliases K bufs
    if (ng == 1) {
        int r = mg * 16 + lq;
        #pragma unroll
        for (int nt = 0; nt < 8; nt++) {
            int d = nt * 8 + lr * 2;
            *(float2*)&Os[r * 68 + d] =
                make_float2(o[nt][0] * fsc[0], o[nt][1] * fsc[0]);
            *(float2*)&Os[(r + 8) * 68 + d] =
                make_float2(o[nt][2] * fsc[1], o[nt][3] * fsc[1]);
        }
    }
    __syncthreads();
    if (ng == 0) {
        int r = mg * 16 + lq;
        #pragma unroll
        for (int nt = 0; nt < 8; nt++) {
            int d = nt * 8 + lr * 2;
            float2 p0 = *(const float2*)&Os[r * 68 + d];
            float2 p1 = *(const float2*)&Os[(r + 8) * 68 + d];
            uint2 u0 = make_uint2(
                f2tf32((o[nt][0] * fsc[0] + p0.x) * linv[0]),
                f2tf32((o[nt][1] * fsc[0] + p0.y) * linv[0]));
            uint2 u1 = make_uint2(
                f2tf32((o[nt][2] * fsc[1] + p1.x) * linv[1]),
                f2tf32((o[nt][3] * fsc[1] + p1.y) * linv[1]));
            size_t g0 = ((size_t)b * NS + q0 + r) * NE + h * NHD + d;
            size_t g1 = ((size_t)b * NS + q0 + r + 8) * NE + h * NHD + d;
            *(uint2*)&ctx[g0] = u0;
            *(uint2*)&ctx[g1] = u1;
        }
    }
}

// ---------------------------------------------------------------------------
extern "C" void kernel_launch(void* const* d_in, const int* in_sizes, int n_in,
                              void* d_out, int out_size)
{
    const float* x     = (const float*)d_in[0];
    const float* W_qkv = (const float*)d_in[1];
    const float* b_qkv = (const float*)d_in[2];
    const float* W_out = (const float*)d_in[3];
    const float* b_out = (const float*)d_in[4];
    float* out = (float*)d_out;

    __half* qkv;
    unsigned *ctx, *xt, *wqkvt, *wot;
    cudaGetSymbolAddress((void**)&qkv,   g_qkv);
    cudaGetSymbolAddress((void**)&ctx,   g_ctx);
    cudaGetSymbolAddress((void**)&xt,    g_xt);
    cudaGetSymbolAddress((void**)&wqkvt, g_wqkvt);
    cudaGetSymbolAddress((void**)&wot,   g_wot);

    cudaFuncSetAttribute(gemm_tt<2>,
                         cudaFuncAttributeMaxDynamicSharedMemorySize,
                         GEMM_SMEM_BYTES);
    cudaFuncSetAttribute(gemm_tt<0>,
                         cudaFuncAttributeMaxDynamicSharedMemorySize,
                         GEMM_SMEM_BYTES);
    cudaFuncSetAttribute(attn_f16,
                         cudaFuncAttributeMaxDynamicSharedMemorySize,
                         ATTN_SMEM_BYTES);

    // 0) pre-convert inputs to tf32 (RNA)
    cvt_tf32<<<(NM * NE) / 1024, 256>>>((const float4*)x, (uint4*)xt);
    cvt_tf32<<<(NQKV * NE) / 1024, 256>>>((const float4*)W_qkv, (uint4*)wqkvt);
    cvt_tf32<<<(NE * NE) / 1024, 256>>>((const float4*)W_out, (uint4*)wot);

    // 1) QKV projection (tf32 math, fp16 out)
    dim3 g1(NQKV / 128, NM / 128);
    gemm_tt<2><<<g1, 256, GEMM_SMEM_BYTES>>>(xt, wqkvt, b_qkv, qkv,
                                             NM, NQKV, NE);

    // 2) Flash attention (fp16 tensor cores, tf32 ctx out)
    dim3 g2(NS / 128, NH, NB);
    attn_f16<<<g2, ATHREADS, ATTN_SMEM_BYTES>>>(qkv, ctx);

    // 3) Output projection (tf32 math, fp32 out)
    dim3 g3(NE / 128, NM / 128);
    gemm_tt<0><<<g3, 256, GEMM_SMEM_BYTES>>>(ctx, wot, b_out, out,
                                             NM, NE, NE);
}

// round 8
// speedup vs baseline: 6.7688x; 1.3253x over previous
#include <cuda_runtime.h>
#include <cuda_fp16.h>

// Problem constants
#define NB 2
#define NS 2048
#define NE 1024
#define NH 16
#define NHD 64
#define NM (NB * NS)      // 4096
#define NQKV (3 * NE)     // 3072

// Scratch (allocation-free rule: __device__ globals). All fp16.
__device__ __half g_qkv[(size_t)NM * NQKV];    // 24 MB
__device__ __half g_ctx[(size_t)NM * NE];      // 8 MB
__device__ __half g_xt[(size_t)NM * NE];       // 8 MB
__device__ __half g_wqkvt[(size_t)NQKV * NE];  // 6 MB
__device__ __half g_wot[(size_t)NE * NE];      // 2 MB

// ---------------------------------------------------------------------------
// helpers
// ---------------------------------------------------------------------------
__device__ __forceinline__ void mma_f16(float* d, const unsigned* a,
                                        const unsigned* b, const float* c) {
    asm volatile(
        "mma.sync.aligned.m16n8k16.row.col.f32.f16.f16.f32 "
        "{%0,%1,%2,%3}, {%4,%5,%6,%7}, {%8,%9}, {%10,%11,%12,%13};"
        : "=f"(d[0]), "=f"(d[1]), "=f"(d[2]), "=f"(d[3])
        : "r"(a[0]), "r"(a[1]), "r"(a[2]), "r"(a[3]),
          "r"(b[0]), "r"(b[1]),
          "f"(c[0]), "f"(c[1]), "f"(c[2]), "f"(c[3]));
}

#define LDSM4(r, addr) \
    asm volatile("ldmatrix.sync.aligned.m8n8.x4.shared.b16 " \
                 "{%0,%1,%2,%3}, [%4];" \
                 : "=r"((r)[0]), "=r"((r)[1]), "=r"((r)[2]), "=r"((r)[3]) \
                 : "r"(addr))
#define LDSM2(r, addr) \
    asm volatile("ldmatrix.sync.aligned.m8n8.x2.shared.b16 " \
                 "{%0,%1}, [%2];" \
                 : "=r"((r)[0]), "=r"((r)[1]) : "r"(addr))
#define LDSM4T(r, addr) \
    asm volatile("ldmatrix.sync.aligned.m8n8.x4.trans.shared.b16 " \
                 "{%0,%1,%2,%3}, [%4];" \
                 : "=r"((r)[0]), "=r"((r)[1]), "=r"((r)[2]), "=r"((r)[3]) \
                 : "r"(addr))

__device__ __forceinline__ unsigned sptr(const void* p) {
    return (unsigned)__cvta_generic_to_shared(p);
}
#define CP16(dst_s, src_g) \
    asm volatile("cp.async.cg.shared.global [%0], [%1], 16;" \
                 :: "r"(dst_s), "l"(src_g))
#define CPCOMMIT() asm volatile("cp.async.commit_group;")
#define CPWAIT0()  asm volatile("cp.async.wait_group 0;")

__device__ __forceinline__ unsigned packh2(float lo, float hi) {
    __half2 h = __floats2half2_rn(lo, hi);
    return *reinterpret_cast<unsigned*>(&h);
}

// ---------------------------------------------------------------------------
// Elementwise fp32 -> fp16 (8 elems / thread, 16B stores)
// ---------------------------------------------------------------------------
__global__ __launch_bounds__(256) void cvt_f16(
    const float4* __restrict__ src, uint4* __restrict__ dst)
{
    int i = blockIdx.x * 256 + threadIdx.x;
    float4 v0 = src[i * 2];
    float4 v1 = src[i * 2 + 1];
    uint4 u;
    u.x = packh2(v0.x, v0.y);
    u.y = packh2(v0.z, v0.w);
    u.z = packh2(v1.x, v1.y);
    u.w = packh2(v1.z, v1.w);
    dst[i] = u;
}

// ---------------------------------------------------------------------------
// FP16 NT GEMM + bias (fp32 accumulate): C[m][n] = sum_k A[m][k]*W[n][k] + b[n]
// 128x128 tile, BK=64, 256 threads, warp grid 2x4, warp tile 64x32.
// smem rows: 64 halves + 8 pad = 144B stride -> conflict-free ldmatrix.
// 2-stage cp.async. OUT: 0 = fp32, 2 = fp16.
// ---------------------------------------------------------------------------
#define GBUF 18432                          // 128 * 144 bytes
#define GEMM_SMEM_BYTES (4 * GBUF)          // A[2] + W[2] = 73728

template <int OUT>
__global__ __launch_bounds__(256) void gemm_h(
    const __half* __restrict__ A, const __half* __restrict__ W,
    const float* __restrict__ bias, void* __restrict__ Cv,
    int Mdim, int Ndim, int Kdim)
{
    extern __shared__ __align__(16) char smg[];
    const unsigned smem_u = sptr(smg);

    const int tid  = threadIdx.x;
    const int wid  = tid >> 5;
    const int lane = tid & 31;
    const int mg   = wid >> 2;
    const int ng   = wid & 3;
    const int bm   = blockIdx.y * 128;
    const int bn   = blockIdx.x * 128;
    const int lq   = lane >> 2;
    const int lr   = lane & 3;

    const unsigned offA = (mg * 64 + (lane & 15)) * 144 + (lane >> 4) * 16;
    const unsigned offW = (ng * 32 + (lane & 7)) * 144 + ((lane >> 3) & 1) * 16;

    float acc[4][4][4] = {};

    // fill buffer: 128 rows x 8 chunks (16B) per matrix
    auto fill = [&](int kt, int buf) {
        const unsigned ad = smem_u + buf * GBUF;
        const unsigned wd = smem_u + (2 + buf) * GBUF;
        #pragma unroll
        for (int i = 0; i < 4; i++) {
            int idx = i * 256 + tid;
            int row = idx >> 3;
            int seg = idx & 7;
            CP16(ad + row * 144 + seg * 16,
                 A + (size_t)(bm + row) * Kdim + kt + seg * 8);
            CP16(wd + row * 144 + seg * 16,
                 W + (size_t)(bn + row) * Kdim + kt + seg * 8);
        }
        CPCOMMIT();
    };

    fill(0, 0);
    int buf = 0;
    for (int kt = 0; kt < Kdim; kt += 64) {
        CPWAIT0();
        __syncthreads();
        if (kt + 64 < Kdim) fill(kt + 64, buf ^ 1);

        const unsigned abase = smem_u + buf * GBUF + offA;
        const unsigned wbase = smem_u + (2 + buf) * GBUF + offW;
        #pragma unroll
        for (int kc = 0; kc < 4; kc++) {           // k16 steps
            unsigned a[4][4], b[4][2];
            #pragma unroll
            for (int mt = 0; mt < 4; mt++)
                LDSM4(a[mt], abase + mt * 2304 + kc * 32);
            #pragma unroll
            for (int nt = 0; nt < 4; nt++)
                LDSM2(b[nt], wbase + nt * 1152 + kc * 32);
            #pragma unroll
            for (int mt = 0; mt < 4; mt++)
                #pragma unroll
                for (int nt = 0; nt < 4; nt++)
                    mma_f16(acc[mt][nt], a[mt], b[nt], acc[mt][nt]);
        }
        buf ^= 1;
    }

    // epilogue
    #pragma unroll
    for (int mt = 0; mt < 4; mt++) {
        int r0 = bm + mg * 64 + mt * 16 + lq;
        #pragma unroll
        for (int nt = 0; nt < 4; nt++) {
            int col = bn + ng * 32 + nt * 8 + lr * 2;
            float2 bv = *(const float2*)&bias[col];
            float v00 = acc[mt][nt][0] + bv.x;
            float v01 = acc[mt][nt][1] + bv.y;
            float v10 = acc[mt][nt][2] + bv.x;
            float v11 = acc[mt][nt][3] + bv.y;
            if (OUT == 2) {
                __half* C = (__half*)Cv;
                *(unsigned*)&C[(size_t)r0 * Ndim + col]       = packh2(v00, v01);
                *(unsigned*)&C[(size_t)(r0 + 8) * Ndim + col] = packh2(v10, v11);
            } else {
                float* C = (float*)Cv;
                *(float2*)&C[(size_t)r0 * Ndim + col]       = make_float2(v00, v01);
                *(float2*)&C[(size_t)(r0 + 8) * Ndim + col] = make_float2(v10, v11);
            }
        }
    }
}

// ---------------------------------------------------------------------------
// Flash attention, fp16 tensor cores (m16n8k16), fp32 softmax/accum.
// 512 threads = 16 warps, warp grid 8(m) x 2(n); split-key private softmax.
// ctx written fp16.
// ---------------------------------------------------------------------------
#define AQ_B   0                       // Q [128][72] fp16 = 18432 B
#define AK_B   18432                   // K [2][128][72]
#define AV_B   55296                   // V [2][128][72]
#define ARM_B  92160                   // m float [2][128]
#define ARS_B  93184                   // l float [2][128]
#define ATTN_SMEM_BYTES 94208
#define ATHREADS 512

__global__ __launch_bounds__(ATHREADS, 1) void attn_f16(
    const __half* __restrict__ qkv, __half* __restrict__ ctx)
{
    extern __shared__ __align__(16) char smc[];
    const unsigned smem_u = sptr(smc);
    __half* Qs = (__half*)(smc + AQ_B);

    const int tid  = threadIdx.x;
    const int wid  = tid >> 5;
    const int lane = tid & 31;
    const int mg   = wid >> 1;
    const int ng   = wid & 1;
    const int lq   = lane >> 2;
    const int lr   = lane & 3;
    const int q0   = blockIdx.x * 128;
    const int h    = blockIdx.y;
    const int b    = blockIdx.z;

    const __half* base  = qkv + (size_t)b * NS * NQKV + h * (3 * NHD);
    const __half* kbase = base + NHD;
    const __half* vbase = base + 2 * NHD;

    const unsigned offQ = AQ_B + (mg * 16 + (lane & 15)) * 144 + (lane >> 4) * 16;
    const unsigned offK = AK_B + (ng * 64 + (lane & 7)) * 144 + ((lane >> 3) & 1) * 16;
    const unsigned offV = AV_B + (ng * 64 + (lane & 15)) * 144 + (lane >> 4) * 16;

    auto fillKV = [&](int t, int buf) {
        const unsigned kd = smem_u + AK_B + buf * 18432;
        const unsigned vd = smem_u + AV_B + buf * 18432;
        #pragma unroll
        for (int i = 0; i < 2; i++) {
            int idx = i * ATHREADS + tid;
            int row = idx >> 3;
            int seg = idx & 7;
            CP16(kd + row * 144 + seg * 16,
                 kbase + (size_t)(t * 128 + row) * NQKV + seg * 8);
            CP16(vd + row * 144 + seg * 16,
                 vbase + (size_t)(t * 128 + row) * NQKV + seg * 8);
        }
        CPCOMMIT();
    };

    fillKV(0, 0);

    // Q fill with 0.125 scale (exact in fp16)
    {
        const __half2 sc = __floats2half2_rn(0.125f, 0.125f);
        #pragma unroll
        for (int i = 0; i < 2; i++) {
            int idx = i * ATHREADS + tid;
            int row = idx >> 3;
            int seg = idx & 7;
            uint4 v = *(const uint4*)(base + (size_t)(q0 + row) * NQKV + seg * 8);
            __half2* p = (__half2*)&v;
            p[0] = __hmul2(p[0], sc);
            p[1] = __hmul2(p[1], sc);
            p[2] = __hmul2(p[2], sc);
            p[3] = __hmul2(p[3], sc);
            *(uint4*)(Qs + row * 72 + seg * 8) = v;
        }
    }

    float o[8][4] = {};
    float m_run[2] = {-1e30f, -1e30f};
    float l_run[2] = {0.f, 0.f};

    int buf = 0;
    for (int t = 0; t < NS / 128; t++) {
        CPWAIT0();
        __syncthreads();
        if (t + 1 < NS / 128) fillKV(t + 1, buf ^ 1);

        const unsigned qb = smem_u + offQ;
        const unsigned kb = smem_u + offK + buf * 18432;
        const unsigned vb = smem_u + offV + buf * 18432;

        // ---- QK^T (fp16 k16) ----
        float s[8][4] = {};
        #pragma unroll
        for (int kc = 0; kc < 4; kc++) {
            unsigned a[4], kf[8][2];
            LDSM4(a, qb + kc * 32);
            #pragma unroll
            for (int nt = 0; nt < 8; nt++)
                LDSM2(kf[nt], kb + nt * 1152 + kc * 32);
            #pragma unroll
            for (int nt = 0; nt < 8; nt++)
                mma_f16(s[nt], a, kf[nt], s[nt]);
        }

        // ---- private online softmax ----
        #pragma unroll
        for (int hf = 0; hf < 2; hf++) {
            float v = -1e30f;
            #pragma unroll
            for (int nt = 0; nt < 8; nt++) {
                v = fmaxf(v, s[nt][hf * 2 + 0]);
                v = fmaxf(v, s[nt][hf * 2 + 1]);
            }
            v = fmaxf(v, __shfl_xor_sync(0xffffffffu, v, 1));
            v = fmaxf(v, __shfl_xor_sync(0xffffffffu, v, 2));
            float m_new = fmaxf(m_run[hf], v);
            float corr  = __expf(m_run[hf] - m_new);
            m_run[hf] = m_new;
            float rs = 0.f;
            #pragma unroll
            for (int nt = 0; nt < 8; nt++) {
                float p0 = __expf(s[nt][hf * 2 + 0] - m_new);
                float p1 = __expf(s[nt][hf * 2 + 1] - m_new);
                s[nt][hf * 2 + 0] = p0;
                s[nt][hf * 2 + 1] = p1;
                rs += p0 + p1;
            }
            rs += __shfl_xor_sync(0xffffffffu, rs, 1);
            rs += __shfl_xor_sync(0xffffffffu, rs, 2);
            l_run[hf] = l_run[hf] * corr + rs;
            #pragma unroll
            for (int nt = 0; nt < 8; nt++) {
                o[nt][hf * 2 + 0] *= corr;
                o[nt][hf * 2 + 1] *= corr;
            }
        }

        // ---- PV (fp16 k16): P frags from s; V via ldmatrix.trans ----
        #pragma unroll
        for (int kc = 0; kc < 4; kc++) {
            unsigned a[4];
            a[0] = packh2(s[2 * kc + 0][0], s[2 * kc + 0][1]);
            a[1] = packh2(s[2 * kc + 0][2], s[2 * kc + 0][3]);
            a[2] = packh2(s[2 * kc + 1][0], s[2 * kc + 1][1]);
            a[3] = packh2(s[2 * kc + 1][2], s[2 * kc + 1][3]);
            #pragma unroll
            for (int np = 0; np < 4; np++) {
                unsigned vf[4];
                LDSM4T(vf, vb + kc * 2304 + np * 32);
                mma_f16(o[2 * np + 0], a, &vf[0], o[2 * np + 0]);
                mma_f16(o[2 * np + 1], a, &vf[2], o[2 * np + 1]);
            }
        }
        buf ^= 1;
    }

    // ---- epilogue: merge key-slices, normalize, store fp16 ctx ----
    __syncthreads();
    float* rm = (float*)(smc + ARM_B);
    float* rl = (float*)(smc + ARS_B);
    if (lr == 0) {
        rm[ng * 128 + mg * 16 + lq]     = m_run[0];
        rm[ng * 128 + mg * 16 + 8 + lq] = m_run[1];
        rl[ng * 128 + mg * 16 + lq]     = l_run[0];
        rl[ng * 128 + mg * 16 + 8 + lq] = l_run[1];
    }
    __syncthreads();

    float fsc[2], linv[2];
    #pragma unroll
    for (int hf = 0; hf < 2; hf++) {
        int row = mg * 16 + hf * 8 + lq;
        float m0 = rm[row], m1 = rm[128 + row];
        float m_tot = fmaxf(m0, m1);
        float l_tot = rl[row] * __expf(m0 - m_tot)
                    + rl[128 + row] * __expf(m1 - m_tot);
        fsc[hf]  = __expf(m_run[hf] - m_tot);
        linv[hf] = 1.0f / l_tot;
    }

    float* Os = (float*)(smc + AK_B);  // [128][68] floats, aliases K bufs
    if (ng == 1) {
        int r = mg * 16 + lq;
        #pragma unroll
        for (int nt = 0; nt < 8; nt++) {
            int d = nt * 8 + lr * 2;
            *(float2*)&Os[r * 68 + d] =
                make_float2(o[nt][0] * fsc[0], o[nt][1] * fsc[0]);
            *(float2*)&Os[(r + 8) * 68 + d] =
                make_float2(o[nt][2] * fsc[1], o[nt][3] * fsc[1]);
        }
    }
    __syncthreads();
    if (ng == 0) {
        int r = mg * 16 + lq;
        #pragma unroll
        for (int nt = 0; nt < 8; nt++) {
            int d = nt * 8 + lr * 2;
            float2 p0 = *(const float2*)&Os[r * 68 + d];
            float2 p1 = *(const float2*)&Os[(r + 8) * 68 + d];
            unsigned u0 = packh2((o[nt][0] * fsc[0] + p0.x) * linv[0],
                                 (o[nt][1] * fsc[0] + p0.y) * linv[0]);
            unsigned u1 = packh2((o[nt][2] * fsc[1] + p1.x) * linv[1],
                                 (o[nt][3] * fsc[1] + p1.y) * linv[1]);
            size_t g0 = ((size_t)b * NS + q0 + r) * NE + h * NHD + d;
            size_t g1 = ((size_t)b * NS + q0 + r + 8) * NE + h * NHD + d;
            *(unsigned*)&ctx[g0] = u0;
            *(unsigned*)&ctx[g1] = u1;
        }
    }
}

// ---------------------------------------------------------------------------
extern "C" void kernel_launch(void* const* d_in, const int* in_sizes, int n_in,
                              void* d_out, int out_size)
{
    const float* x     = (const float*)d_in[0];
    const float* W_qkv = (const float*)d_in[1];
    const float* b_qkv = (const float*)d_in[2];
    const float* W_out = (const float*)d_in[3];
    const float* b_out = (const float*)d_in[4];
    float* out = (float*)d_out;

    __half *qkv, *ctx, *xt, *wqkvt, *wot;
    cudaGetSymbolAddress((void**)&qkv,   g_qkv);
    cudaGetSymbolAddress((void**)&ctx,   g_ctx);
    cudaGetSymbolAddress((void**)&xt,    g_xt);
    cudaGetSymbolAddress((void**)&wqkvt, g_wqkvt);
    cudaGetSymbolAddress((void**)&wot,   g_wot);

    cudaFuncSetAttribute(gemm_h<2>,
                         cudaFuncAttributeMaxDynamicSharedMemorySize,
                         GEMM_SMEM_BYTES);
    cudaFuncSetAttribute(gemm_h<0>,
                         cudaFuncAttributeMaxDynamicSharedMemorySize,
                         GEMM_SMEM_BYTES);
    cudaFuncSetAttribute(attn_f16,
                         cudaFuncAttributeMaxDynamicSharedMemorySize,
                         ATTN_SMEM_BYTES);

    // 0) pre-convert inputs to fp16 (8 elems/thread)
    cvt_f16<<<(NM * NE) / 2048, 256>>>((const float4*)x, (uint4*)xt);
    cvt_f16<<<(NQKV * NE) / 2048, 256>>>((const float4*)W_qkv, (uint4*)wqkvt);
    cvt_f16<<<(NE * NE) / 2048, 256>>>((const float4*)W_out, (uint4*)wot);

    // 1) QKV projection (fp16 math, fp32 accum, fp16 out)
    dim3 g1(NQKV / 128, NM / 128);
    gemm_h<2><<<g1, 256, GEMM_SMEM_BYTES>>>(xt, wqkvt, b_qkv, qkv,
                                            NM, NQKV, NE);

    // 2) Flash attention (fp16 tensor cores, fp16 ctx out)
    dim3 g2(NS / 128, NH, NB);
    attn_f16<<<g2, ATHREADS, ATTN_SMEM_BYTES>>>(qkv, ctx);

    // 3) Output projection (fp16 math, fp32 accum, fp32 out)
    dim3 g3(NE / 128, NM / 128);
    gemm_h<0><<<g3, 256, GEMM_SMEM_BYTES>>>(ctx, wot, b_out, out,
                                            NM, NE, NE);
}

// round 9
// speedup vs baseline: 7.4381x; 1.0989x over previous
#include <cuda_runtime.h>
#include <cuda_fp16.h>

// Problem constants
#define NB 2
#define NS 2048
#define NE 1024
#define NH 16
#define NHD 64
#define NM (NB * NS)      // 4096
#define NQKV (3 * NE)     // 3072

// Scratch (allocation-free rule: __device__ globals). All fp16.
__device__ __half g_qkv[(size_t)NM * NQKV];    // 24 MB
__device__ __half g_ctx[(size_t)NM * NE];      // 8 MB
__device__ __half g_xt[(size_t)NM * NE];       // 8 MB
__device__ __half g_wqkvt[(size_t)NQKV * NE];  // 6 MB
__device__ __half g_wot[(size_t)NE * NE];      // 2 MB

// ---------------------------------------------------------------------------
// helpers
// ---------------------------------------------------------------------------
__device__ __forceinline__ void mma_f16(float* d, const unsigned* a,
                                        const unsigned* b, const float* c) {
    asm volatile(
        "mma.sync.aligned.m16n8k16.row.col.f32.f16.f16.f32 "
        "{%0,%1,%2,%3}, {%4,%5,%6,%7}, {%8,%9}, {%10,%11,%12,%13};"
        : "=f"(d[0]), "=f"(d[1]), "=f"(d[2]), "=f"(d[3])
        : "r"(a[0]), "r"(a[1]), "r"(a[2]), "r"(a[3]),
          "r"(b[0]), "r"(b[1]),
          "f"(c[0]), "f"(c[1]), "f"(c[2]), "f"(c[3]));
}

#define LDSM4(r, addr) \
    asm volatile("ldmatrix.sync.aligned.m8n8.x4.shared.b16 " \
                 "{%0,%1,%2,%3}, [%4];" \
                 : "=r"((r)[0]), "=r"((r)[1]), "=r"((r)[2]), "=r"((r)[3]) \
                 : "r"(addr))
#define LDSM2(r, addr) \
    asm volatile("ldmatrix.sync.aligned.m8n8.x2.shared.b16 " \
                 "{%0,%1}, [%2];" \
                 : "=r"((r)[0]), "=r"((r)[1]) : "r"(addr))
#define LDSM4T(r, addr) \
    asm volatile("ldmatrix.sync.aligned.m8n8.x4.trans.shared.b16 " \
                 "{%0,%1,%2,%3}, [%4];" \
                 : "=r"((r)[0]), "=r"((r)[1]), "=r"((r)[2]), "=r"((r)[3]) \
                 : "r"(addr))

__device__ __forceinline__ unsigned sptr(const void* p) {
    return (unsigned)__cvta_generic_to_shared(p);
}
#define CP16(dst_s, src_g) \
    asm volatile("cp.async.cg.shared.global [%0], [%1], 16;" \
                 :: "r"(dst_s), "l"(src_g))
#define CPCOMMIT() asm volatile("cp.async.commit_group;")
#define CPWAIT0()  asm volatile("cp.async.wait_group 0;")

__device__ __forceinline__ unsigned packh2(float lo, float hi) {
    __half2 h = __floats2half2_rn(lo, hi);
    return *reinterpret_cast<unsigned*>(&h);
}

// packed fp16 exp2 of two fp32 values
__device__ __forceinline__ unsigned exp2_h2(float t0, float t1) {
    unsigned u = packh2(t0, t1);
    asm("ex2.approx.f16x2 %0, %1;" : "=r"(u) : "r"(u));
    return u;
}

// ---------------------------------------------------------------------------
// Elementwise fp32 -> fp16 (8 elems / thread, 16B stores)
// ---------------------------------------------------------------------------
__global__ __launch_bounds__(256) void cvt_f16(
    const float4* __restrict__ src, uint4* __restrict__ dst)
{
    int i = blockIdx.x * 256 + threadIdx.x;
    float4 v0 = src[i * 2];
    float4 v1 = src[i * 2 + 1];
    uint4 u;
    u.x = packh2(v0.x, v0.y);
    u.y = packh2(v0.z, v0.w);
    u.z = packh2(v1.x, v1.y);
    u.w = packh2(v1.z, v1.w);
    dst[i] = u;
}

// ---------------------------------------------------------------------------
// FP16 NT GEMM + bias (fp32 accumulate). 128x128 tile, BK=64, 256 threads,
// warp grid 2x4 (warp tile 64x32), 2-stage cp.async, ldmatrix loads.
// __launch_bounds__(256,2): force 2 CTAs/SM (regs <= 128).
// OUT: 0 = fp32, 2 = fp16.
// ---------------------------------------------------------------------------
#define GBUF 18432                          // 128 * 144 bytes
#define GEMM_SMEM_BYTES (4 * GBUF)          // 73728

template <int OUT>
__global__ __launch_bounds__(256, 2) void gemm_h(
    const __half* __restrict__ A, const __half* __restrict__ W,
    const float* __restrict__ bias, void* __restrict__ Cv,
    int Mdim, int Ndim, int Kdim)
{
    extern __shared__ __align__(16) char smg[];
    const unsigned smem_u = sptr(smg);

    const int tid  = threadIdx.x;
    const int wid  = tid >> 5;
    const int lane = tid & 31;
    const int mg   = wid >> 2;
    const int ng   = wid & 3;
    const int bm   = blockIdx.y * 128;
    const int bn   = blockIdx.x * 128;
    const int lq   = lane >> 2;
    const int lr   = lane & 3;

    const unsigned offA = (mg * 64 + (lane & 15)) * 144 + (lane >> 4) * 16;
    const unsigned offW = (ng * 32 + (lane & 7)) * 144 + ((lane >> 3) & 1) * 16;

    float acc[4][4][4] = {};

    auto fill = [&](int kt, int buf) {
        const unsigned ad = smem_u + buf * GBUF;
        const unsigned wd = smem_u + (2 + buf) * GBUF;
        #pragma unroll
        for (int i = 0; i < 4; i++) {
            int idx = i * 256 + tid;
            int row = idx >> 3;
            int seg = idx & 7;
            CP16(ad + row * 144 + seg * 16,
                 A + (size_t)(bm + row) * Kdim + kt + seg * 8);
            CP16(wd + row * 144 + seg * 16,
                 W + (size_t)(bn + row) * Kdim + kt + seg * 8);
        }
        CPCOMMIT();
    };

    fill(0, 0);
    int buf = 0;
    for (int kt = 0; kt < Kdim; kt += 64) {
        CPWAIT0();
        __syncthreads();
        if (kt + 64 < Kdim) fill(kt + 64, buf ^ 1);

        const unsigned abase = smem_u + buf * GBUF + offA;
        const unsigned wbase = smem_u + (2 + buf) * GBUF + offW;
        #pragma unroll
        for (int kc = 0; kc < 4; kc++) {
            unsigned a[4][4], b[4][2];
            #pragma unroll
            for (int mt = 0; mt < 4; mt++)
                LDSM4(a[mt], abase + mt * 2304 + kc * 32);
            #pragma unroll
            for (int nt = 0; nt < 4; nt++)
                LDSM2(b[nt], wbase + nt * 1152 + kc * 32);
            #pragma unroll
            for (int mt = 0; mt < 4; mt++)
                #pragma unroll
                for (int nt = 0; nt < 4; nt++)
                    mma_f16(acc[mt][nt], a[mt], b[nt], acc[mt][nt]);
        }
        buf ^= 1;
    }

    // epilogue
    #pragma unroll
    for (int mt = 0; mt < 4; mt++) {
        int r0 = bm + mg * 64 + mt * 16 + lq;
        #pragma unroll
        for (int nt = 0; nt < 4; nt++) {
            int col = bn + ng * 32 + nt * 8 + lr * 2;
            float2 bv = *(const float2*)&bias[col];
            float v00 = acc[mt][nt][0] + bv.x;
            float v01 = acc[mt][nt][1] + bv.y;
            float v10 = acc[mt][nt][2] + bv.x;
            float v11 = acc[mt][nt][3] + bv.y;
            if (OUT == 2) {
                __half* C = (__half*)Cv;
                *(unsigned*)&C[(size_t)r0 * Ndim + col]       = packh2(v00, v01);
                *(unsigned*)&C[(size_t)(r0 + 8) * Ndim + col] = packh2(v10, v11);
            } else {
                float* C = (float*)Cv;
                *(float2*)&C[(size_t)r0 * Ndim + col]       = make_float2(v00, v01);
                *(float2*)&C[(size_t)(r0 + 8) * Ndim + col] = make_float2(v10, v11);
            }
        }
    }
}

// ---------------------------------------------------------------------------
// Flash attention, fp16 tensor cores, fp32 softmax/accum.
// 512 threads = 16 warps, warp grid 8(m) x 2(n); split-key private softmax.
// Softmax exp via ex2.approx.f16x2 (produces packed PV A-frags directly);
// row-sum l accumulated via ones-column MMA (no shuffle reduction).
// ---------------------------------------------------------------------------
#define AQ_B   0                       // Q [128][72] fp16 = 18432 B
#define AK_B   18432                   // K [2][128][72]
#define AV_B   55296                   // V [2][128][72]
#define ARM_B  92160                   // m float [2][128]
#define ARS_B  93184                   // l float [2][128]
#define ATTN_SMEM_BYTES 94208
#define ATHREADS 512
#define L2E 1.44269504f

__global__ __launch_bounds__(ATHREADS, 1) void attn_f16(
    const __half* __restrict__ qkv, __half* __restrict__ ctx)
{
    extern __shared__ __align__(16) char smc[];
    const unsigned smem_u = sptr(smc);
    __half* Qs = (__half*)(smc + AQ_B);

    const int tid  = threadIdx.x;
    const int wid  = tid >> 5;
    const int lane = tid & 31;
    const int mg   = wid >> 1;
    const int ng   = wid & 1;
    const int lq   = lane >> 2;
    const int lr   = lane & 3;
    const int q0   = blockIdx.x * 128;
    const int h    = blockIdx.y;
    const int b    = blockIdx.z;

    const __half* base  = qkv + (size_t)b * NS * NQKV + h * (3 * NHD);
    const __half* kbase = base + NHD;
    const __half* vbase = base + 2 * NHD;

    const unsigned offQ = AQ_B + (mg * 16 + (lane & 15)) * 144 + (lane >> 4) * 16;
    const unsigned offK = AK_B + (ng * 64 + (lane & 7)) * 144 + ((lane >> 3) & 1) * 16;
    const unsigned offV = AV_B + (ng * 64 + (lane & 15)) * 144 + (lane >> 4) * 16;

    auto fillKV = [&](int t, int buf) {
        const unsigned kd = smem_u + AK_B + buf * 18432;
        const unsigned vd = smem_u + AV_B + buf * 18432;
        #pragma unroll
        for (int i = 0; i < 2; i++) {
            int idx = i * ATHREADS + tid;
            int row = idx >> 3;
            int seg = idx & 7;
            CP16(kd + row * 144 + seg * 16,
                 kbase + (size_t)(t * 128 + row) * NQKV + seg * 8);
            CP16(vd + row * 144 + seg * 16,
                 vbase + (size_t)(t * 128 + row) * NQKV + seg * 8);
        }
        CPCOMMIT();
    };

    fillKV(0, 0);

    // Q fill with 0.125 scale (exact in fp16)
    {
        const __half2 sc = __floats2half2_rn(0.125f, 0.125f);
        #pragma unroll
        for (int i = 0; i < 2; i++) {
            int idx = i * ATHREADS + tid;
            int row = idx >> 3;
            int seg = idx & 7;
            uint4 v = *(const uint4*)(base + (size_t)(q0 + row) * NQKV + seg * 8);
            __half2* p = (__half2*)&v;
            p[0] = __hmul2(p[0], sc);
            p[1] = __hmul2(p[1], sc);
            p[2] = __hmul2(p[2], sc);
            p[3] = __hmul2(p[3], sc);
            *(uint4*)(Qs + row * 72 + seg * 8) = v;
        }
    }

    float o[8][4] = {};
    float osum[4] = {};                 // row-sum accumulator (ones-column MMA)
    float m_run[2] = {-1e30f, -1e30f};

    int buf = 0;
    for (int t = 0; t < NS / 128; t++) {
        CPWAIT0();
        __syncthreads();
        if (t + 1 < NS / 128) fillKV(t + 1, buf ^ 1);

        const unsigned qb = smem_u + offQ;
        const unsigned kb = smem_u + offK + buf * 18432;
        const unsigned vb = smem_u + offV + buf * 18432;

        // ---- QK^T (fp16 k16) ----
        float s[8][4] = {};
        #pragma unroll
        for (int kc = 0; kc < 4; kc++) {
            unsigned a[4], kf[8][2];
            LDSM4(a, qb + kc * 32);
            #pragma unroll
            for (int nt = 0; nt < 8; nt++)
                LDSM2(kf[nt], kb + nt * 1152 + kc * 32);
            #pragma unroll
            for (int nt = 0; nt < 8; nt++)
                mma_f16(s[nt], a, kf[nt], s[nt]);
        }

        // ---- softmax: max + fp16x2 exp2 -> packed P fragments ----
        unsigned pf[8][2];
        #pragma unroll
        for (int hf = 0; hf < 2; hf++) {
            float v = -1e30f;
            #pragma unroll
            for (int nt = 0; nt < 8; nt++) {
                v = fmaxf(v, s[nt][hf * 2 + 0]);
                v = fmaxf(v, s[nt][hf * 2 + 1]);
            }
            v = fmaxf(v, __shfl_xor_sync(0xffffffffu, v, 1));
            v = fmaxf(v, __shfl_xor_sync(0xffffffffu, v, 2));
            float m_new = fmaxf(m_run[hf], v);
            float corr  = __expf(m_run[hf] - m_new);
            m_run[hf] = m_new;
            float mb = m_new * L2E;
            #pragma unroll
            for (int nt = 0; nt < 8; nt++) {
                float t0 = fmaf(s[nt][hf * 2 + 0], L2E, -mb);
                float t1 = fmaf(s[nt][hf * 2 + 1], L2E, -mb);
                pf[nt][hf] = exp2_h2(t0, t1);
            }
            #pragma unroll
            for (int nt = 0; nt < 8; nt++) {
                o[nt][hf * 2 + 0] *= corr;
                o[nt][hf * 2 + 1] *= corr;
            }
            osum[hf * 2 + 0] *= corr;
            osum[hf * 2 + 1] *= corr;
        }

        // ---- PV + ones-column row sum ----
        const unsigned ONES2 = 0x3C003C00u;
        unsigned bo[2] = {ONES2, ONES2};
        #pragma unroll
        for (int kc = 0; kc < 4; kc++) {
            unsigned a[4];
            a[0] = pf[2 * kc + 0][0];
            a[1] = pf[2 * kc + 0][1];
            a[2] = pf[2 * kc + 1][0];
            a[3] = pf[2 * kc + 1][1];
            #pragma unroll
            for (int np = 0; np < 4; np++) {
                unsigned vf[4];
                LDSM4T(vf, vb + kc * 2304 + np * 32);
                mma_f16(o[2 * np + 0], a, &vf[0], o[2 * np + 0]);
                mma_f16(o[2 * np + 1], a, &vf[2], o[2 * np + 1]);
            }
            mma_f16(osum, a, bo, osum);
        }
        buf ^= 1;
    }

    // ---- epilogue: merge key-slices, normalize, store fp16 ctx ----
    __syncthreads();
    float* rm = (float*)(smc + ARM_B);
    float* rl = (float*)(smc + ARS_B);
    if (lr == 0) {
        rm[ng * 128 + mg * 16 + lq]     = m_run[0];
        rm[ng * 128 + mg * 16 + 8 + lq] = m_run[1];
        rl[ng * 128 + mg * 16 + lq]     = osum[0];
        rl[ng * 128 + mg * 16 + 8 + lq] = osum[2];
    }
    __syncthreads();

    float fsc[2], linv[2];
    #pragma unroll
    for (int hf = 0; hf < 2; hf++) {
        int row = mg * 16 + hf * 8 + lq;
        float m0 = rm[row], m1 = rm[128 + row];
        float m_tot = fmaxf(m0, m1);
        float l_tot = rl[row] * __expf(m0 - m_tot)
                    + rl[128 + row] * __expf(m1 - m_tot);
        fsc[hf]  = __expf(m_run[hf] - m_tot);
        linv[hf] = 1.0f / l_tot;
    }

    float* Os = (float*)(smc + AK_B);  // [128][68] floats, aliases K bufs
    if (ng == 1) {
        int r = mg * 16 + lq;
        #pragma unroll
        for (int nt = 0; nt < 8; nt++) {
            int d = nt * 8 + lr * 2;
            *(float2*)&Os[r * 68 + d] =
                make_float2(o[nt][0] * fsc[0], o[nt][1] * fsc[0]);
            *(float2*)&Os[(r + 8) * 68 + d] =
                make_float2(o[nt][2] * fsc[1], o[nt][3] * fsc[1]);
        }
    }
    __syncthreads();
    if (ng == 0) {
        int r = mg * 16 + lq;
        #pragma unroll
        for (int nt = 0; nt < 8; nt++) {
            int d = nt * 8 + lr * 2;
            float2 p0 = *(const float2*)&Os[r * 68 + d];
            float2 p1 = *(const float2*)&Os[(r + 8) * 68 + d];
            unsigned u0 = packh2((o[nt][0] * fsc[0] + p0.x) * linv[0],
                                 (o[nt][1] * fsc[0] + p0.y) * linv[0]);
            unsigned u1 = packh2((o[nt][2] * fsc[1] + p1.x) * linv[1],
                                 (o[nt][3] * fsc[1] + p1.y) * linv[1]);
            size_t g0 = ((size_t)b * NS + q0 + r) * NE + h * NHD + d;
            size_t g1 = ((size_t)b * NS + q0 + r + 8) * NE + h * NHD + d;
            *(unsigned*)&ctx[g0] = u0;
            *(unsigned*)&ctx[g1] = u1;
        }
    }
}

// ---------------------------------------------------------------------------
extern "C" void kernel_launch(void* const* d_in, const int* in_sizes, int n_in,
                              void* d_out, int out_size)
{
    const float* x     = (const float*)d_in[0];
    const float* W_qkv = (const float*)d_in[1];
    const float* b_qkv = (const float*)d_in[2];
    const float* W_out = (const float*)d_in[3];
    const float* b_out = (const float*)d_in[4];
    float* out = (float*)d_out;

    __half *qkv, *ctx, *xt, *wqkvt, *wot;
    cudaGetSymbolAddress((void**)&qkv,   g_qkv);
    cudaGetSymbolAddress((void**)&ctx,   g_ctx);
    cudaGetSymbolAddress((void**)&xt,    g_xt);
    cudaGetSymbolAddress((void**)&wqkvt, g_wqkvt);
    cudaGetSymbolAddress((void**)&wot,   g_wot);

    cudaFuncSetAttribute(gemm_h<2>,
                         cudaFuncAttributeMaxDynamicSharedMemorySize,
                         GEMM_SMEM_BYTES);
    cudaFuncSetAttribute(gemm_h<0>,
                         cudaFuncAttributeMaxDynamicSharedMemorySize,
                         GEMM_SMEM_BYTES);
    cudaFuncSetAttribute(attn_f16,
                         cudaFuncAttributeMaxDynamicSharedMemorySize,
                         ATTN_SMEM_BYTES);

    // 0) pre-convert inputs to fp16
    cvt_f16<<<(NM * NE) / 2048, 256>>>((const float4*)x, (uint4*)xt);
    cvt_f16<<<(NQKV * NE) / 2048, 256>>>((const float4*)W_qkv, (uint4*)wqkvt);
    cvt_f16<<<(NE * NE) / 2048, 256>>>((const float4*)W_out, (uint4*)wot);

    // 1) QKV projection (fp16 math, fp32 accum, fp16 out)
    dim3 g1(NQKV / 128, NM / 128);
    gemm_h<2><<<g1, 256, GEMM_SMEM_BYTES>>>(xt, wqkvt, b_qkv, qkv,
                                            NM, NQKV, NE);

    // 2) Flash attention (fp16 tensor cores, fp16 ctx out)
    dim3 g2(NS / 128, NH, NB);
    attn_f16<<<g2, ATHREADS, ATTN_SMEM_BYTES>>>(qkv, ctx);

    // 3) Output projection (fp16 math, fp32 accum, fp32 out)
    dim3 g3(NE / 128, NM / 128);
    gemm_h<0><<<g3, 256, GEMM_SMEM_BYTES>>>(ctx, wot, b_out, out,
                                            NM, NE, NE);
}

// round 10
// speedup vs baseline: 7.7937x; 1.0478x over previous
#include <cuda_runtime.h>
#include <cuda_fp16.h>

// Problem constants
#define NB 2
#define NS 2048
#define NE 1024
#define NH 16
#define NHD 64
#define NM (NB * NS)      // 4096
#define NQKV (3 * NE)     // 3072

// Scratch (allocation-free rule: __device__ globals). All fp16.
__device__ __half g_qkv[(size_t)NM * NQKV];    // 24 MB
__device__ __half g_ctx[(size_t)NM * NE];      // 8 MB
__device__ __half g_xt[(size_t)NM * NE];       // 8 MB
__device__ __half g_wqkvt[(size_t)NQKV * NE];  // 6 MB
__device__ __half g_wot[(size_t)NE * NE];      // 2 MB

// ---------------------------------------------------------------------------
// helpers
// ---------------------------------------------------------------------------
__device__ __forceinline__ void mma_f16(float* d, const unsigned* a,
                                        const unsigned* b, const float* c) {
    asm volatile(
        "mma.sync.aligned.m16n8k16.row.col.f32.f16.f16.f32 "
        "{%0,%1,%2,%3}, {%4,%5,%6,%7}, {%8,%9}, {%10,%11,%12,%13};"
        : "=f"(d[0]), "=f"(d[1]), "=f"(d[2]), "=f"(d[3])
        : "r"(a[0]), "r"(a[1]), "r"(a[2]), "r"(a[3]),
          "r"(b[0]), "r"(b[1]),
          "f"(c[0]), "f"(c[1]), "f"(c[2]), "f"(c[3]));
}

#define LDSM4(r, addr) \
    asm volatile("ldmatrix.sync.aligned.m8n8.x4.shared.b16 " \
                 "{%0,%1,%2,%3}, [%4];" \
                 : "=r"((r)[0]), "=r"((r)[1]), "=r"((r)[2]), "=r"((r)[3]) \
                 : "r"(addr))
#define LDSM2(r, addr) \
    asm volatile("ldmatrix.sync.aligned.m8n8.x2.shared.b16 " \
                 "{%0,%1}, [%2];" \
                 : "=r"((r)[0]), "=r"((r)[1]) : "r"(addr))
#define LDSM4T(r, addr) \
    asm volatile("ldmatrix.sync.aligned.m8n8.x4.trans.shared.b16 " \
                 "{%0,%1,%2,%3}, [%4];" \
                 : "=r"((r)[0]), "=r"((r)[1]), "=r"((r)[2]), "=r"((r)[3]) \
                 : "r"(addr))

__device__ __forceinline__ unsigned sptr(const void* p) {
    return (unsigned)__cvta_generic_to_shared(p);
}
#define CP16(dst_s, src_g) \
    asm volatile("cp.async.cg.shared.global [%0], [%1], 16;" \
                 :: "r"(dst_s), "l"(src_g))
#define CPCOMMIT() asm volatile("cp.async.commit_group;")
#define CPWAIT0()  asm volatile("cp.async.wait_group 0;")

// mbarrier ops
#define MBAR_INIT(addr, cnt) \
    asm volatile("mbarrier.init.shared.b64 [%0], %1;" \
                 :: "r"(addr), "r"(cnt) : "memory")
#define MBAR_ARRIVE(addr) \
    asm volatile("mbarrier.arrive.shared::cta.b64 _, [%0];" \
                 :: "r"(addr) : "memory")
#define CP_MBAR_ARRIVE(addr) \
    asm volatile("cp.async.mbarrier.arrive.noinc.shared::cta.b64 [%0];" \
                 :: "r"(addr) : "memory")
#define MBAR_WAIT_PAR(addr, ph) do { \
    unsigned _d = 0; \
    while (!_d) { \
        asm volatile("{\n\t.reg .pred p;\n\t" \
            "mbarrier.try_wait.parity.acquire.cta.shared::cta.b64 p, [%1], %2, 0x989680;\n\t" \
            "selp.b32 %0, 1, 0, p;\n\t}" \
            : "=r"(_d) : "r"(addr), "r"(ph) : "memory"); \
    } \
} while (0)

__device__ __forceinline__ unsigned packh2(float lo, float hi) {
    __half2 h = __floats2half2_rn(lo, hi);
    return *reinterpret_cast<unsigned*>(&h);
}

// packed fp16 exp2 of two fp32 values
__device__ __forceinline__ unsigned exp2_h2(float t0, float t1) {
    unsigned u = packh2(t0, t1);
    asm("ex2.approx.f16x2 %0, %1;" : "=r"(u) : "r"(u));
    return u;
}

// ---------------------------------------------------------------------------
// Elementwise fp32 -> fp16 (8 elems / thread, 16B stores)
// ---------------------------------------------------------------------------
__global__ __launch_bounds__(256) void cvt_f16(
    const float4* __restrict__ src, uint4* __restrict__ dst)
{
    int i = blockIdx.x * 256 + threadIdx.x;
    float4 v0 = src[i * 2];
    float4 v1 = src[i * 2 + 1];
    uint4 u;
    u.x = packh2(v0.x, v0.y);
    u.y = packh2(v0.z, v0.w);
    u.z = packh2(v1.x, v1.y);
    u.w = packh2(v1.z, v1.w);
    dst[i] = u;
}

// ---------------------------------------------------------------------------
// FP16 NT GEMM + bias (fp32 accumulate) — unchanged from round 9.
// ---------------------------------------------------------------------------
#define GBUF 18432                          // 128 * 144 bytes
#define GEMM_SMEM_BYTES (4 * GBUF)          // 73728

template <int OUT>
__global__ __launch_bounds__(256, 2) void gemm_h(
    const __half* __restrict__ A, const __half* __restrict__ W,
    const float* __restrict__ bias, void* __restrict__ Cv,
    int Mdim, int Ndim, int Kdim)
{
    extern __shared__ __align__(16) char smg[];
    const unsigned smem_u = sptr(smg);

    const int tid  = threadIdx.x;
    const int wid  = tid >> 5;
    const int lane = tid & 31;
    const int mg   = wid >> 2;
    const int ng   = wid & 3;
    const int bm   = blockIdx.y * 128;
    const int bn   = blockIdx.x * 128;
    const int lq   = lane >> 2;
    const int lr   = lane & 3;

    const unsigned offA = (mg * 64 + (lane & 15)) * 144 + (lane >> 4) * 16;
    const unsigned offW = (ng * 32 + (lane & 7)) * 144 + ((lane >> 3) & 1) * 16;

    float acc[4][4][4] = {};

    auto fill = [&](int kt, int buf) {
        const unsigned ad = smem_u + buf * GBUF;
        const unsigned wd = smem_u + (2 + buf) * GBUF;
        #pragma unroll
        for (int i = 0; i < 4; i++) {
            int idx = i * 256 + tid;
            int row = idx >> 3;
            int seg = idx & 7;
            CP16(ad + row * 144 + seg * 16,
                 A + (size_t)(bm + row) * Kdim + kt + seg * 8);
            CP16(wd + row * 144 + seg * 16,
                 W + (size_t)(bn + row) * Kdim + kt + seg * 8);
        }
        CPCOMMIT();
    };

    fill(0, 0);
    int buf = 0;
    for (int kt = 0; kt < Kdim; kt += 64) {
        CPWAIT0();
        __syncthreads();
        if (kt + 64 < Kdim) fill(kt + 64, buf ^ 1);

        const unsigned abase = smem_u + buf * GBUF + offA;
        const unsigned wbase = smem_u + (2 + buf) * GBUF + offW;
        #pragma unroll
        for (int kc = 0; kc < 4; kc++) {
            unsigned a[4][4], b[4][2];
            #pragma unroll
            for (int mt = 0; mt < 4; mt++)
                LDSM4(a[mt], abase + mt * 2304 + kc * 32);
            #pragma unroll
            for (int nt = 0; nt < 4; nt++)
                LDSM2(b[nt], wbase + nt * 1152 + kc * 32);
            #pragma unroll
            for (int mt = 0; mt < 4; mt++)
                #pragma unroll
                for (int nt = 0; nt < 4; nt++)
                    mma_f16(acc[mt][nt], a[mt], b[nt], acc[mt][nt]);
        }
        buf ^= 1;
    }

    // epilogue
    #pragma unroll
    for (int mt = 0; mt < 4; mt++) {
        int r0 = bm + mg * 64 + mt * 16 + lq;
        #pragma unroll
        for (int nt = 0; nt < 4; nt++) {
            int col = bn + ng * 32 + nt * 8 + lr * 2;
            float2 bv = *(const float2*)&bias[col];
            float v00 = acc[mt][nt][0] + bv.x;
            float v01 = acc[mt][nt][1] + bv.y;
            float v10 = acc[mt][nt][2] + bv.x;
            float v11 = acc[mt][nt][3] + bv.y;
            if (OUT == 2) {
                __half* C = (__half*)Cv;
                *(unsigned*)&C[(size_t)r0 * Ndim + col]       = packh2(v00, v01);
                *(unsigned*)&C[(size_t)(r0 + 8) * Ndim + col] = packh2(v10, v11);
            } else {
                float* C = (float*)Cv;
                *(float2*)&C[(size_t)r0 * Ndim + col]       = make_float2(v00, v01);
                *(float2*)&C[(size_t)(r0 + 8) * Ndim + col] = make_float2(v10, v11);
            }
        }
    }
}

// ---------------------------------------------------------------------------
// Flash attention, fp16 tensor cores — decoupled mbarrier pipeline.
// 512 threads = 16 warps, warp grid 8(m) x 2(n); split-key private softmax.
// K/V ring of 3 buffers; full[] signaled by cp.async.mbarrier.arrive from all
// 512 threads; empty[] arrive after last read, waited only at refill time.
// NO __syncthreads in the main loop -> warps decouple and overlap pipes.
// ---------------------------------------------------------------------------
#define AQ_B   0                       // Q [128][72] fp16 = 18432 B
#define AK_B   18432                   // K [3][128][72]  = 55296 B
#define AV_B   73728                   // V [3][128][72]  = 55296 B
#define ARM_B  129024                  // m float [2][128]
#define ARS_B  130048                  // l float [2][128]
#define AMB_B  131072                  // mbarriers: full[3], empty[3]
#define ATTN_SMEM_BYTES 131200
#define ATHREADS 512
#define NT (NS / 128)                  // 16 key tiles
#define L2E 1.44269504f

__global__ __launch_bounds__(ATHREADS, 1) void attn_f16(
    const __half* __restrict__ qkv, __half* __restrict__ ctx)
{
    extern __shared__ __align__(16) char smc[];
    const unsigned smem_u = sptr(smc);
    __half* Qs = (__half*)(smc + AQ_B);

    const int tid  = threadIdx.x;
    const int wid  = tid >> 5;
    const int lane = tid & 31;
    const int mg   = wid >> 1;
    const int ng   = wid & 1;
    const int lq   = lane >> 2;
    const int lr   = lane & 3;
    const int q0   = blockIdx.x * 128;
    const int h    = blockIdx.y;
    const int b    = blockIdx.z;

    const __half* base  = qkv + (size_t)b * NS * NQKV + h * (3 * NHD);
    const __half* kbase = base + NHD;
    const __half* vbase = base + 2 * NHD;

    const unsigned offQ = AQ_B + (mg * 16 + (lane & 15)) * 144 + (lane >> 4) * 16;
    const unsigned offK = (ng * 64 + (lane & 7)) * 144 + ((lane >> 3) & 1) * 16;
    const unsigned offV = (ng * 64 + (lane & 15)) * 144 + (lane >> 4) * 16;

    const unsigned mb_full  = smem_u + AMB_B;        // 3 x 8B
    const unsigned mb_empty = smem_u + AMB_B + 24;   // 3 x 8B

    // init mbarriers
    if (tid == 0) {
        #pragma unroll
        for (int j = 0; j < 3; j++) {
            MBAR_INIT(mb_full + j * 8, ATHREADS);
            MBAR_INIT(mb_empty + j * 8, ATHREADS);
        }
    }
    __syncthreads();

    // per-thread fill of tile t into ring buffer t%3, signaling full[t%3]
    auto fill = [&](int t) {
        const int bf = t % 3;
        const unsigned kd = smem_u + AK_B + bf * 18432;
        const unsigned vd = smem_u + AV_B + bf * 18432;
        #pragma unroll
        for (int i = 0; i < 2; i++) {
            int idx = i * ATHREADS + tid;
            int row = idx >> 3;
            int seg = idx & 7;
            CP16(kd + row * 144 + seg * 16,
                 kbase + (size_t)(t * 128 + row) * NQKV + seg * 8);
            CP16(vd + row * 144 + seg * 16,
                 vbase + (size_t)(t * 128 + row) * NQKV + seg * 8);
        }
        CP_MBAR_ARRIVE(mb_full + bf * 8);
    };

    fill(0);
    fill(1);

    // Q fill with 0.125 scale (exact in fp16)
    {
        const __half2 sc = __floats2half2_rn(0.125f, 0.125f);
        #pragma unroll
        for (int i = 0; i < 2; i++) {
            int idx = i * ATHREADS + tid;
            int row = idx >> 3;
            int seg = idx & 7;
            uint4 v = *(const uint4*)(base + (size_t)(q0 + row) * NQKV + seg * 8);
            __half2* p = (__half2*)&v;
            p[0] = __hmul2(p[0], sc);
            p[1] = __hmul2(p[1], sc);
            p[2] = __hmul2(p[2], sc);
            p[3] = __hmul2(p[3], sc);
            *(uint4*)(Qs + row * 72 + seg * 8) = v;
        }
    }
    __syncthreads();   // Q visible; mbarrier protocol handles K/V from here on

    float o[8][4] = {};
    float osum[4] = {};
    float m_run[2] = {-1e30f, -1e30f};

    for (int t = 0; t < NT; t++) {
        const int bf = t % 3;

        // prefetch tile t+2 into buffer (t+2)%3 (readers were tile t-1)
        {
            int u = t + 2;
            if (u < NT) {
                if (u >= 3)
                    MBAR_WAIT_PAR(mb_empty + (u % 3) * 8, (u / 3 - 1) & 1);
                fill(u);
            }
        }

        // wait K/V of tile t
        MBAR_WAIT_PAR(mb_full + bf * 8, (t / 3) & 1);

        const unsigned qb = smem_u + offQ;
        const unsigned kb = smem_u + AK_B + bf * 18432 + offK;
        const unsigned vb = smem_u + AV_B + bf * 18432 + offV;

        // ---- QK^T (fp16 k16) ----
        float s[8][4] = {};
        #pragma unroll
        for (int kc = 0; kc < 4; kc++) {
            unsigned a[4], kf[8][2];
            LDSM4(a, qb + kc * 32);
            #pragma unroll
            for (int nt = 0; nt < 8; nt++)
                LDSM2(kf[nt], kb + nt * 1152 + kc * 32);
            #pragma unroll
            for (int nt = 0; nt < 8; nt++)
                mma_f16(s[nt], a, kf[nt], s[nt]);
        }

        // ---- softmax: max + fp16x2 exp2 -> packed P fragments ----
        unsigned pf[8][2];
        #pragma unroll
        for (int hf = 0; hf < 2; hf++) {
            float v = -1e30f;
            #pragma unroll
            for (int nt = 0; nt < 8; nt++) {
                v = fmaxf(v, s[nt][hf * 2 + 0]);
                v = fmaxf(v, s[nt][hf * 2 + 1]);
            }
            v = fmaxf(v, __shfl_xor_sync(0xffffffffu, v, 1));
            v = fmaxf(v, __shfl_xor_sync(0xffffffffu, v, 2));
            float m_new = fmaxf(m_run[hf], v);
            float corr  = __expf(m_run[hf] - m_new);
            m_run[hf] = m_new;
            float mb = m_new * L2E;
            #pragma unroll
            for (int nt = 0; nt < 8; nt++) {
                float t0 = fmaf(s[nt][hf * 2 + 0], L2E, -mb);
                float t1 = fmaf(s[nt][hf * 2 + 1], L2E, -mb);
                pf[nt][hf] = exp2_h2(t0, t1);
            }
            #pragma unroll
            for (int nt = 0; nt < 8; nt++) {
                o[nt][hf * 2 + 0] *= corr;
                o[nt][hf * 2 + 1] *= corr;
            }
            osum[hf * 2 + 0] *= corr;
            osum[hf * 2 + 1] *= corr;
        }

        // ---- PV + ones-column row sum ----
        const unsigned ONES2 = 0x3C003C00u;
        unsigned bo[2] = {ONES2, ONES2};
        #pragma unroll
        for (int kc = 0; kc < 4; kc++) {
            unsigned a[4];
            a[0] = pf[2 * kc + 0][0];
            a[1] = pf[2 * kc + 0][1];
            a[2] = pf[2 * kc + 1][0];
            a[3] = pf[2 * kc + 1][1];
            #pragma unroll
            for (int np = 0; np < 4; np++) {
                unsigned vf[4];
                LDSM4T(vf, vb + kc * 2304 + np * 32);
                mma_f16(o[2 * np + 0], a, &vf[0], o[2 * np + 0]);
                mma_f16(o[2 * np + 1], a, &vf[2], o[2 * np + 1]);
            }
            mma_f16(osum, a, bo, osum);
        }

        // done reading buffer bf for this tile
        MBAR_ARRIVE(mb_empty + bf * 8);
    }

    // ---- epilogue: merge key-slices, normalize, store fp16 ctx ----
    __syncthreads();
    float* rm = (float*)(smc + ARM_B);
    float* rl = (float*)(smc + ARS_B);
    if (lr == 0) {
        rm[ng * 128 + mg * 16 + lq]     = m_run[0];
        rm[ng * 128 + mg * 16 + 8 + lq] = m_run[1];
        rl[ng * 128 + mg * 16 + lq]     = osum[0];
        rl[ng * 128 + mg * 16 + 8 + lq] = osum[2];
    }
    __syncthreads();

    float fsc[2], linv[2];
    #pragma unroll
    for (int hf = 0; hf < 2; hf++) {
        int row = mg * 16 + hf * 8 + lq;
        float m0 = rm[row], m1 = rm[128 + row];
        float m_tot = fmaxf(m0, m1);
        float l_tot = rl[row] * __expf(m0 - m_tot)
                    + rl[128 + row] * __expf(m1 - m_tot);
        fsc[hf]  = __expf(m_run[hf] - m_tot);
        linv[hf] = 1.0f / l_tot;
    }

    float* Os = (float*)(smc + AK_B);  // [128][68] floats, aliases K bufs
    if (ng == 1) {
        int r = mg * 16 + lq;
        #pragma unroll
        for (int nt = 0; nt < 8; nt++) {
            int d = nt * 8 + lr * 2;
            *(float2*)&Os[r * 68 + d] =
                make_float2(o[nt][0] * fsc[0], o[nt][1] * fsc[0]);
            *(float2*)&Os[(r + 8) * 68 + d] =
                make_float2(o[nt][2] * fsc[1], o[nt][3] * fsc[1]);
        }
    }
    __syncthreads();
    if (ng == 0) {
        int r = mg * 16 + lq;
        #pragma unroll
        for (int nt = 0; nt < 8; nt++) {
            int d = nt * 8 + lr * 2;
            float2 p0 = *(const float2*)&Os[r * 68 + d];
            float2 p1 = *(const float2*)&Os[(r + 8) * 68 + d];
            unsigned u0 = packh2((o[nt][0] * fsc[0] + p0.x) * linv[0],
                                 (o[nt][1] * fsc[0] + p0.y) * linv[0]);
            unsigned u1 = packh2((o[nt][2] * fsc[1] + p1.x) * linv[1],
                                 (o[nt][3] * fsc[1] + p1.y) * linv[1]);
            size_t g0 = ((size_t)b * NS + q0 + r) * NE + h * NHD + d;
            size_t g1 = ((size_t)b * NS + q0 + r + 8) * NE + h * NHD + d;
            *(unsigned*)&ctx[g0] = u0;
            *(unsigned*)&ctx[g1] = u1;
        }
    }
}

// ---------------------------------------------------------------------------
extern "C" void kernel_launch(void* const* d_in, const int* in_sizes, int n_in,
                              void* d_out, int out_size)
{
    const float* x     = (const float*)d_in[0];
    const float* W_qkv = (const float*)d_in[1];
    const float* b_qkv = (const float*)d_in[2];
    const float* W_out = (const float*)d_in[3];
    const float* b_out = (const float*)d_in[4];
    float* out = (float*)d_out;

    __half *qkv, *ctx, *xt, *wqkvt, *wot;
    cudaGetSymbolAddress((void**)&qkv,   g_qkv);
    cudaGetSymbolAddress((void**)&ctx,   g_ctx);
    cudaGetSymbolAddress((void**)&xt,    g_xt);
    cudaGetSymbolAddress((void**)&wqkvt, g_wqkvt);
    cudaGetSymbolAddress((void**)&wot,   g_wot);

    cudaFuncSetAttribute(gemm_h<2>,
                         cudaFuncAttributeMaxDynamicSharedMemorySize,
                         GEMM_SMEM_BYTES);
    cudaFuncSetAttribute(gemm_h<0>,
                         cudaFuncAttributeMaxDynamicSharedMemorySize,
                         GEMM_SMEM_BYTES);
    cudaFuncSetAttribute(attn_f16,
                         cudaFuncAttributeMaxDynamicSharedMemorySize,
                         ATTN_SMEM_BYTES);

    // 0) pre-convert inputs to fp16
    cvt_f16<<<(NM * NE) / 2048, 256>>>((const float4*)x, (uint4*)xt);
    cvt_f16<<<(NQKV * NE) / 2048, 256>>>((const float4*)W_qkv, (uint4*)wqkvt);
    cvt_f16<<<(NE * NE) / 2048, 256>>>((const float4*)W_out, (uint4*)wot);

    // 1) QKV projection (fp16 math, fp32 accum, fp16 out)
    dim3 g1(NQKV / 128, NM / 128);
    gemm_h<2><<<g1, 256, GEMM_SMEM_BYTES>>>(xt, wqkvt, b_qkv, qkv,
                                            NM, NQKV, NE);

    // 2) Flash attention (fp16 tensor cores, decoupled pipeline)
    dim3 g2(NS / 128, NH, NB);
    attn_f16<<<g2, ATHREADS, ATTN_SMEM_BYTES>>>(qkv, ctx);

    // 3) Output projection (fp16 math, fp32 accum, fp32 out)
    dim3 g3(NE / 128, NM / 128);
    gemm_h<0><<<g3, 256, GEMM_SMEM_BYTES>>>(ctx, wot, b_out, out,
                                            NM, NE, NE);
}

// round 11
// speedup vs baseline: 7.8496x; 1.0072x over previous
#include <cuda_runtime.h>
#include <cuda_fp16.h>

// Problem constants
#define NB 2
#define NS 2048
#define NE 1024
#define NH 16
#define NHD 64
#define NM (NB * NS)      // 4096
#define NQKV (3 * NE)     // 3072

// Scratch (allocation-free rule: __device__ globals). All fp16.
__device__ __half g_qkv[(size_t)NM * NQKV];    // 24 MB
__device__ __half g_ctx[(size_t)NM * NE];      // 8 MB
__device__ __half g_xt[(size_t)NM * NE];       // 8 MB
__device__ __half g_wqkvt[(size_t)NQKV * NE];  // 6 MB
__device__ __half g_wot[(size_t)NE * NE];      // 2 MB

// ---------------------------------------------------------------------------
// helpers
// ---------------------------------------------------------------------------
__device__ __forceinline__ void mma_f16(float* d, const unsigned* a,
                                        const unsigned* b, const float* c) {
    asm volatile(
        "mma.sync.aligned.m16n8k16.row.col.f32.f16.f16.f32 "
        "{%0,%1,%2,%3}, {%4,%5,%6,%7}, {%8,%9}, {%10,%11,%12,%13};"
        : "=f"(d[0]), "=f"(d[1]), "=f"(d[2]), "=f"(d[3])
        : "r"(a[0]), "r"(a[1]), "r"(a[2]), "r"(a[3]),
          "r"(b[0]), "r"(b[1]),
          "f"(c[0]), "f"(c[1]), "f"(c[2]), "f"(c[3]));
}

#define LDSM4(r, addr) \
    asm volatile("ldmatrix.sync.aligned.m8n8.x4.shared.b16 " \
                 "{%0,%1,%2,%3}, [%4];" \
                 : "=r"((r)[0]), "=r"((r)[1]), "=r"((r)[2]), "=r"((r)[3]) \
                 : "r"(addr))
#define LDSM4T(r, addr) \
    asm volatile("ldmatrix.sync.aligned.m8n8.x4.trans.shared.b16 " \
                 "{%0,%1,%2,%3}, [%4];" \
                 : "=r"((r)[0]), "=r"((r)[1]), "=r"((r)[2]), "=r"((r)[3]) \
                 : "r"(addr))

__device__ __forceinline__ unsigned sptr(const void* p) {
    return (unsigned)__cvta_generic_to_shared(p);
}
#define CP16(dst_s, src_g) \
    asm volatile("cp.async.cg.shared.global [%0], [%1], 16;" \
                 :: "r"(dst_s), "l"(src_g))
#define CPCOMMIT() asm volatile("cp.async.commit_group;")
#define CPWAIT0()  asm volatile("cp.async.wait_group 0;")

// mbarrier ops
#define MBAR_INIT(addr, cnt) \
    asm volatile("mbarrier.init.shared.b64 [%0], %1;" \
                 :: "r"(addr), "r"(cnt) : "memory")
#define MBAR_ARRIVE(addr) \
    asm volatile("mbarrier.arrive.shared::cta.b64 _, [%0];" \
                 :: "r"(addr) : "memory")
#define CP_MBAR_ARRIVE(addr) \
    asm volatile("cp.async.mbarrier.arrive.noinc.shared::cta.b64 [%0];" \
                 :: "r"(addr) : "memory")
#define MBAR_WAIT_PAR(addr, ph) do { \
    unsigned _d = 0; \
    while (!_d) { \
        asm volatile("{\n\t.reg .pred p;\n\t" \
            "mbarrier.try_wait.parity.acquire.cta.shared::cta.b64 p, [%1], %2, 0x989680;\n\t" \
            "selp.b32 %0, 1, 0, p;\n\t}" \
            : "=r"(_d) : "r"(addr), "r"(ph) : "memory"); \
    } \
} while (0)

__device__ __forceinline__ unsigned packh2(float lo, float hi) {
    __half2 h = __floats2half2_rn(lo, hi);
    return *reinterpret_cast<unsigned*>(&h);
}

__device__ __forceinline__ unsigned exp2_h2(float t0, float t1) {
    unsigned u = packh2(t0, t1);
    asm("ex2.approx.f16x2 %0, %1;" : "=r"(u) : "r"(u));
    return u;
}

// ---------------------------------------------------------------------------
// Elementwise fp32 -> fp16
// ---------------------------------------------------------------------------
__global__ __launch_bounds__(256) void cvt_f16(
    const float4* __restrict__ src, uint4* __restrict__ dst)
{
    int i = blockIdx.x * 256 + threadIdx.x;
    float4 v0 = src[i * 2];
    float4 v1 = src[i * 2 + 1];
    uint4 u;
    u.x = packh2(v0.x, v0.y);
    u.y = packh2(v0.z, v0.w);
    u.z = packh2(v1.x, v1.y);
    u.w = packh2(v1.z, v1.w);
    dst[i] = u;
}

// ---------------------------------------------------------------------------
// FP16 NT GEMM + bias (fp32 accumulate). 128x128 tile, BK=64, 256 threads,
// warp grid 2x4 (warp tile 64x32), 2-stage cp.async.
// W fragments via paired LDSM4 (2 per kc instead of 4 LDSM2).
// ---------------------------------------------------------------------------
#define GBUF 18432                          // 128 * 144 bytes
#define GEMM_SMEM_BYTES (4 * GBUF)          // 73728

template <int OUT>
__global__ __launch_bounds__(256, 2) void gemm_h(
    const __half* __restrict__ A, const __half* __restrict__ W,
    const float* __restrict__ bias, void* __restrict__ Cv,
    int Mdim, int Ndim, int Kdim)
{
    extern __shared__ __align__(16) char smg[];
    const unsigned smem_u = sptr(smg);

    const int tid  = threadIdx.x;
    const int wid  = tid >> 5;
    const int lane = tid & 31;
    const int mg   = wid >> 2;
    const int ng   = wid & 3;
    const int bm   = blockIdx.y * 128;
    const int bn   = blockIdx.x * 128;
    const int lq   = lane >> 2;
    const int lr   = lane & 3;

    const unsigned offA = (mg * 64 + (lane & 15)) * 144 + (lane >> 4) * 16;
    // paired-x4 B layout: rows split by lane>>4 (8 rows), k-half by (lane>>3)&1
    const unsigned offW4 = (ng * 32 + ((lane >> 4) << 3) + (lane & 7)) * 144
                         + ((lane >> 3) & 1) * 16;

    float acc[4][4][4] = {};

    auto fill = [&](int kt, int buf) {
        const unsigned ad = smem_u + buf * GBUF;
        const unsigned wd = smem_u + (2 + buf) * GBUF;
        #pragma unroll
        for (int i = 0; i < 4; i++) {
            int idx = i * 256 + tid;
            int row = idx >> 3;
            int seg = idx & 7;
            CP16(ad + row * 144 + seg * 16,
                 A + (size_t)(bm + row) * Kdim + kt + seg * 8);
            CP16(wd + row * 144 + seg * 16,
                 W + (size_t)(bn + row) * Kdim + kt + seg * 8);
        }
        CPCOMMIT();
    };

    fill(0, 0);
    int buf = 0;
    for (int kt = 0; kt < Kdim; kt += 64) {
        CPWAIT0();
        __syncthreads();
        if (kt + 64 < Kdim) fill(kt + 64, buf ^ 1);

        const unsigned abase = smem_u + buf * GBUF + offA;
        const unsigned wbase = smem_u + (2 + buf) * GBUF + offW4;
        #pragma unroll
        for (int kc = 0; kc < 4; kc++) {
            unsigned a[4][4], b4[2][4];
            #pragma unroll
            for (int mt = 0; mt < 4; mt++)
                LDSM4(a[mt], abase + mt * 2304 + kc * 32);
            #pragma unroll
            for (int p = 0; p < 2; p++)
                LDSM4(b4[p], wbase + p * 2304 + kc * 32);
            #pragma unroll
            for (int mt = 0; mt < 4; mt++)
                #pragma unroll
                for (int nt = 0; nt < 4; nt++)
                    mma_f16(acc[mt][nt], a[mt],
                            &b4[nt >> 1][(nt & 1) * 2], acc[mt][nt]);
        }
        buf ^= 1;
    }

    // epilogue
    #pragma unroll
    for (int mt = 0; mt < 4; mt++) {
        int r0 = bm + mg * 64 + mt * 16 + lq;
        #pragma unroll
        for (int nt = 0; nt < 4; nt++) {
            int col = bn + ng * 32 + nt * 8 + lr * 2;
            float2 bv = *(const float2*)&bias[col];
            float v00 = acc[mt][nt][0] + bv.x;
            float v01 = acc[mt][nt][1] + bv.y;
            float v10 = acc[mt][nt][2] + bv.x;
            float v11 = acc[mt][nt][3] + bv.y;
            if (OUT == 2) {
                __half* C = (__half*)Cv;
                *(unsigned*)&C[(size_t)r0 * Ndim + col]       = packh2(v00, v01);
                *(unsigned*)&C[(size_t)(r0 + 8) * Ndim + col] = packh2(v10, v11);
            } else {
                float* C = (float*)Cv;
                *(float2*)&C[(size_t)r0 * Ndim + col]       = make_float2(v00, v01);
                *(float2*)&C[(size_t)(r0 + 8) * Ndim + col] = make_float2(v10, v11);
            }
        }
    }
}

// ---------------------------------------------------------------------------
// Flash attention, fp16 tensor cores — decoupled mbarrier pipeline.
// Q fragments hoisted into registers (loop-invariant); K fragments via
// paired LDSM4 (16 per tile instead of 32 LDSM2).
// ---------------------------------------------------------------------------
#define AQ_B   0                       // Q [128][72] fp16 = 18432 B
#define AK_B   18432                   // K [3][128][72]  = 55296 B
#define AV_B   73728                   // V [3][128][72]  = 55296 B
#define ARM_B  129024                  // m float [2][128]
#define ARS_B  130048                  // l float [2][128]
#define AMB_B  131072                  // mbarriers: full[3], empty[3]
#define ATTN_SMEM_BYTES 131200
#define ATHREADS 512
#define NTILES (NS / 128)              // 16 key tiles
#define L2E 1.44269504f

__global__ __launch_bounds__(ATHREADS, 1) void attn_f16(
    const __half* __restrict__ qkv, __half* __restrict__ ctx)
{
    extern __shared__ __align__(16) char smc[];
    const unsigned smem_u = sptr(smc);
    __half* Qs = (__half*)(smc + AQ_B);

    const int tid  = threadIdx.x;
    const int wid  = tid >> 5;
    const int lane = tid & 31;
    const int mg   = wid >> 1;
    const int ng   = wid & 1;
    const int lq   = lane >> 2;
    const int lr   = lane & 3;
    const int q0   = blockIdx.x * 128;
    const int h    = blockIdx.y;
    const int b    = blockIdx.z;

    const __half* base  = qkv + (size_t)b * NS * NQKV + h * (3 * NHD);
    const __half* kbase = base + NHD;
    const __half* vbase = base + 2 * NHD;

    const unsigned offQ = AQ_B + (mg * 16 + (lane & 15)) * 144 + (lane >> 4) * 16;
    // paired-x4 K layout (two n-tiles per LDSM4)
    const unsigned offK4 = (ng * 64 + ((lane >> 4) << 3) + (lane & 7)) * 144
                         + ((lane >> 3) & 1) * 16;
    const unsigned offV = (ng * 64 + (lane & 15)) * 144 + (lane >> 4) * 16;

    const unsigned mb_full  = smem_u + AMB_B;        // 3 x 8B
    const unsigned mb_empty = smem_u + AMB_B + 24;   // 3 x 8B

    if (tid == 0) {
        #pragma unroll
        for (int j = 0; j < 3; j++) {
            MBAR_INIT(mb_full + j * 8, ATHREADS);
            MBAR_INIT(mb_empty + j * 8, ATHREADS);
        }
    }
    __syncthreads();

    auto fill = [&](int t) {
        const int bf = t % 3;
        const unsigned kd = smem_u + AK_B + bf * 18432;
        const unsigned vd = smem_u + AV_B + bf * 18432;
        #pragma unroll
        for (int i = 0; i < 2; i++) {
            int idx = i * ATHREADS + tid;
            int row = idx >> 3;
            int seg = idx & 7;
            CP16(kd + row * 144 + seg * 16,
                 kbase + (size_t)(t * 128 + row) * NQKV + seg * 8);
            CP16(vd + row * 144 + seg * 16,
                 vbase + (size_t)(t * 128 + row) * NQKV + seg * 8);
        }
        CP_MBAR_ARRIVE(mb_full + bf * 8);
    };

    fill(0);
    fill(1);

    // Q fill with 0.125 scale (exact in fp16)
    {
        const __half2 sc = __floats2half2_rn(0.125f, 0.125f);
        #pragma unroll
        for (int i = 0; i < 2; i++) {
            int idx = i * ATHREADS + tid;
            int row = idx >> 3;
            int seg = idx & 7;
            uint4 v = *(const uint4*)(base + (size_t)(q0 + row) * NQKV + seg * 8);
            __half2* p = (__half2*)&v;
            p[0] = __hmul2(p[0], sc);
            p[1] = __hmul2(p[1], sc);
            p[2] = __hmul2(p[2], sc);
            p[3] = __hmul2(p[3], sc);
            *(uint4*)(Qs + row * 72 + seg * 8) = v;
        }
    }
    __syncthreads();   // Q visible

    // hoist Q fragments (loop-invariant): 16 regs
    unsigned aq[4][4];
    {
        const unsigned qb = smem_u + offQ;
        #pragma unroll
        for (int kc = 0; kc < 4; kc++)
            LDSM4(aq[kc], qb + kc * 32);
    }

    float o[8][4] = {};
    float osum[4] = {};
    float m_run[2] = {-1e30f, -1e30f};

    for (int t = 0; t < NTILES; t++) {
        const int bf = t % 3;

        // prefetch tile t+2
        {
            int u = t + 2;
            if (u < NTILES) {
                if (u >= 3)
                    MBAR_WAIT_PAR(mb_empty + (u % 3) * 8, (u / 3 - 1) & 1);
                fill(u);
            }
        }

        MBAR_WAIT_PAR(mb_full + bf * 8, (t / 3) & 1);

        const unsigned kb = smem_u + AK_B + bf * 18432 + offK4;
        const unsigned vb = smem_u + AV_B + bf * 18432 + offV;

        // ---- QK^T (fp16 k16): K frags via paired LDSM4 ----
        float s[8][4] = {};
        #pragma unroll
        for (int kc = 0; kc < 4; kc++) {
            unsigned kf[4][4];
            #pragma unroll
            for (int p = 0; p < 4; p++)
                LDSM4(kf[p], kb + p * 2304 + kc * 32);
            #pragma unroll
            for (int nt = 0; nt < 8; nt++)
                mma_f16(s[nt], aq[kc],
                        &kf[nt >> 1][(nt & 1) * 2], s[nt]);
        }

        // ---- softmax: max + fp16x2 exp2 -> packed P fragments ----
        unsigned pf[8][2];
        #pragma unroll
        for (int hf = 0; hf < 2; hf++) {
            float v = -1e30f;
            #pragma unroll
            for (int nt = 0; nt < 8; nt++) {
                v = fmaxf(v, s[nt][hf * 2 + 0]);
                v = fmaxf(v, s[nt][hf * 2 + 1]);
            }
            v = fmaxf(v, __shfl_xor_sync(0xffffffffu, v, 1));
            v = fmaxf(v, __shfl_xor_sync(0xffffffffu, v, 2));
            float m_new = fmaxf(m_run[hf], v);
            float corr  = __expf(m_run[hf] - m_new);
            m_run[hf] = m_new;
            float mb = m_new * L2E;
            #pragma unroll
            for (int nt = 0; nt < 8; nt++) {
                float t0 = fmaf(s[nt][hf * 2 + 0], L2E, -mb);
                float t1 = fmaf(s[nt][hf * 2 + 1], L2E, -mb);
                pf[nt][hf] = exp2_h2(t0, t1);
            }
            #pragma unroll
            for (int nt = 0; nt < 8; nt++) {
                o[nt][hf * 2 + 0] *= corr;
                o[nt][hf * 2 + 1] *= corr;
            }
            osum[hf * 2 + 0] *= corr;
            osum[hf * 2 + 1] *= corr;
        }

        // ---- PV + ones-column row sum ----
        const unsigned ONES2 = 0x3C003C00u;
        unsigned bo[2] = {ONES2, ONES2};
        #pragma unroll
        for (int kc = 0; kc < 4; kc++) {
            unsigned a[4];
            a[0] = pf[2 * kc + 0][0];
            a[1] = pf[2 * kc + 0][1];
            a[2] = pf[2 * kc + 1][0];
            a[3] = pf[2 * kc + 1][1];
            #pragma unroll
            for (int np = 0; np < 4; np++) {
                unsigned vf[4];
                LDSM4T(vf, vb + kc * 2304 + np * 32);
                mma_f16(o[2 * np + 0], a, &vf[0], o[2 * np + 0]);
                mma_f16(o[2 * np + 1], a, &vf[2], o[2 * np + 1]);
            }
            mma_f16(osum, a, bo, osum);
        }

        MBAR_ARRIVE(mb_empty + bf * 8);
    }

    // ---- epilogue: merge key-slices, normalize, store fp16 ctx ----
    __syncthreads();
    float* rm = (float*)(smc + ARM_B);
    float* rl = (float*)(smc + ARS_B);
    if (lr == 0) {
        rm[ng * 128 + mg * 16 + lq]     = m_run[0];
        rm[ng * 128 + mg * 16 + 8 + lq] = m_run[1];
        rl[ng * 128 + mg * 16 + lq]     = osum[0];
        rl[ng * 128 + mg * 16 + 8 + lq] = osum[2];
    }
    __syncthreads();

    float fsc[2], linv[2];
    #pragma unroll
    for (int hf = 0; hf < 2; hf++) {
        int row = mg * 16 + hf * 8 + lq;
        float m0 = rm[row], m1 = rm[128 + row];
        float m_tot = fmaxf(m0, m1);
        float l_tot = rl[row] * __expf(m0 - m_tot)
                    + rl[128 + row] * __expf(m1 - m_tot);
        fsc[hf]  = __expf(m_run[hf] - m_tot);
        linv[hf] = 1.0f / l_tot;
    }

    float* Os = (float*)(smc + AK_B);  // [128][68] floats, aliases K bufs
    if (ng == 1) {
        int r = mg * 16 + lq;
        #pragma unroll
        for (int nt = 0; nt < 8; nt++) {
            int d = nt * 8 + lr * 2;
            *(float2*)&Os[r * 68 + d] =
                make_float2(o[nt][0] * fsc[0], o[nt][1] * fsc[0]);
            *(float2*)&Os[(r + 8) * 68 + d] =
                make_float2(o[nt][2] * fsc[1], o[nt][3] * fsc[1]);
        }
    }
    __syncthreads();
    if (ng == 0) {
        int r = mg * 16 + lq;
        #pragma unroll
        for (int nt = 0; nt < 8; nt++) {
            int d = nt * 8 + lr * 2;
            float2 p0 = *(const float2*)&Os[r * 68 + d];
            float2 p1 = *(const float2*)&Os[(r + 8) * 68 + d];
            unsigned u0 = packh2((o[nt][0] * fsc[0] + p0.x) * linv[0],
                                 (o[nt][1] * fsc[0] + p0.y) * linv[0]);
            unsigned u1 = packh2((o[nt][2] * fsc[1] + p1.x) * linv[1],
                                 (o[nt][3] * fsc[1] + p1.y) * linv[1]);
            size_t g0 = ((size_t)b * NS + q0 + r) * NE + h * NHD + d;
            size_t g1 = ((size_t)b * NS + q0 + r + 8) * NE + h * NHD + d;
            *(unsigned*)&ctx[g0] = u0;
            *(unsigned*)&ctx[g1] = u1;
        }
    }
}

// ---------------------------------------------------------------------------
extern "C" void kernel_launch(void* const* d_in, const int* in_sizes, int n_in,
                              void* d_out, int out_size)
{
    const float* x     = (const float*)d_in[0];
    const float* W_qkv = (const float*)d_in[1];
    const float* b_qkv = (const float*)d_in[2];
    const float* W_out = (const float*)d_in[3];
    const float* b_out = (const float*)d_in[4];
    float* out = (float*)d_out;

    __half *qkv, *ctx, *xt, *wqkvt, *wot;
    cudaGetSymbolAddress((void**)&qkv,   g_qkv);
    cudaGetSymbolAddress((void**)&ctx,   g_ctx);
    cudaGetSymbolAddress((void**)&xt,    g_xt);
    cudaGetSymbolAddress((void**)&wqkvt, g_wqkvt);
    cudaGetSymbolAddress((void**)&wot,   g_wot);

    cudaFuncSetAttribute(gemm_h<2>,
                         cudaFuncAttributeMaxDynamicSharedMemorySize,
                         GEMM_SMEM_BYTES);
    cudaFuncSetAttribute(gemm_h<0>,
                         cudaFuncAttributeMaxDynamicSharedMemorySize,
                         GEMM_SMEM_BYTES);
    cudaFuncSetAttribute(attn_f16,
                         cudaFuncAttributeMaxDynamicSharedMemorySize,
                         ATTN_SMEM_BYTES);

    // 0) pre-convert inputs to fp16
    cvt_f16<<<(NM * NE) / 2048, 256>>>((const float4*)x, (uint4*)xt);
    cvt_f16<<<(NQKV * NE) / 2048, 256>>>((const float4*)W_qkv, (uint4*)wqkvt);
    cvt_f16<<<(NE * NE) / 2048, 256>>>((const float4*)W_out, (uint4*)wot);

    // 1) QKV projection (fp16 math, fp32 accum, fp16 out)
    dim3 g1(NQKV / 128, NM / 128);
    gemm_h<2><<<g1, 256, GEMM_SMEM_BYTES>>>(xt, wqkvt, b_qkv, qkv,
                                            NM, NQKV, NE);

    // 2) Flash attention (fp16 tensor cores, decoupled pipeline)
    dim3 g2(NS / 128, NH, NB);
    attn_f16<<<g2, ATHREADS, ATTN_SMEM_BYTES>>>(qkv, ctx);

    // 3) Output projection (fp16 math, fp32 accum, fp32 out)
    dim3 g3(NE / 128, NM / 128);
    gemm_h<0><<<g3, 256, GEMM_SMEM_BYTES>>>(ctx, wot, b_out, out,
                                            NM, NE, NE);
}

// round 12
// speedup vs baseline: 8.0448x; 1.0249x over previous
#include <cuda_runtime.h>
#include <cuda_fp16.h>

// Problem constants
#define NB 2
#define NS 2048
#define NE 1024
#define NH 16
#define NHD 64
#define NM (NB * NS)      // 4096
#define NQKV (3 * NE)     // 3072

// Scratch (allocation-free rule: __device__ globals). All fp16.
__device__ __half g_qkv[(size_t)NM * NQKV];    // 24 MB
__device__ __half g_ctx[(size_t)NM * NE];      // 8 MB
__device__ __half g_xt[(size_t)NM * NE];       // 8 MB
__device__ __half g_wqkvt[(size_t)NQKV * NE];  // 6 MB
__device__ __half g_wot[(size_t)NE * NE];      // 2 MB

// ---------------------------------------------------------------------------
// helpers
// ---------------------------------------------------------------------------
__device__ __forceinline__ void mma_f16(float* d, const unsigned* a,
                                        const unsigned* b, const float* c) {
    asm volatile(
        "mma.sync.aligned.m16n8k16.row.col.f32.f16.f16.f32 "
        "{%0,%1,%2,%3}, {%4,%5,%6,%7}, {%8,%9}, {%10,%11,%12,%13};"
        : "=f"(d[0]), "=f"(d[1]), "=f"(d[2]), "=f"(d[3])
        : "r"(a[0]), "r"(a[1]), "r"(a[2]), "r"(a[3]),
          "r"(b[0]), "r"(b[1]),
          "f"(c[0]), "f"(c[1]), "f"(c[2]), "f"(c[3]));
}

#define LDSM4(r, addr) \
    asm volatile("ldmatrix.sync.aligned.m8n8.x4.shared.b16 " \
                 "{%0,%1,%2,%3}, [%4];" \
                 : "=r"((r)[0]), "=r"((r)[1]), "=r"((r)[2]), "=r"((r)[3]) \
                 : "r"(addr))
#define LDSM4T(r, addr) \
    asm volatile("ldmatrix.sync.aligned.m8n8.x4.trans.shared.b16 " \
                 "{%0,%1,%2,%3}, [%4];" \
                 : "=r"((r)[0]), "=r"((r)[1]), "=r"((r)[2]), "=r"((r)[3]) \
                 : "r"(addr))

__device__ __forceinline__ unsigned sptr(const void* p) {
    return (unsigned)__cvta_generic_to_shared(p);
}
#define CP16(dst_s, src_g) \
    asm volatile("cp.async.cg.shared.global [%0], [%1], 16;" \
                 :: "r"(dst_s), "l"(src_g))
#define CPCOMMIT() asm volatile("cp.async.commit_group;")
#define CPWAIT0()  asm volatile("cp.async.wait_group 0;")

// mbarrier ops
#define MBAR_INIT(addr, cnt) \
    asm volatile("mbarrier.init.shared.b64 [%0], %1;" \
                 :: "r"(addr), "r"(cnt) : "memory")
#define MBAR_ARRIVE(addr) \
    asm volatile("mbarrier.arrive.shared::cta.b64 _, [%0];" \
                 :: "r"(addr) : "memory")
#define CP_MBAR_ARRIVE(addr) \
    asm volatile("cp.async.mbarrier.arrive.noinc.shared::cta.b64 [%0];" \
                 :: "r"(addr) : "memory")
#define MBAR_WAIT_PAR(addr, ph) do { \
    unsigned _d = 0; \
    while (!_d) { \
        asm volatile("{\n\t.reg .pred p;\n\t" \
            "mbarrier.try_wait.parity.acquire.cta.shared::cta.b64 p, [%1], %2, 0x989680;\n\t" \
            "selp.b32 %0, 1, 0, p;\n\t}" \
            : "=r"(_d) : "r"(addr), "r"(ph) : "memory"); \
    } \
} while (0)

__device__ __forceinline__ unsigned packh2(float lo, float hi) {
    __half2 h = __floats2half2_rn(lo, hi);
    return *reinterpret_cast<unsigned*>(&h);
}

__device__ __forceinline__ unsigned exp2_h2(float t0, float t1) {
    unsigned u = packh2(t0, t1);
    asm("ex2.approx.f16x2 %0, %1;" : "=r"(u) : "r"(u));
    return u;
}

// ---------------------------------------------------------------------------
// Elementwise fp32 -> fp16
// ---------------------------------------------------------------------------
__global__ __launch_bounds__(256) void cvt_f16(
    const float4* __restrict__ src, uint4* __restrict__ dst)
{
    int i = blockIdx.x * 256 + threadIdx.x;
    float4 v0 = src[i * 2];
    float4 v1 = src[i * 2 + 1];
    uint4 u;
    u.x = packh2(v0.x, v0.y);
    u.y = packh2(v0.z, v0.w);
    u.z = packh2(v1.x, v1.y);
    u.w = packh2(v1.z, v1.w);
    dst[i] = u;
}

// ---------------------------------------------------------------------------
// FP16 NT GEMM + bias — unchanged from round 11.
// ---------------------------------------------------------------------------
#define GBUF 18432                          // 128 * 144 bytes
#define GEMM_SMEM_BYTES (4 * GBUF)          // 73728

template <int OUT>
__global__ __launch_bounds__(256, 2) void gemm_h(
    const __half* __restrict__ A, const __half* __restrict__ W,
    const float* __restrict__ bias, void* __restrict__ Cv,
    int Mdim, int Ndim, int Kdim)
{
    extern __shared__ __align__(16) char smg[];
    const unsigned smem_u = sptr(smg);

    const int tid  = threadIdx.x;
    const int wid  = tid >> 5;
    const int lane = tid & 31;
    const int mg   = wid >> 2;
    const int ng   = wid & 3;
    const int bm   = blockIdx.y * 128;
    const int bn   = blockIdx.x * 128;
    const int lq   = lane >> 2;
    const int lr   = lane & 3;

    const unsigned offA = (mg * 64 + (lane & 15)) * 144 + (lane >> 4) * 16;
    const unsigned offW4 = (ng * 32 + ((lane >> 4) << 3) + (lane & 7)) * 144
                         + ((lane >> 3) & 1) * 16;

    float acc[4][4][4] = {};

    auto fill = [&](int kt, int buf) {
        const unsigned ad = smem_u + buf * GBUF;
        const unsigned wd = smem_u + (2 + buf) * GBUF;
        #pragma unroll
        for (int i = 0; i < 4; i++) {
            int idx = i * 256 + tid;
            int row = idx >> 3;
            int seg = idx & 7;
            CP16(ad + row * 144 + seg * 16,
                 A + (size_t)(bm + row) * Kdim + kt + seg * 8);
            CP16(wd + row * 144 + seg * 16,
                 W + (size_t)(bn + row) * Kdim + kt + seg * 8);
        }
        CPCOMMIT();
    };

    fill(0, 0);
    int buf = 0;
    for (int kt = 0; kt < Kdim; kt += 64) {
        CPWAIT0();
        __syncthreads();
        if (kt + 64 < Kdim) fill(kt + 64, buf ^ 1);

        const unsigned abase = smem_u + buf * GBUF + offA;
        const unsigned wbase = smem_u + (2 + buf) * GBUF + offW4;
        #pragma unroll
        for (int kc = 0; kc < 4; kc++) {
            unsigned a[4][4], b4[2][4];
            #pragma unroll
            for (int mt = 0; mt < 4; mt++)
                LDSM4(a[mt], abase + mt * 2304 + kc * 32);
            #pragma unroll
            for (int p = 0; p < 2; p++)
                LDSM4(b4[p], wbase + p * 2304 + kc * 32);
            #pragma unroll
            for (int mt = 0; mt < 4; mt++)
                #pragma unroll
                for (int nt = 0; nt < 4; nt++)
                    mma_f16(acc[mt][nt], a[mt],
                            &b4[nt >> 1][(nt & 1) * 2], acc[mt][nt]);
        }
        buf ^= 1;
    }

    #pragma unroll
    for (int mt = 0; mt < 4; mt++) {
        int r0 = bm + mg * 64 + mt * 16 + lq;
        #pragma unroll
        for (int nt = 0; nt < 4; nt++) {
            int col = bn + ng * 32 + nt * 8 + lr * 2;
            float2 bv = *(const float2*)&bias[col];
            float v00 = acc[mt][nt][0] + bv.x;
            float v01 = acc[mt][nt][1] + bv.y;
            float v10 = acc[mt][nt][2] + bv.x;
            float v11 = acc[mt][nt][3] + bv.y;
            if (OUT == 2) {
                __half* C = (__half*)Cv;
                *(unsigned*)&C[(size_t)r0 * Ndim + col]       = packh2(v00, v01);
                *(unsigned*)&C[(size_t)(r0 + 8) * Ndim + col] = packh2(v10, v11);
            } else {
                float* C = (float*)Cv;
                *(float2*)&C[(size_t)r0 * Ndim + col]       = make_float2(v00, v01);
                *(float2*)&C[(size_t)(r0 + 8) * Ndim + col] = make_float2(v10, v11);
            }
        }
    }
}

// ---------------------------------------------------------------------------
// Flash attention v3: 256 threads = 8 warps, warp grid 4(m) x 2(n),
// warp tile 32 q-rows (mt=2) x 64 keys -> 2x fragment reuse, half the
// smem LDSM traffic per HMMA. Decoupled mbarrier pipeline (ring 3).
// ---------------------------------------------------------------------------
#define AQ_B   0                       // Q [128][72] fp16 = 18432 B
#define AK_B   18432                   // K [3][128][72]  = 55296 B
#define AV_B   73728                   // V [3][128][72]  = 55296 B
#define ARM_B  129024                  // m float [2][128]
#define ARS_B  130048                  // l float [2][128]
#define AMB_B  131072                  // mbarriers: full[3], empty[3]
#define ATTN_SMEM_BYTES 131200
#define ATHREADS 256
#define NTILES (NS / 128)              // 16 key tiles
#define L2E 1.44269504f

__global__ __launch_bounds__(ATHREADS, 1) void attn_f16(
    const __half* __restrict__ qkv, __half* __restrict__ ctx)
{
    extern __shared__ __align__(16) char smc[];
    const unsigned smem_u = sptr(smc);
    __half* Qs = (__half*)(smc + AQ_B);

    const int tid  = threadIdx.x;
    const int wid  = tid >> 5;       // 0..7
    const int lane = tid & 31;
    const int mg   = wid >> 1;       // 0..3 -> 32 q-rows each
    const int ng   = wid & 1;        // 0..1 -> 64-key slice
    const int lq   = lane >> 2;
    const int lr   = lane & 3;
    const int q0   = blockIdx.x * 128;
    const int h    = blockIdx.y;
    const int b    = blockIdx.z;

    const __half* base  = qkv + (size_t)b * NS * NQKV + h * (3 * NHD);
    const __half* kbase = base + NHD;
    const __half* vbase = base + 2 * NHD;

    // per-thread ldmatrix byte offsets
    const unsigned offQ  = AQ_B + (mg * 32 + (lane & 15)) * 144 + (lane >> 4) * 16;
    const unsigned offK4 = (ng * 64 + ((lane >> 4) << 3) + (lane & 7)) * 144
                         + ((lane >> 3) & 1) * 16;
    const unsigned offV  = (ng * 64 + (lane & 15)) * 144 + (lane >> 4) * 16;

    const unsigned mb_full  = smem_u + AMB_B;        // 3 x 8B
    const unsigned mb_empty = smem_u + AMB_B + 24;   // 3 x 8B

    if (tid == 0) {
        #pragma unroll
        for (int j = 0; j < 3; j++) {
            MBAR_INIT(mb_full + j * 8, ATHREADS);
            MBAR_INIT(mb_empty + j * 8, ATHREADS);
        }
    }
    __syncthreads();

    auto fill = [&](int t) {
        const int bf = t % 3;
        const unsigned kd = smem_u + AK_B + bf * 18432;
        const unsigned vd = smem_u + AV_B + bf * 18432;
        #pragma unroll
        for (int i = 0; i < 4; i++) {
            int idx = i * ATHREADS + tid;
            int row = idx >> 3;
            int seg = idx & 7;
            CP16(kd + row * 144 + seg * 16,
                 kbase + (size_t)(t * 128 + row) * NQKV + seg * 8);
            CP16(vd + row * 144 + seg * 16,
                 vbase + (size_t)(t * 128 + row) * NQKV + seg * 8);
        }
        CP_MBAR_ARRIVE(mb_full + bf * 8);
    };

    fill(0);
    fill(1);

    // Q fill with 0.125 scale (exact in fp16)
    {
        const __half2 sc = __floats2half2_rn(0.125f, 0.125f);
        #pragma unroll
        for (int i = 0; i < 4; i++) {
            int idx = i * ATHREADS + tid;
            int row = idx >> 3;
            int seg = idx & 7;
            uint4 v = *(const uint4*)(base + (size_t)(q0 + row) * NQKV + seg * 8);
            __half2* p = (__half2*)&v;
            p[0] = __hmul2(p[0], sc);
            p[1] = __hmul2(p[1], sc);
            p[2] = __hmul2(p[2], sc);
            p[3] = __hmul2(p[3], sc);
            *(uint4*)(Qs + row * 72 + seg * 8) = v;
        }
    }
    __syncthreads();   // Q visible

    float o[2][8][4] = {};
    float osum[2][4] = {};
    float m_run[2][2] = {{-1e30f, -1e30f}, {-1e30f, -1e30f}};

    for (int t = 0; t < NTILES; t++) {
        const int bf = t % 3;

        // prefetch tile t+2
        {
            int u = t + 2;
            if (u < NTILES) {
                if (u >= 3)
                    MBAR_WAIT_PAR(mb_empty + (u % 3) * 8, (u / 3 - 1) & 1);
                fill(u);
            }
        }

        MBAR_WAIT_PAR(mb_full + bf * 8, (t / 3) & 1);

        const unsigned qb = smem_u + offQ;
        const unsigned kb = smem_u + AK_B + bf * 18432 + offK4;
        const unsigned vb = smem_u + AV_B + bf * 18432 + offV;

        // ---- QK^T (fp16 k16): 32 q-rows x 64 keys per warp ----
        float s[2][8][4] = {};
        #pragma unroll
        for (int kc = 0; kc < 4; kc++) {
            unsigned aq[2][4], kf[4][4];
            LDSM4(aq[0], qb + kc * 32);
            LDSM4(aq[1], qb + 2304 + kc * 32);
            #pragma unroll
            for (int p = 0; p < 4; p++)
                LDSM4(kf[p], kb + p * 2304 + kc * 32);
            #pragma unroll
            for (int mt = 0; mt < 2; mt++)
                #pragma unroll
                for (int nt = 0; nt < 8; nt++)
                    mma_f16(s[mt][nt], aq[mt],
                            &kf[nt >> 1][(nt & 1) * 2], s[mt][nt]);
        }

        // ---- softmax: max + fp16x2 exp2 -> packed P fragments ----
        unsigned pf[2][8][2];
        #pragma unroll
        for (int mt = 0; mt < 2; mt++) {
            #pragma unroll
            for (int hf = 0; hf < 2; hf++) {
                float v = -1e30f;
                #pragma unroll
                for (int nt = 0; nt < 8; nt++) {
                    v = fmaxf(v, s[mt][nt][hf * 2 + 0]);
                    v = fmaxf(v, s[mt][nt][hf * 2 + 1]);
                }
                v = fmaxf(v, __shfl_xor_sync(0xffffffffu, v, 1));
                v = fmaxf(v, __shfl_xor_sync(0xffffffffu, v, 2));
                float m_new = fmaxf(m_run[mt][hf], v);
                float corr  = __expf(m_run[mt][hf] - m_new);
                m_run[mt][hf] = m_new;
                float mb = m_new * L2E;
                #pragma unroll
                for (int nt = 0; nt < 8; nt++) {
                    float t0 = fmaf(s[mt][nt][hf * 2 + 0], L2E, -mb);
                    float t1 = fmaf(s[mt][nt][hf * 2 + 1], L2E, -mb);
                    pf[mt][nt][hf] = exp2_h2(t0, t1);
                }
                #pragma unroll
                for (int nt = 0; nt < 8; nt++) {
                    o[mt][nt][hf * 2 + 0] *= corr;
                    o[mt][nt][hf * 2 + 1] *= corr;
                }
                osum[mt][hf * 2 + 0] *= corr;
                osum[mt][hf * 2 + 1] *= corr;
            }
        }

        // ---- PV + ones-column row sum (V frags reused across mt) ----
        const unsigned ONES2 = 0x3C003C00u;
        unsigned bo[2] = {ONES2, ONES2};
        #pragma unroll
        for (int kc = 0; kc < 4; kc++) {
            unsigned a[2][4];
            #pragma unroll
            for (int mt = 0; mt < 2; mt++) {
                a[mt][0] = pf[mt][2 * kc + 0][0];
                a[mt][1] = pf[mt][2 * kc + 0][1];
                a[mt][2] = pf[mt][2 * kc + 1][0];
                a[mt][3] = pf[mt][2 * kc + 1][1];
            }
            #pragma unroll
            for (int np = 0; np < 4; np++) {
                unsigned vf[4];
                LDSM4T(vf, vb + kc * 2304 + np * 32);
                #pragma unroll
                for (int mt = 0; mt < 2; mt++) {
                    mma_f16(o[mt][2 * np + 0], a[mt], &vf[0], o[mt][2 * np + 0]);
                    mma_f16(o[mt][2 * np + 1], a[mt], &vf[2], o[mt][2 * np + 1]);
                }
            }
            #pragma unroll
            for (int mt = 0; mt < 2; mt++)
                mma_f16(osum[mt], a[mt], bo, osum[mt]);
        }

        MBAR_ARRIVE(mb_empty + bf * 8);
    }

    // ---- epilogue: merge the two key-slices, normalize, store fp16 ctx ----
    __syncthreads();
    float* rm = (float*)(smc + ARM_B);
    float* rl = (float*)(smc + ARS_B);
    if (lr == 0) {
        #pragma unroll
        for (int mt = 0; mt < 2; mt++) {
            int r = mg * 32 + mt * 16 + lq;
            rm[ng * 128 + r]     = m_run[mt][0];
            rm[ng * 128 + r + 8] = m_run[mt][1];
            rl[ng * 128 + r]     = osum[mt][0];
            rl[ng * 128 + r + 8] = osum[mt][2];
        }
    }
    __syncthreads();

    float fsc[2][2], linv[2][2];
    #pragma unroll
    for (int mt = 0; mt < 2; mt++) {
        #pragma unroll
        for (int hf = 0; hf < 2; hf++) {
            int row = mg * 32 + mt * 16 + hf * 8 + lq;
            float m0 = rm[row], m1 = rm[128 + row];
            float m_tot = fmaxf(m0, m1);
            float l_tot = rl[row] * __expf(m0 - m_tot)
                        + rl[128 + row] * __expf(m1 - m_tot);
            fsc[mt][hf]  = __expf(m_run[mt][hf] - m_tot);
            linv[mt][hf] = 1.0f / l_tot;
        }
    }

    float* Os = (float*)(smc + AK_B);  // [128][68] floats, aliases K bufs
    if (ng == 1) {
        #pragma unroll
        for (int mt = 0; mt < 2; mt++) {
            int r = mg * 32 + mt * 16 + lq;
            #pragma unroll
            for (int nt = 0; nt < 8; nt++) {
                int d = nt * 8 + lr * 2;
                *(float2*)&Os[r * 68 + d] =
                    make_float2(o[mt][nt][0] * fsc[mt][0],
                                o[mt][nt][1] * fsc[mt][0]);
                *(float2*)&Os[(r + 8) * 68 + d] =
                    make_float2(o[mt][nt][2] * fsc[mt][1],
                                o[mt][nt][3] * fsc[mt][1]);
            }
        }
    }
    __syncthreads();
    if (ng == 0) {
        #pragma unroll
        for (int mt = 0; mt < 2; mt++) {
            int r = mg * 32 + mt * 16 + lq;
            #pragma unroll
            for (int nt = 0; nt < 8; nt++) {
                int d = nt * 8 + lr * 2;
                float2 p0 = *(const float2*)&Os[r * 68 + d];
                float2 p1 = *(const float2*)&Os[(r + 8) * 68 + d];
                unsigned u0 = packh2(
                    (o[mt][nt][0] * fsc[mt][0] + p0.x) * linv[mt][0],
                    (o[mt][nt][1] * fsc[mt][0] + p0.y) * linv[mt][0]);
                unsigned u1 = packh2(
                    (o[mt][nt][2] * fsc[mt][1] + p1.x) * linv[mt][1],
                    (o[mt][nt][3] * fsc[mt][1] + p1.y) * linv[mt][1]);
                size_t g0 = ((size_t)b * NS + q0 + r) * NE + h * NHD + d;
                size_t g1 = ((size_t)b * NS + q0 + r + 8) * NE + h * NHD + d;
                *(unsigned*)&ctx[g0] = u0;
                *(unsigned*)&ctx[g1] = u1;
            }
        }
    }
}

// ---------------------------------------------------------------------------
extern "C" void kernel_launch(void* const* d_in, const int* in_sizes, int n_in,
                              void* d_out, int out_size)
{
    const float* x     = (const float*)d_in[0];
    const float* W_qkv = (const float*)d_in[1];
    const float* b_qkv = (const float*)d_in[2];
    const float* W_out = (const float*)d_in[3];
    const float* b_out = (const float*)d_in[4];
    float* out = (float*)d_out;

    __half *qkv, *ctx, *xt, *wqkvt, *wot;
    cudaGetSymbolAddress((void**)&qkv,   g_qkv);
    cudaGetSymbolAddress((void**)&ctx,   g_ctx);
    cudaGetSymbolAddress((void**)&xt,    g_xt);
    cudaGetSymbolAddress((void**)&wqkvt, g_wqkvt);
    cudaGetSymbolAddress((void**)&wot,   g_wot);

    cudaFuncSetAttribute(gemm_h<2>,
                         cudaFuncAttributeMaxDynamicSharedMemorySize,
                         GEMM_SMEM_BYTES);
    cudaFuncSetAttribute(gemm_h<0>,
                         cudaFuncAttributeMaxDynamicSharedMemorySize,
                         GEMM_SMEM_BYTES);
    cudaFuncSetAttribute(attn_f16,
                         cudaFuncAttributeMaxDynamicSharedMemorySize,
                         ATTN_SMEM_BYTES);

    // 0) pre-convert inputs to fp16
    cvt_f16<<<(NM * NE) / 2048, 256>>>((const float4*)x, (uint4*)xt);
    cvt_f16<<<(NQKV * NE) / 2048, 256>>>((const float4*)W_qkv, (uint4*)wqkvt);
    cvt_f16<<<(NE * NE) / 2048, 256>>>((const float4*)W_out, (uint4*)wot);

    // 1) QKV projection (fp16 math, fp32 accum, fp16 out)
    dim3 g1(NQKV / 128, NM / 128);
    gemm_h<2><<<g1, 256, GEMM_SMEM_BYTES>>>(xt, wqkvt, b_qkv, qkv,
                                            NM, NQKV, NE);

    // 2) Flash attention (fp16 tensor cores, 2x fragment reuse)
    dim3 g2(NS / 128, NH, NB);
    attn_f16<<<g2, ATHREADS, ATTN_SMEM_BYTES>>>(qkv, ctx);

    // 3) Output projection (fp16 math, fp32 accum, fp32 out)
    dim3 g3(NE / 128, NM / 128);
    gemm_h<0><<<g3, 256, GEMM_SMEM_BYTES>>>(ctx, wot, b_out, out,
                                            NM, NE, NE);
}

// round 13
// speedup vs baseline: 8.1065x; 1.0077x over previous
#include <cuda_runtime.h>
#include <cuda_fp16.h>

// Problem constants
#define NB 2
#define NS 2048
#define NE 1024
#define NH 16
#define NHD 64
#define NM (NB * NS)      // 4096
#define NQKV (3 * NE)     // 3072

// Scratch (allocation-free rule: __device__ globals). All fp16.
__device__ __half g_qkv[(size_t)NM * NQKV];    // 24 MB
__device__ __half g_ctx[(size_t)NM * NE];      // 8 MB
__device__ __half g_xt[(size_t)NM * NE];       // 8 MB
__device__ __half g_wqkvt[(size_t)NQKV * NE];  // 6 MB
__device__ __half g_wot[(size_t)NE * NE];      // 2 MB

// ---------------------------------------------------------------------------
// helpers
// ---------------------------------------------------------------------------
__device__ __forceinline__ void mma_f16(float* d, const unsigned* a,
                                        const unsigned* b, const float* c) {
    asm volatile(
        "mma.sync.aligned.m16n8k16.row.col.f32.f16.f16.f32 "
        "{%0,%1,%2,%3}, {%4,%5,%6,%7}, {%8,%9}, {%10,%11,%12,%13};"
        : "=f"(d[0]), "=f"(d[1]), "=f"(d[2]), "=f"(d[3])
        : "r"(a[0]), "r"(a[1]), "r"(a[2]), "r"(a[3]),
          "r"(b[0]), "r"(b[1]),
          "f"(c[0]), "f"(c[1]), "f"(c[2]), "f"(c[3]));
}

#define LDSM4(r, addr) \
    asm volatile("ldmatrix.sync.aligned.m8n8.x4.shared.b16 " \
                 "{%0,%1,%2,%3}, [%4];" \
                 : "=r"((r)[0]), "=r"((r)[1]), "=r"((r)[2]), "=r"((r)[3]) \
                 : "r"(addr))
#define LDSM4T(r, addr) \
    asm volatile("ldmatrix.sync.aligned.m8n8.x4.trans.shared.b16 " \
                 "{%0,%1,%2,%3}, [%4];" \
                 : "=r"((r)[0]), "=r"((r)[1]), "=r"((r)[2]), "=r"((r)[3]) \
                 : "r"(addr))

__device__ __forceinline__ unsigned sptr(const void* p) {
    return (unsigned)__cvta_generic_to_shared(p);
}
#define CP16(dst_s, src_g) \
    asm volatile("cp.async.cg.shared.global [%0], [%1], 16;" \
                 :: "r"(dst_s), "l"(src_g))
#define CPCOMMIT() asm volatile("cp.async.commit_group;")
#define CPWAIT0()  asm volatile("cp.async.wait_group 0;")

// mbarrier ops
#define MBAR_INIT(addr, cnt) \
    asm volatile("mbarrier.init.shared.b64 [%0], %1;" \
                 :: "r"(addr), "r"(cnt) : "memory")
#define MBAR_ARRIVE(addr) \
    asm volatile("mbarrier.arrive.shared::cta.b64 _, [%0];" \
                 :: "r"(addr) : "memory")
#define CP_MBAR_ARRIVE(addr) \
    asm volatile("cp.async.mbarrier.arrive.noinc.shared::cta.b64 [%0];" \
                 :: "r"(addr) : "memory")
#define MBAR_WAIT_PAR(addr, ph) do { \
    unsigned _d = 0; \
    while (!_d) { \
        asm volatile("{\n\t.reg .pred p;\n\t" \
            "mbarrier.try_wait.parity.acquire.cta.shared::cta.b64 p, [%1], %2, 0x989680;\n\t" \
            "selp.b32 %0, 1, 0, p;\n\t}" \
            : "=r"(_d) : "r"(addr), "r"(ph) : "memory"); \
    } \
} while (0)

__device__ __forceinline__ unsigned packh2(float lo, float hi) {
    __half2 h = __floats2half2_rn(lo, hi);
    return *reinterpret_cast<unsigned*>(&h);
}

__device__ __forceinline__ unsigned exp2_h2(float t0, float t1) {
    unsigned u = packh2(t0, t1);
    asm("ex2.approx.f16x2 %0, %1;" : "=r"(u) : "r"(u));
    return u;
}

// ---------------------------------------------------------------------------
// Elementwise fp32 -> fp16
// ---------------------------------------------------------------------------
__global__ __launch_bounds__(256) void cvt_f16(
    const float4* __restrict__ src, uint4* __restrict__ dst)
{
    int i = blockIdx.x * 256 + threadIdx.x;
    float4 v0 = src[i * 2];
    float4 v1 = src[i * 2 + 1];
    uint4 u;
    u.x = packh2(v0.x, v0.y);
    u.y = packh2(v0.z, v0.w);
    u.z = packh2(v1.x, v1.y);
    u.w = packh2(v1.z, v1.w);
    dst[i] = u;
}

// ---------------------------------------------------------------------------
// FP16 NT GEMM + bias (fp32 accumulate). 128x128 CTA tile, BK=64,
// 128 threads = 4 warps, warp grid 2x2, warp tile 64x64 (128 B/HMMA smem).
// 2-stage cp.async, __launch_bounds__(128,2) -> 2 CTAs/SM.
// ---------------------------------------------------------------------------
#define GBUF 18432                          // 128 * 144 bytes
#define GEMM_SMEM_BYTES (4 * GBUF)          // 73728
#define GTHREADS 128

template <int OUT>
__global__ __launch_bounds__(GTHREADS, 2) void gemm_h(
    const __half* __restrict__ A, const __half* __restrict__ W,
    const float* __restrict__ bias, void* __restrict__ Cv,
    int Mdim, int Ndim, int Kdim)
{
    extern __shared__ __align__(16) char smg[];
    const unsigned smem_u = sptr(smg);

    const int tid  = threadIdx.x;
    const int wid  = tid >> 5;       // 0..3
    const int lane = tid & 31;
    const int mg   = wid >> 1;       // 0..1 -> 64-row half
    const int ng   = wid & 1;        // 0..1 -> 64-col half
    const int bm   = blockIdx.y * 128;
    const int bn   = blockIdx.x * 128;
    const int lq   = lane >> 2;
    const int lr   = lane & 3;

    const unsigned offA = (mg * 64 + (lane & 15)) * 144 + (lane >> 4) * 16;
    // paired-x4 B layout: 8 rows split by lane>>4, k-half by (lane>>3)&1
    const unsigned offW4 = (ng * 64 + ((lane >> 4) << 3) + (lane & 7)) * 144
                         + ((lane >> 3) & 1) * 16;

    float acc[4][8][4] = {};         // [mt 16-rows][nt 8-cols][frag]

    auto fill = [&](int kt, int buf) {
        const unsigned ad = smem_u + buf * GBUF;
        const unsigned wd = smem_u + (2 + buf) * GBUF;
        #pragma unroll
        for (int i = 0; i < 8; i++) {
            int idx = i * GTHREADS + tid;
            int row = idx >> 3;
            int seg = idx & 7;
            CP16(ad + row * 144 + seg * 16,
                 A + (size_t)(bm + row) * Kdim + kt + seg * 8);
            CP16(wd + row * 144 + seg * 16,
                 W + (size_t)(bn + row) * Kdim + kt + seg * 8);
        }
        CPCOMMIT();
    };

    fill(0, 0);
    int buf = 0;
    for (int kt = 0; kt < Kdim; kt += 64) {
        CPWAIT0();
        __syncthreads();
        if (kt + 64 < Kdim) fill(kt + 64, buf ^ 1);

        const unsigned abase = smem_u + buf * GBUF + offA;
        const unsigned wbase = smem_u + (2 + buf) * GBUF + offW4;
        #pragma unroll
        for (int kc = 0; kc < 4; kc++) {
            unsigned a[4][4], b4[4][4];
            #pragma unroll
            for (int mt = 0; mt < 4; mt++)
                LDSM4(a[mt], abase + mt * 2304 + kc * 32);
            #pragma unroll
            for (int p = 0; p < 4; p++)
                LDSM4(b4[p], wbase + p * 2304 + kc * 32);
            #pragma unroll
            for (int mt = 0; mt < 4; mt++)
                #pragma unroll
                for (int nt = 0; nt < 8; nt++)
                    mma_f16(acc[mt][nt], a[mt],
                            &b4[nt >> 1][(nt & 1) * 2], acc[mt][nt]);
        }
        buf ^= 1;
    }

    // epilogue
    #pragma unroll
    for (int mt = 0; mt < 4; mt++) {
        int r0 = bm + mg * 64 + mt * 16 + lq;
        #pragma unroll
        for (int nt = 0; nt < 8; nt++) {
            int col = bn + ng * 64 + nt * 8 + lr * 2;
            float2 bv = *(const float2*)&bias[col];
            float v00 = acc[mt][nt][0] + bv.x;
            float v01 = acc[mt][nt][1] + bv.y;
            float v10 = acc[mt][nt][2] + bv.x;
            float v11 = acc[mt][nt][3] + bv.y;
            if (OUT == 2) {
                __half* C = (__half*)Cv;
                *(unsigned*)&C[(size_t)r0 * Ndim + col]       = packh2(v00, v01);
                *(unsigned*)&C[(size_t)(r0 + 8) * Ndim + col] = packh2(v10, v11);
            } else {
                float* C = (float*)Cv;
                *(float2*)&C[(size_t)r0 * Ndim + col]       = make_float2(v00, v01);
                *(float2*)&C[(size_t)(r0 + 8) * Ndim + col] = make_float2(v10, v11);
            }
        }
    }
}

// ---------------------------------------------------------------------------
// Flash attention v3 + hoisted Q fragments: 256 threads = 8 warps,
// warp grid 4(m) x 2(n), warp tile 32 q-rows x 64 keys (2x fragment reuse),
// decoupled mbarrier pipeline (ring 3). Q frags loaded once (32 regs).
// ---------------------------------------------------------------------------
#define AQ_B   0                       // Q [128][72] fp16 = 18432 B
#define AK_B   18432                   // K [3][128][72]  = 55296 B
#define AV_B   73728                   // V [3][128][72]  = 55296 B
#define ARM_B  129024                  // m float [2][128]
#define ARS_B  130048                  // l float [2][128]
#define AMB_B  131072                  // mbarriers: full[3], empty[3]
#define ATTN_SMEM_BYTES 131200
#define ATHREADS 256
#define NTILES (NS / 128)              // 16 key tiles
#define L2E 1.44269504f

__global__ __launch_bounds__(ATHREADS, 1) void attn_f16(
    const __half* __restrict__ qkv, __half* __restrict__ ctx)
{
    extern __shared__ __align__(16) char smc[];
    const unsigned smem_u = sptr(smc);
    __half* Qs = (__half*)(smc + AQ_B);

    const int tid  = threadIdx.x;
    const int wid  = tid >> 5;       // 0..7
    const int lane = tid & 31;
    const int mg   = wid >> 1;       // 0..3 -> 32 q-rows each
    const int ng   = wid & 1;        // 0..1 -> 64-key slice
    const int lq   = lane >> 2;
    const int lr   = lane & 3;
    const int q0   = blockIdx.x * 128;
    const int h    = blockIdx.y;
    const int b    = blockIdx.z;

    const __half* base  = qkv + (size_t)b * NS * NQKV + h * (3 * NHD);
    const __half* kbase = base + NHD;
    const __half* vbase = base + 2 * NHD;

    const unsigned offQ  = AQ_B + (mg * 32 + (lane & 15)) * 144 + (lane >> 4) * 16;
    const unsigned offK4 = (ng * 64 + ((lane >> 4) << 3) + (lane & 7)) * 144
                         + ((lane >> 3) & 1) * 16;
    const unsigned offV  = (ng * 64 + (lane & 15)) * 144 + (lane >> 4) * 16;

    const unsigned mb_full  = smem_u + AMB_B;        // 3 x 8B
    const unsigned mb_empty = smem_u + AMB_B + 24;   // 3 x 8B

    if (tid == 0) {
        #pragma unroll
        for (int j = 0; j < 3; j++) {
            MBAR_INIT(mb_full + j * 8, ATHREADS);
            MBAR_INIT(mb_empty + j * 8, ATHREADS);
        }
    }
    __syncthreads();

    auto fill = [&](int t) {
        const int bf = t % 3;
        const unsigned kd = smem_u + AK_B + bf * 18432;
        const unsigned vd = smem_u + AV_B + bf * 18432;
        #pragma unroll
        for (int i = 0; i < 4; i++) {
            int idx = i * ATHREADS + tid;
            int row = idx >> 3;
            int seg = idx & 7;
            CP16(kd + row * 144 + seg * 16,
                 kbase + (size_t)(t * 128 + row) * NQKV + seg * 8);
            CP16(vd + row * 144 + seg * 16,
                 vbase + (size_t)(t * 128 + row) * NQKV + seg * 8);
        }
        CP_MBAR_ARRIVE(mb_full + bf * 8);
    };

    fill(0);
    fill(1);

    // Q fill with 0.125 scale (exact in fp16)
    {
        const __half2 sc = __floats2half2_rn(0.125f, 0.125f);
        #pragma unroll
        for (int i = 0; i < 4; i++) {
            int idx = i * ATHREADS + tid;
            int row = idx >> 3;
            int seg = idx & 7;
            uint4 v = *(const uint4*)(base + (size_t)(q0 + row) * NQKV + seg * 8);
            __half2* p = (__half2*)&v;
            p[0] = __hmul2(p[0], sc);
            p[1] = __hmul2(p[1], sc);
            p[2] = __hmul2(p[2], sc);
            p[3] = __hmul2(p[3], sc);
            *(uint4*)(Qs + row * 72 + seg * 8) = v;
        }
    }
    __syncthreads();   // Q visible

    // hoist Q fragments (loop-invariant, 32 regs)
    unsigned aq[4][2][4];
    {
        const unsigned qb = smem_u + offQ;
        #pragma unroll
        for (int kc = 0; kc < 4; kc++) {
            LDSM4(aq[kc][0], qb + kc * 32);
            LDSM4(aq[kc][1], qb + 2304 + kc * 32);
        }
    }

    float o[2][8][4] = {};
    float osum[2][4] = {};
    float m_run[2][2] = {{-1e30f, -1e30f}, {-1e30f, -1e30f}};

    for (int t = 0; t < NTILES; t++) {
        const int bf = t % 3;

        // prefetch tile t+2
        {
            int u = t + 2;
            if (u < NTILES) {
                if (u >= 3)
                    MBAR_WAIT_PAR(mb_empty + (u % 3) * 8, (u / 3 - 1) & 1);
                fill(u);
            }
        }

        MBAR_WAIT_PAR(mb_full + bf * 8, (t / 3) & 1);

        const unsigned kb = smem_u + AK_B + bf * 18432 + offK4;
        const unsigned vb = smem_u + AV_B + bf * 18432 + offV;

        // ---- QK^T (fp16 k16): 32 q-rows x 64 keys per warp ----
        float s[2][8][4] = {};
        #pragma unroll
        for (int kc = 0; kc < 4; kc++) {
            unsigned kf[4][4];
            #pragma unroll
            for (int p = 0; p < 4; p++)
                LDSM4(kf[p], kb + p * 2304 + kc * 32);
            #pragma unroll
            for (int mt = 0; mt < 2; mt++)
                #pragma unroll
                for (int nt = 0; nt < 8; nt++)
                    mma_f16(s[mt][nt], aq[kc][mt],
                            &kf[nt >> 1][(nt & 1) * 2], s[mt][nt]);
        }

        // ---- softmax: max + fp16x2 exp2 -> packed P fragments ----
        unsigned pf[2][8][2];
        #pragma unroll
        for (int mt = 0; mt < 2; mt++) {
            #pragma unroll
            for (int hf = 0; hf < 2; hf++) {
                float v = -1e30f;
                #pragma unroll
                for (int nt = 0; nt < 8; nt++) {
                    v = fmaxf(v, s[mt][nt][hf * 2 + 0]);
                    v = fmaxf(v, s[mt][nt][hf * 2 + 1]);
                }
                v = fmaxf(v, __shfl_xor_sync(0xffffffffu, v, 1));
                v = fmaxf(v, __shfl_xor_sync(0xffffffffu, v, 2));
                float m_new = fmaxf(m_run[mt][hf], v);
                float corr  = __expf(m_run[mt][hf] - m_new);
                m_run[mt][hf] = m_new;
                float mb = m_new * L2E;
                #pragma unroll
                for (int nt = 0; nt < 8; nt++) {
                    float t0 = fmaf(s[mt][nt][hf * 2 + 0], L2E, -mb);
                    float t1 = fmaf(s[mt][nt][hf * 2 + 1], L2E, -mb);
                    pf[mt][nt][hf] = exp2_h2(t0, t1);
                }
                #pragma unroll
                for (int nt = 0; nt < 8; nt++) {
                    o[mt][nt][hf * 2 + 0] *= corr;
                    o[mt][nt][hf * 2 + 1] *= corr;
                }
                osum[mt][hf * 2 + 0] *= corr;
                osum[mt][hf * 2 + 1] *= corr;
            }
        }

        // ---- PV + ones-column row sum (V frags reused across mt) ----
        const unsigned ONES2 = 0x3C003C00u;
        unsigned bo[2] = {ONES2, ONES2};
        #pragma unroll
        for (int kc = 0; kc < 4; kc++) {
            unsigned a[2][4];
            #pragma unroll
            for (int mt = 0; mt < 2; mt++) {
                a[mt][0] = pf[mt][2 * kc + 0][0];
                a[mt][1] = pf[mt][2 * kc + 0][1];
                a[mt][2] = pf[mt][2 * kc + 1][0];
                a[mt][3] = pf[mt][2 * kc + 1][1];
            }
            #pragma unroll
            for (int np = 0; np < 4; np++) {
                unsigned vf[4];
                LDSM4T(vf, vb + kc * 2304 + np * 32);
                #pragma unroll
                for (int mt = 0; mt < 2; mt++) {
                    mma_f16(o[mt][2 * np + 0], a[mt], &vf[0], o[mt][2 * np + 0]);
                    mma_f16(o[mt][2 * np + 1], a[mt], &vf[2], o[mt][2 * np + 1]);
                }
            }
            #pragma unroll
            for (int mt = 0; mt < 2; mt++)
                mma_f16(osum[mt], a[mt], bo, osum[mt]);
        }

        MBAR_ARRIVE(mb_empty + bf * 8);
    }

    // ---- epilogue: merge the two key-slices, normalize, store fp16 ctx ----
    __syncthreads();
    float* rm = (float*)(smc + ARM_B);
    float* rl = (float*)(smc + ARS_B);
    if (lr == 0) {
        #pragma unroll
        for (int mt = 0; mt < 2; mt++) {
            int r = mg * 32 + mt * 16 + lq;
            rm[ng * 128 + r]     = m_run[mt][0];
            rm[ng * 128 + r + 8] = m_run[mt][1];
            rl[ng * 128 + r]     = osum[mt][0];
            rl[ng * 128 + r + 8] = osum[mt][2];
        }
    }
    __syncthreads();

    float fsc[2][2], linv[2][2];
    #pragma unroll
    for (int mt = 0; mt < 2; mt++) {
        #pragma unroll
        for (int hf = 0; hf < 2; hf++) {
            int row = mg * 32 + mt * 16 + hf * 8 + lq;
            float m0 = rm[row], m1 = rm[128 + row];
            float m_tot = fmaxf(m0, m1);
            float l_tot = rl[row] * __expf(m0 - m_tot)
                        + rl[128 + row] * __expf(m1 - m_tot);
            fsc[mt][hf]  = __expf(m_run[mt][hf] - m_tot);
            linv[mt][hf] = 1.0f / l_tot;
        }
    }

    float* Os = (float*)(smc + AK_B);  // [128][68] floats, aliases K bufs
    if (ng == 1) {
        #pragma unroll
        for (int mt = 0; mt < 2; mt++) {
            int r = mg * 32 + mt * 16 + lq;
            #pragma unroll
            for (int nt = 0; nt < 8; nt++) {
                int d = nt * 8 + lr * 2;
                *(float2*)&Os[r * 68 + d] =
                    make_float2(o[mt][nt][0] * fsc[mt][0],
                                o[mt][nt][1] * fsc[mt][0]);
                *(float2*)&Os[(r + 8) * 68 + d] =
                    make_float2(o[mt][nt][2] * fsc[mt][1],
                                o[mt][nt][3] * fsc[mt][1]);
            }
        }
    }
    __syncthreads();
    if (ng == 0) {
        #pragma unroll
        for (int mt = 0; mt < 2; mt++) {
            int r = mg * 32 + mt * 16 + lq;
            #pragma unroll
            for (int nt = 0; nt < 8; nt++) {
                int d = nt * 8 + lr * 2;
                float2 p0 = *(const float2*)&Os[r * 68 + d];
                float2 p1 = *(const float2*)&Os[(r + 8) * 68 + d];
                unsigned u0 = packh2(
                    (o[mt][nt][0] * fsc[mt][0] + p0.x) * linv[mt][0],
                    (o[mt][nt][1] * fsc[mt][0] + p0.y) * linv[mt][0]);
                unsigned u1 = packh2(
                    (o[mt][nt][2] * fsc[mt][1] + p1.x) * linv[mt][1],
                    (o[mt][nt][3] * fsc[mt][1] + p1.y) * linv[mt][1]);
                size_t g0 = ((size_t)b * NS + q0 + r) * NE + h * NHD + d;
                size_t g1 = ((size_t)b * NS + q0 + r + 8) * NE + h * NHD + d;
                *(unsigned*)&ctx[g0] = u0;
                *(unsigned*)&ctx[g1] = u1;
            }
        }
    }
}

// ---------------------------------------------------------------------------
extern "C" void kernel_launch(void* const* d_in, const int* in_sizes, int n_in,
                              void* d_out, int out_size)
{
    const float* x     = (const float*)d_in[0];
    const float* W_qkv = (const float*)d_in[1];
    const float* b_qkv = (const float*)d_in[2];
    const float* W_out = (const float*)d_in[3];
    const float* b_out = (const float*)d_in[4];
    float* out = (float*)d_out;

    __half *qkv, *ctx, *xt, *wqkvt, *wot;
    cudaGetSymbolAddress((void**)&qkv,   g_qkv);
    cudaGetSymbolAddress((void**)&ctx,   g_ctx);
    cudaGetSymbolAddress((void**)&xt,    g_xt);
    cudaGetSymbolAddress((void**)&wqkvt, g_wqkvt);
    cudaGetSymbolAddress((void**)&wot,   g_wot);

    cudaFuncSetAttribute(gemm_h<2>,
                         cudaFuncAttributeMaxDynamicSharedMemorySize,
                         GEMM_SMEM_BYTES);
    cudaFuncSetAttribute(gemm_h<0>,
                         cudaFuncAttributeMaxDynamicSharedMemorySize,
                         GEMM_SMEM_BYTES);
    cudaFuncSetAttribute(attn_f16,
                         cudaFuncAttributeMaxDynamicSharedMemorySize,
                         ATTN_SMEM_BYTES);

    // 0) pre-convert inputs to fp16
    cvt_f16<<<(NM * NE) / 2048, 256>>>((const float4*)x, (uint4*)xt);
    cvt_f16<<<(NQKV * NE) / 2048, 256>>>((const float4*)W_qkv, (uint4*)wqkvt);
    cvt_f16<<<(NE * NE) / 2048, 256>>>((const float4*)W_out, (uint4*)wot);

    // 1) QKV projection (fp16 math, fp32 accum, fp16 out)
    dim3 g1(NQKV / 128, NM / 128);
    gemm_h<2><<<g1, GTHREADS, GEMM_SMEM_BYTES>>>(xt, wqkvt, b_qkv, qkv,
                                                 NM, NQKV, NE);

    // 2) Flash attention (fp16 tensor cores, 2x fragment reuse + Q hoist)
    dim3 g2(NS / 128, NH, NB);
    attn_f16<<<g2, ATHREADS, ATTN_SMEM_BYTES>>>(qkv, ctx);

    // 3) Output projection (fp16 math, fp32 accum, fp32 out)
    dim3 g3(NE / 128, NM / 128);
    gemm_h<0><<<g3, GTHREADS, GEMM_SMEM_BYTES>>>(ctx, wot, b_out, out,
                                                 NM, NE, NE);
}

// round 14
// speedup vs baseline: 8.4533x; 1.0428x over previous
#include <cuda_runtime.h>
#include <cuda_fp16.h>

// Problem constants
#define NB 2
#define NS 2048
#define NE 1024
#define NH 16
#define NHD 64
#define NM (NB * NS)      // 4096
#define NQKV (3 * NE)     // 3072

// Scratch (allocation-free rule: __device__ globals). All fp16.
__device__ __half g_qkv[(size_t)NM * NQKV];    // 24 MB
__device__ __half g_ctx[(size_t)NM * NE];      // 8 MB
__device__ __half g_xt[(size_t)NM * NE];       // 8 MB
__device__ __half g_wqkvt[(size_t)NQKV * NE];  // 6 MB
__device__ __half g_wot[(size_t)NE * NE];      // 2 MB

// ---------------------------------------------------------------------------
// helpers
// ---------------------------------------------------------------------------
__device__ __forceinline__ void mma_f16(float* d, const unsigned* a,
                                        const unsigned* b, const float* c) {
    asm volatile(
        "mma.sync.aligned.m16n8k16.row.col.f32.f16.f16.f32 "
        "{%0,%1,%2,%3}, {%4,%5,%6,%7}, {%8,%9}, {%10,%11,%12,%13};"
        : "=f"(d[0]), "=f"(d[1]), "=f"(d[2]), "=f"(d[3])
        : "r"(a[0]), "r"(a[1]), "r"(a[2]), "r"(a[3]),
          "r"(b[0]), "r"(b[1]),
          "f"(c[0]), "f"(c[1]), "f"(c[2]), "f"(c[3]));
}

#define LDSM4(r, addr) \
    asm volatile("ldmatrix.sync.aligned.m8n8.x4.shared.b16 " \
                 "{%0,%1,%2,%3}, [%4];" \
                 : "=r"((r)[0]), "=r"((r)[1]), "=r"((r)[2]), "=r"((r)[3]) \
                 : "r"(addr))
#define LDSM4T(r, addr) \
    asm volatile("ldmatrix.sync.aligned.m8n8.x4.trans.shared.b16 " \
                 "{%0,%1,%2,%3}, [%4];" \
                 : "=r"((r)[0]), "=r"((r)[1]), "=r"((r)[2]), "=r"((r)[3]) \
                 : "r"(addr))

__device__ __forceinline__ unsigned sptr(const void* p) {
    return (unsigned)__cvta_generic_to_shared(p);
}
#define CP16(dst_s, src_g) \
    asm volatile("cp.async.cg.shared.global [%0], [%1], 16;" \
                 :: "r"(dst_s), "l"(src_g))
#define CPCOMMIT() asm volatile("cp.async.commit_group;")
#define CPWAIT0()  asm volatile("cp.async.wait_group 0;")

// mbarrier ops
#define MBAR_INIT(addr, cnt) \
    asm volatile("mbarrier.init.shared.b64 [%0], %1;" \
                 :: "r"(addr), "r"(cnt) : "memory")
#define MBAR_ARRIVE(addr) \
    asm volatile("mbarrier.arrive.shared::cta.b64 _, [%0];" \
                 :: "r"(addr) : "memory")
#define CP_MBAR_ARRIVE(addr) \
    asm volatile("cp.async.mbarrier.arrive.noinc.shared::cta.b64 [%0];" \
                 :: "r"(addr) : "memory")
#define MBAR_WAIT_PAR(addr, ph) do { \
    unsigned _d = 0; \
    while (!_d) { \
        asm volatile("{\n\t.reg .pred p;\n\t" \
            "mbarrier.try_wait.parity.acquire.cta.shared::cta.b64 p, [%1], %2, 0x989680;\n\t" \
            "selp.b32 %0, 1, 0, p;\n\t}" \
            : "=r"(_d) : "r"(addr), "r"(ph) : "memory"); \
    } \
} while (0)

__device__ __forceinline__ unsigned packh2(float lo, float hi) {
    __half2 h = __floats2half2_rn(lo, hi);
    return *reinterpret_cast<unsigned*>(&h);
}

__device__ __forceinline__ unsigned exp2_h2(float t0, float t1) {
    unsigned u = packh2(t0, t1);
    asm("ex2.approx.f16x2 %0, %1;" : "=r"(u) : "r"(u));
    return u;
}

// ---------------------------------------------------------------------------
// Merged elementwise fp32 -> fp16 for x, W_qkv, W_out (one launch)
// ---------------------------------------------------------------------------
#define NX4 ((NM * NE) / 8)          // 524288 uint4 outputs
#define NW4 ((NQKV * NE) / 8)        // 393216
#define NO4 ((NE * NE) / 8)          // 131072
#define NCVT (NX4 + NW4 + NO4)       // 1048576

__global__ __launch_bounds__(256) void cvt_all(
    const float4* __restrict__ x,  const float4* __restrict__ wq,
    const float4* __restrict__ wo,
    uint4* __restrict__ xt, uint4* __restrict__ wqt, uint4* __restrict__ wot)
{
    int i = blockIdx.x * 256 + threadIdx.x;
    const float4* src;
    uint4* dst;
    int j;
    if (i < NX4)            { j = i;              src = x;  dst = xt;  }
    else if (i < NX4 + NW4) { j = i - NX4;        src = wq; dst = wqt; }
    else                    { j = i - NX4 - NW4;  src = wo; dst = wot; }
    float4 v0 = src[j * 2];
    float4 v1 = src[j * 2 + 1];
    uint4 u;
    u.x = packh2(v0.x, v0.y);
    u.y = packh2(v0.z, v0.w);
    u.z = packh2(v1.x, v1.y);
    u.w = packh2(v1.z, v1.w);
    dst[j] = u;
}

// ---------------------------------------------------------------------------
// FP16 NT GEMM + bias (round-11 proven config): 128x128 CTA tile, BK=64,
// 256 threads, warp grid 2x4, warp tile 64x32, 2-stage cp.async,
// paired-x4 W fragments, __launch_bounds__(256,2).
// ---------------------------------------------------------------------------
#define GBUF 18432                          // 128 * 144 bytes
#define GEMM_SMEM_BYTES (4 * GBUF)          // 73728

template <int OUT>
__global__ __launch_bounds__(256, 2) void gemm_h(
    const __half* __restrict__ A, const __half* __restrict__ W,
    const float* __restrict__ bias, void* __restrict__ Cv,
    int Mdim, int Ndim, int Kdim)
{
    extern __shared__ __align__(16) char smg[];
    const unsigned smem_u = sptr(smg);

    const int tid  = threadIdx.x;
    const int wid  = tid >> 5;
    const int lane = tid & 31;
    const int mg   = wid >> 2;
    const int ng   = wid & 3;
    const int bm   = blockIdx.y * 128;
    const int bn   = blockIdx.x * 128;
    const int lq   = lane >> 2;
    const int lr   = lane & 3;

    const unsigned offA = (mg * 64 + (lane & 15)) * 144 + (lane >> 4) * 16;
    const unsigned offW4 = (ng * 32 + ((lane >> 4) << 3) + (lane & 7)) * 144
                         + ((lane >> 3) & 1) * 16;

    float acc[4][4][4] = {};

    auto fill = [&](int kt, int buf) {
        const unsigned ad = smem_u + buf * GBUF;
        const unsigned wd = smem_u + (2 + buf) * GBUF;
        #pragma unroll
        for (int i = 0; i < 4; i++) {
            int idx = i * 256 + tid;
            int row = idx >> 3;
            int seg = idx & 7;
            CP16(ad + row * 144 + seg * 16,
                 A + (size_t)(bm + row) * Kdim + kt + seg * 8);
            CP16(wd + row * 144 + seg * 16,
                 W + (size_t)(bn + row) * Kdim + kt + seg * 8);
        }
        CPCOMMIT();
    };

    fill(0, 0);
    int buf = 0;
    for (int kt = 0; kt < Kdim; kt += 64) {
        CPWAIT0();
        __syncthreads();
        if (kt + 64 < Kdim) fill(kt + 64, buf ^ 1);

        const unsigned abase = smem_u + buf * GBUF + offA;
        const unsigned wbase = smem_u + (2 + buf) * GBUF + offW4;
        #pragma unroll
        for (int kc = 0; kc < 4; kc++) {
            unsigned a[4][4], b4[2][4];
            #pragma unroll
            for (int mt = 0; mt < 4; mt++)
                LDSM4(a[mt], abase + mt * 2304 + kc * 32);
            #pragma unroll
            for (int p = 0; p < 2; p++)
                LDSM4(b4[p], wbase + p * 2304 + kc * 32);
            #pragma unroll
            for (int mt = 0; mt < 4; mt++)
                #pragma unroll
                for (int nt = 0; nt < 4; nt++)
                    mma_f16(acc[mt][nt], a[mt],
                            &b4[nt >> 1][(nt & 1) * 2], acc[mt][nt]);
        }
        buf ^= 1;
    }

    #pragma unroll
    for (int mt = 0; mt < 4; mt++) {
        int r0 = bm + mg * 64 + mt * 16 + lq;
        #pragma unroll
        for (int nt = 0; nt < 4; nt++) {
            int col = bn + ng * 32 + nt * 8 + lr * 2;
            float2 bv = *(const float2*)&bias[col];
            float v00 = acc[mt][nt][0] + bv.x;
            float v01 = acc[mt][nt][1] + bv.y;
            float v10 = acc[mt][nt][2] + bv.x;
            float v11 = acc[mt][nt][3] + bv.y;
            if (OUT == 2) {
                __half* C = (__half*)Cv;
                *(unsigned*)&C[(size_t)r0 * Ndim + col]       = packh2(v00, v01);
                *(unsigned*)&C[(size_t)(r0 + 8) * Ndim + col] = packh2(v10, v11);
            } else {
                float* C = (float*)Cv;
                *(float2*)&C[(size_t)r0 * Ndim + col]       = make_float2(v00, v01);
                *(float2*)&C[(size_t)(r0 + 8) * Ndim + col] = make_float2(v10, v11);
            }
        }
    }
}

// ---------------------------------------------------------------------------
// Flash attention v4: 2 CTAs/SM occupancy probe.
// 256 threads = 8 warps, warp grid 4(m) x 2(n), warp tile 16 q-rows x 64 keys.
// CTA q-tile = 64 rows; K/V ring of 2; smem ~84 KB -> 2 CTAs/SM, 16 warps/SM.
// Q fragments hoisted (16 regs). Decoupled mbarrier pipeline per CTA.
// ---------------------------------------------------------------------------
#define AQ_B   0                       // Q [64][72] fp16 = 9216 B
#define AK_B   9216                    // K [2][128][72] = 36864 B
#define AV_B   46080                   // V [2][128][72] = 36864 B
#define ARM_B  82944                   // m float [2][64] = 512
#define ARS_B  83456                   // l float [2][64] = 512
#define AMB_B  83968                   // mbarriers: full[2], empty[2]
#define ATTN_SMEM_BYTES 84096
#define ATHREADS 256
#define NTILES (NS / 128)              // 16 key tiles
#define L2E 1.44269504f

__global__ __launch_bounds__(ATHREADS, 2) void attn_f16(
    const __half* __restrict__ qkv, __half* __restrict__ ctx)
{
    extern __shared__ __align__(16) char smc[];
    const unsigned smem_u = sptr(smc);
    __half* Qs = (__half*)(smc + AQ_B);

    const int tid  = threadIdx.x;
    const int wid  = tid >> 5;       // 0..7
    const int lane = tid & 31;
    const int mg   = wid >> 1;       // 0..3 -> 16 q-rows each
    const int ng   = wid & 1;        // 0..1 -> 64-key slice
    const int lq   = lane >> 2;
    const int lr   = lane & 3;
    const int q0   = blockIdx.x * 64;
    const int h    = blockIdx.y;
    const int b    = blockIdx.z;

    const __half* base  = qkv + (size_t)b * NS * NQKV + h * (3 * NHD);
    const __half* kbase = base + NHD;
    const __half* vbase = base + 2 * NHD;

    const unsigned offQ  = AQ_B + (mg * 16 + (lane & 15)) * 144 + (lane >> 4) * 16;
    const unsigned offK4 = (ng * 64 + ((lane >> 4) << 3) + (lane & 7)) * 144
                         + ((lane >> 3) & 1) * 16;
    const unsigned offV  = (ng * 64 + (lane & 15)) * 144 + (lane >> 4) * 16;

    const unsigned mb_full  = smem_u + AMB_B;        // 2 x 8B
    const unsigned mb_empty = smem_u + AMB_B + 16;   // 2 x 8B

    if (tid == 0) {
        #pragma unroll
        for (int j = 0; j < 2; j++) {
            MBAR_INIT(mb_full + j * 8, ATHREADS);
            MBAR_INIT(mb_empty + j * 8, ATHREADS);
        }
    }
    __syncthreads();

    auto fill = [&](int t) {
        const int bf = t & 1;
        const unsigned kd = smem_u + AK_B + bf * 18432;
        const unsigned vd = smem_u + AV_B + bf * 18432;
        #pragma unroll
        for (int i = 0; i < 4; i++) {
            int idx = i * ATHREADS + tid;
            int row = idx >> 3;
            int seg = idx & 7;
            CP16(kd + row * 144 + seg * 16,
                 kbase + (size_t)(t * 128 + row) * NQKV + seg * 8);
            CP16(vd + row * 144 + seg * 16,
                 vbase + (size_t)(t * 128 + row) * NQKV + seg * 8);
        }
        CP_MBAR_ARRIVE(mb_full + bf * 8);
    };

    fill(0);
    fill(1);

    // Q fill with 0.125 scale (exact in fp16): 64 rows x 8 segs
    {
        const __half2 sc = __floats2half2_rn(0.125f, 0.125f);
        #pragma unroll
        for (int i = 0; i < 2; i++) {
            int idx = i * ATHREADS + tid;
            int row = idx >> 3;
            int seg = idx & 7;
            uint4 v = *(const uint4*)(base + (size_t)(q0 + row) * NQKV + seg * 8);
            __half2* p = (__half2*)&v;
            p[0] = __hmul2(p[0], sc);
            p[1] = __hmul2(p[1], sc);
            p[2] = __hmul2(p[2], sc);
            p[3] = __hmul2(p[3], sc);
            *(uint4*)(Qs + row * 72 + seg * 8) = v;
        }
    }
    __syncthreads();   // Q visible

    // hoist Q fragments (loop-invariant, 16 regs)
    unsigned aq[4][4];
    {
        const unsigned qb = smem_u + offQ;
        #pragma unroll
        for (int kc = 0; kc < 4; kc++)
            LDSM4(aq[kc], qb + kc * 32);
    }

    float o[8][4] = {};
    float osum[4] = {};
    float m_run[2] = {-1e30f, -1e30f};

    for (int t = 0; t < NTILES; t++) {
        const int bf = t & 1;

        MBAR_WAIT_PAR(mb_full + bf * 8, (t >> 1) & 1);

        const unsigned kb = smem_u + AK_B + bf * 18432 + offK4;
        const unsigned vb = smem_u + AV_B + bf * 18432 + offV;

        // ---- QK^T (fp16 k16): 16 q-rows x 64 keys per warp ----
        float s[8][4] = {};
        #pragma unroll
        for (int kc = 0; kc < 4; kc++) {
            unsigned kf[4][4];
            #pragma unroll
            for (int p = 0; p < 4; p++)
                LDSM4(kf[p], kb + p * 2304 + kc * 32);
            #pragma unroll
            for (int nt = 0; nt < 8; nt++)
                mma_f16(s[nt], aq[kc],
                        &kf[nt >> 1][(nt & 1) * 2], s[nt]);
        }

        // ---- softmax: max + fp16x2 exp2 -> packed P fragments ----
        unsigned pf[8][2];
        #pragma unroll
        for (int hf = 0; hf < 2; hf++) {
            float v = -1e30f;
            #pragma unroll
            for (int nt = 0; nt < 8; nt++) {
                v = fmaxf(v, s[nt][hf * 2 + 0]);
                v = fmaxf(v, s[nt][hf * 2 + 1]);
            }
            v = fmaxf(v, __shfl_xor_sync(0xffffffffu, v, 1));
            v = fmaxf(v, __shfl_xor_sync(0xffffffffu, v, 2));
            float m_new = fmaxf(m_run[hf], v);
            float corr  = __expf(m_run[hf] - m_new);
            m_run[hf] = m_new;
            float mb = m_new * L2E;
            #pragma unroll
            for (int nt = 0; nt < 8; nt++) {
                float t0 = fmaf(s[nt][hf * 2 + 0], L2E, -mb);
                float t1 = fmaf(s[nt][hf * 2 + 1], L2E, -mb);
                pf[nt][hf] = exp2_h2(t0, t1);
            }
            #pragma unroll
            for (int nt = 0; nt < 8; nt++) {
                o[nt][hf * 2 + 0] *= corr;
                o[nt][hf * 2 + 1] *= corr;
            }
            osum[hf * 2 + 0] *= corr;
            osum[hf * 2 + 1] *= corr;
        }

        // ---- PV + ones-column row sum ----
        const unsigned ONES2 = 0x3C003C00u;
        unsigned bo[2] = {ONES2, ONES2};
        #pragma unroll
        for (int kc = 0; kc < 4; kc++) {
            unsigned a[4];
            a[0] = pf[2 * kc + 0][0];
            a[1] = pf[2 * kc + 0][1];
            a[2] = pf[2 * kc + 1][0];
            a[3] = pf[2 * kc + 1][1];
            #pragma unroll
            for (int np = 0; np < 4; np++) {
                unsigned vf[4];
                LDSM4T(vf, vb + kc * 2304 + np * 32);
                mma_f16(o[2 * np + 0], a, &vf[0], o[2 * np + 0]);
                mma_f16(o[2 * np + 1], a, &vf[2], o[2 * np + 1]);
            }
            mma_f16(osum, a, bo, osum);
        }

        MBAR_ARRIVE(mb_empty + bf * 8);

        // refill this buffer with tile t+2 (waits all readers done)
        {
            int u = t + 2;
            if (u < NTILES) {
                MBAR_WAIT_PAR(mb_empty + (u & 1) * 8, ((u >> 1) - 1) & 1);
                fill(u);
            }
        }
    }

    // ---- epilogue: merge the two key-slices, normalize, store fp16 ctx ----
    __syncthreads();
    float* rm = (float*)(smc + ARM_B);   // [ng][64]
    float* rl = (float*)(smc + ARS_B);
    if (lr == 0) {
        int r = mg * 16 + lq;
        rm[ng * 64 + r]     = m_run[0];
        rm[ng * 64 + r + 8] = m_run[1];
        rl[ng * 64 + r]     = osum[0];
        rl[ng * 64 + r + 8] = osum[2];
    }
    __syncthreads();

    float fsc[2], linv[2];
    #pragma unroll
    for (int hf = 0; hf < 2; hf++) {
        int row = mg * 16 + hf * 8 + lq;
        float m0 = rm[row], m1 = rm[64 + row];
        float m_tot = fmaxf(m0, m1);
        float l_tot = rl[row] * __expf(m0 - m_tot)
                    + rl[64 + row] * __expf(m1 - m_tot);
        fsc[hf]  = __expf(m_run[hf] - m_tot);
        linv[hf] = 1.0f / l_tot;
    }

    float* Os = (float*)(smc + AK_B);    // [64][68] floats, aliases K buf0
    if (ng == 1) {
        int r = mg * 16 + lq;
        #pragma unroll
        for (int nt = 0; nt < 8; nt++) {
            int d = nt * 8 + lr * 2;
            *(float2*)&Os[r * 68 + d] =
                make_float2(o[nt][0] * fsc[0], o[nt][1] * fsc[0]);
            *(float2*)&Os[(r + 8) * 68 + d] =
                make_float2(o[nt][2] * fsc[1], o[nt][3] * fsc[1]);
        }
    }
    __syncthreads();
    if (ng == 0) {
        int r = mg * 16 + lq;
        #pragma unroll
        for (int nt = 0; nt < 8; nt++) {
            int d = nt * 8 + lr * 2;
            float2 p0 = *(const float2*)&Os[r * 68 + d];
            float2 p1 = *(const float2*)&Os[(r + 8) * 68 + d];
            unsigned u0 = packh2((o[nt][0] * fsc[0] + p0.x) * linv[0],
                                 (o[nt][1] * fsc[0] + p0.y) * linv[0]);
            unsigned u1 = packh2((o[nt][2] * fsc[1] + p1.x) * linv[1],
                                 (o[nt][3] * fsc[1] + p1.y) * linv[1]);
            size_t g0 = ((size_t)b * NS + q0 + r) * NE + h * NHD + d;
            size_t g1 = ((size_t)b * NS + q0 + r + 8) * NE + h * NHD + d;
            *(unsigned*)&ctx[g0] = u0;
            *(unsigned*)&ctx[g1] = u1;
        }
    }
}

// ---------------------------------------------------------------------------
extern "C" void kernel_launch(void* const* d_in, const int* in_sizes, int n_in,
                              void* d_out, int out_size)
{
    const float* x     = (const float*)d_in[0];
    const float* W_qkv = (const float*)d_in[1];
    const float* b_qkv = (const float*)d_in[2];
    const float* W_out = (const float*)d_in[3];
    const float* b_out = (const float*)d_in[4];
    float* out = (float*)d_out;

    __half *qkv, *ctx, *xt, *wqkvt, *wot;
    cudaGetSymbolAddress((void**)&qkv,   g_qkv);
    cudaGetSymbolAddress((void**)&ctx,   g_ctx);
    cudaGetSymbolAddress((void**)&xt,    g_xt);
    cudaGetSymbolAddress((void**)&wqkvt, g_wqkvt);
    cudaGetSymbolAddress((void**)&wot,   g_wot);

    cudaFuncSetAttribute(gemm_h<2>,
                         cudaFuncAttributeMaxDynamicSharedMemorySize,
                         GEMM_SMEM_BYTES);
    cudaFuncSetAttribute(gemm_h<0>,
                         cudaFuncAttributeMaxDynamicSharedMemorySize,
                         GEMM_SMEM_BYTES);
    cudaFuncSetAttribute(attn_f16,
                         cudaFuncAttributeMaxDynamicSharedMemorySize,
                         ATTN_SMEM_BYTES);

    // 0) pre-convert inputs to fp16 (single merged launch)
    cvt_all<<<NCVT / 256, 256>>>((const float4*)x, (const float4*)W_qkv,
                                 (const float4*)W_out,
                                 (uint4*)xt, (uint4*)wqkvt, (uint4*)wot);

    // 1) QKV projection (fp16 math, fp32 accum, fp16 out)
    dim3 g1(NQKV / 128, NM / 128);
    gemm_h<2><<<g1, 256, GEMM_SMEM_BYTES>>>(xt, wqkvt, b_qkv, qkv,
                                            NM, NQKV, NE);

    // 2) Flash attention (fp16 tensor cores, 2 CTAs/SM)
    dim3 g2(NS / 64, NH, NB);
    attn_f16<<<g2, ATHREADS, ATTN_SMEM_BYTES>>>(qkv, ctx);

    // 3) Output projection (fp16 math, fp32 accum, fp32 out)
    dim3 g3(NE / 128, NM / 128);
    gemm_h<0><<<g3, 256, GEMM_SMEM_BYTES>>>(ctx, wot, b_out, out,
                                            NM, NE, NE);
}

// round 15
// speedup vs baseline: 8.7508x; 1.0352x over previous
#include <cuda_runtime.h>
#include <cuda_fp16.h>

// Problem constants
#define NB 2
#define NS 2048
#define NE 1024
#define NH 16
#define NHD 64
#define NM (NB * NS)      // 4096
#define NQKV (3 * NE)     // 3072

// Scratch (allocation-free rule: __device__ globals). All fp16.
__device__ __half g_qkv[(size_t)NM * NQKV];    // 24 MB
__device__ __half g_ctx[(size_t)NM * NE];      // 8 MB
__device__ __half g_xt[(size_t)NM * NE];       // 8 MB
__device__ __half g_wqkvt[(size_t)NQKV * NE];  // 6 MB
__device__ __half g_wot[(size_t)NE * NE];      // 2 MB

// ---------------------------------------------------------------------------
// helpers
// ---------------------------------------------------------------------------
__device__ __forceinline__ void mma_f16(float* d, const unsigned* a,
                                        const unsigned* b, const float* c) {
    asm volatile(
        "mma.sync.aligned.m16n8k16.row.col.f32.f16.f16.f32 "
        "{%0,%1,%2,%3}, {%4,%5,%6,%7}, {%8,%9}, {%10,%11,%12,%13};"
        : "=f"(d[0]), "=f"(d[1]), "=f"(d[2]), "=f"(d[3])
        : "r"(a[0]), "r"(a[1]), "r"(a[2]), "r"(a[3]),
          "r"(b[0]), "r"(b[1]),
          "f"(c[0]), "f"(c[1]), "f"(c[2]), "f"(c[3]));
}

#define LDSM4(r, addr) \
    asm volatile("ldmatrix.sync.aligned.m8n8.x4.shared.b16 " \
                 "{%0,%1,%2,%3}, [%4];" \
                 : "=r"((r)[0]), "=r"((r)[1]), "=r"((r)[2]), "=r"((r)[3]) \
                 : "r"(addr))
#define LDSM4T(r, addr) \
    asm volatile("ldmatrix.sync.aligned.m8n8.x4.trans.shared.b16 " \
                 "{%0,%1,%2,%3}, [%4];" \
                 : "=r"((r)[0]), "=r"((r)[1]), "=r"((r)[2]), "=r"((r)[3]) \
                 : "r"(addr))

__device__ __forceinline__ unsigned sptr(const void* p) {
    return (unsigned)__cvta_generic_to_shared(p);
}
#define CP16(dst_s, src_g) \
    asm volatile("cp.async.cg.shared.global [%0], [%1], 16;" \
                 :: "r"(dst_s), "l"(src_g))

// mbarrier ops
#define MBAR_INIT(addr, cnt) \
    asm volatile("mbarrier.init.shared.b64 [%0], %1;" \
                 :: "r"(addr), "r"(cnt) : "memory")
#define MBAR_ARRIVE(addr) \
    asm volatile("mbarrier.arrive.shared::cta.b64 _, [%0];" \
                 :: "r"(addr) : "memory")
#define CP_MBAR_ARRIVE(addr) \
    asm volatile("cp.async.mbarrier.arrive.noinc.shared::cta.b64 [%0];" \
                 :: "r"(addr) : "memory")
#define MBAR_WAIT_PAR(addr, ph) do { \
    unsigned _d = 0; \
    while (!_d) { \
        asm volatile("{\n\t.reg .pred p;\n\t" \
            "mbarrier.try_wait.parity.acquire.cta.shared::cta.b64 p, [%1], %2, 0x989680;\n\t" \
            "selp.b32 %0, 1, 0, p;\n\t}" \
            : "=r"(_d) : "r"(addr), "r"(ph) : "memory"); \
    } \
} while (0)

__device__ __forceinline__ unsigned packh2(float lo, float hi) {
    __half2 h = __floats2half2_rn(lo, hi);
    return *reinterpret_cast<unsigned*>(&h);
}

__device__ __forceinline__ unsigned exp2_h2(float t0, float t1) {
    unsigned u = packh2(t0, t1);
    asm("ex2.approx.f16x2 %0, %1;" : "=r"(u) : "r"(u));
    return u;
}

// ---------------------------------------------------------------------------
// Merged elementwise fp32 -> fp16 for x, W_qkv, W_out (one launch)
// ---------------------------------------------------------------------------
#define NX4 ((NM * NE) / 8)
#define NW4 ((NQKV * NE) / 8)
#define NO4 ((NE * NE) / 8)
#define NCVT (NX4 + NW4 + NO4)

__global__ __launch_bounds__(256) void cvt_all(
    const float4* __restrict__ x,  const float4* __restrict__ wq,
    const float4* __restrict__ wo,
    uint4* __restrict__ xt, uint4* __restrict__ wqt, uint4* __restrict__ wot)
{
    int i = blockIdx.x * 256 + threadIdx.x;
    const float4* src;
    uint4* dst;
    int j;
    if (i < NX4)            { j = i;              src = x;  dst = xt;  }
    else if (i < NX4 + NW4) { j = i - NX4;        src = wq; dst = wqt; }
    else                    { j = i - NX4 - NW4;  src = wo; dst = wot; }
    float4 v0 = src[j * 2];
    float4 v1 = src[j * 2 + 1];
    uint4 u;
    u.x = packh2(v0.x, v0.y);
    u.y = packh2(v0.z, v0.w);
    u.z = packh2(v1.x, v1.y);
    u.w = packh2(v1.z, v1.w);
    dst[j] = u;
}

// ---------------------------------------------------------------------------
// FP16 NT GEMM + bias, decoupled ring-3 mbarrier pipeline (no __syncthreads
// in mainloop). 128x128 CTA tile, BK=64, 256 threads, warp grid 2x4,
// warp tile 64x32, paired-x4 W fragments, __launch_bounds__(256,2).
// smem: A[3]+W[3] bufs (110592 B) + mbarriers.
// ---------------------------------------------------------------------------
#define GBUF 18432                           // 128 * 144 bytes
#define GA_B  0                              // A bufs [3]
#define GW_B  (3 * GBUF)                     // W bufs [3]
#define GMB_B (6 * GBUF)                     // mbarriers: full[3], empty[3]
#define GEMM_SMEM_BYTES (6 * GBUF + 128)     // 110720

template <int OUT>
__global__ __launch_bounds__(256, 2) void gemm_h(
    const __half* __restrict__ A, const __half* __restrict__ W,
    const float* __restrict__ bias, void* __restrict__ Cv,
    int Mdim, int Ndim, int Kdim)
{
    extern __shared__ __align__(16) char smg[];
    const unsigned smem_u = sptr(smg);

    const int tid  = threadIdx.x;
    const int wid  = tid >> 5;
    const int lane = tid & 31;
    const int mg   = wid >> 2;
    const int ng   = wid & 3;
    const int bm   = blockIdx.y * 128;
    const int bn   = blockIdx.x * 128;
    const int lq   = lane >> 2;
    const int lr   = lane & 3;
    const int NT   = Kdim / 64;

    const unsigned offA = (mg * 64 + (lane & 15)) * 144 + (lane >> 4) * 16;
    const unsigned offW4 = (ng * 32 + ((lane >> 4) << 3) + (lane & 7)) * 144
                         + ((lane >> 3) & 1) * 16;

    const unsigned mb_full  = smem_u + GMB_B;        // 3 x 8B
    const unsigned mb_empty = smem_u + GMB_B + 24;   // 3 x 8B

    if (tid == 0) {
        #pragma unroll
        for (int j = 0; j < 3; j++) {
            MBAR_INIT(mb_full + j * 8, 256);
            MBAR_INIT(mb_empty + j * 8, 256);
        }
    }
    __syncthreads();

    float acc[4][4][4] = {};

    // fill K-chunk t (64 cols) into ring buffer t%3, signal full[t%3]
    auto fill = [&](int t) {
        const int bf = t % 3;
        const unsigned ad = smem_u + GA_B + bf * GBUF;
        const unsigned wd = smem_u + GW_B + bf * GBUF;
        const int kt = t * 64;
        #pragma unroll
        for (int i = 0; i < 4; i++) {
            int idx = i * 256 + tid;
            int row = idx >> 3;
            int seg = idx & 7;
            CP16(ad + row * 144 + seg * 16,
                 A + (size_t)(bm + row) * Kdim + kt + seg * 8);
            CP16(wd + row * 144 + seg * 16,
                 W + (size_t)(bn + row) * Kdim + kt + seg * 8);
        }
        CP_MBAR_ARRIVE(mb_full + bf * 8);
    };

    fill(0);
    fill(1);

    for (int t = 0; t < NT; t++) {
        const int bf = t % 3;

        // prefetch chunk t+2 into buffer (t+2)%3
        {
            int u = t + 2;
            if (u < NT) {
                if (u >= 3)
                    MBAR_WAIT_PAR(mb_empty + (u % 3) * 8, (u / 3 - 1) & 1);
                fill(u);
            }
        }

        MBAR_WAIT_PAR(mb_full + bf * 8, (t / 3) & 1);

        const unsigned abase = smem_u + GA_B + bf * GBUF + offA;
        const unsigned wbase = smem_u + GW_B + bf * GBUF + offW4;
        #pragma unroll
        for (int kc = 0; kc < 4; kc++) {
            unsigned a[4][4], b4[2][4];
            #pragma unroll
            for (int mt = 0; mt < 4; mt++)
                LDSM4(a[mt], abase + mt * 2304 + kc * 32);
            #pragma unroll
            for (int p = 0; p < 2; p++)
                LDSM4(b4[p], wbase + p * 2304 + kc * 32);
            #pragma unroll
            for (int mt = 0; mt < 4; mt++)
                #pragma unroll
                for (int nt = 0; nt < 4; nt++)
                    mma_f16(acc[mt][nt], a[mt],
                            &b4[nt >> 1][(nt & 1) * 2], acc[mt][nt]);
        }

        MBAR_ARRIVE(mb_empty + bf * 8);
    }

    // epilogue (accumulators are private; no barrier needed)
    #pragma unroll
    for (int mt = 0; mt < 4; mt++) {
        int r0 = bm + mg * 64 + mt * 16 + lq;
        #pragma unroll
        for (int nt = 0; nt < 4; nt++) {
            int col = bn + ng * 32 + nt * 8 + lr * 2;
            float2 bv = *(const float2*)&bias[col];
            float v00 = acc[mt][nt][0] + bv.x;
            float v01 = acc[mt][nt][1] + bv.y;
            float v10 = acc[mt][nt][2] + bv.x;
            float v11 = acc[mt][nt][3] + bv.y;
            if (OUT == 2) {
                __half* C = (__half*)Cv;
                *(unsigned*)&C[(size_t)r0 * Ndim + col]       = packh2(v00, v01);
                *(unsigned*)&C[(size_t)(r0 + 8) * Ndim + col] = packh2(v10, v11);
            } else {
                float* C = (float*)Cv;
                *(float2*)&C[(size_t)r0 * Ndim + col]       = make_float2(v00, v01);
                *(float2*)&C[(size_t)(r0 + 8) * Ndim + col] = make_float2(v10, v11);
            }
        }
    }
}

// ---------------------------------------------------------------------------
// Flash attention v4 (round-14, unchanged): 2 CTAs/SM, 256 threads = 8 warps,
// warp grid 4(m) x 2(n), warp tile 16 q-rows x 64 keys, K/V ring of 2,
// hoisted Q fragments, decoupled mbarrier pipeline.
// ---------------------------------------------------------------------------
#define AQ_B   0                       // Q [64][72] fp16 = 9216 B
#define AK_B   9216                    // K [2][128][72] = 36864 B
#define AV_B   46080                   // V [2][128][72] = 36864 B
#define ARM_B  82944                   // m float [2][64]
#define ARS_B  83456                   // l float [2][64]
#define AMB_B  83968                   // mbarriers: full[2], empty[2]
#define ATTN_SMEM_BYTES 84096
#define ATHREADS 256
#define NTILES (NS / 128)              // 16 key tiles
#define L2E 1.44269504f

__global__ __launch_bounds__(ATHREADS, 2) void attn_f16(
    const __half* __restrict__ qkv, __half* __restrict__ ctx)
{
    extern __shared__ __align__(16) char smc[];
    const unsigned smem_u = sptr(smc);
    __half* Qs = (__half*)(smc + AQ_B);

    const int tid  = threadIdx.x;
    const int wid  = tid >> 5;
    const int lane = tid & 31;
    const int mg   = wid >> 1;
    const int ng   = wid & 1;
    const int lq   = lane >> 2;
    const int lr   = lane & 3;
    const int q0   = blockIdx.x * 64;
    const int h    = blockIdx.y;
    const int b    = blockIdx.z;

    const __half* base  = qkv + (size_t)b * NS * NQKV + h * (3 * NHD);
    const __half* kbase = base + NHD;
    const __half* vbase = base + 2 * NHD;

    const unsigned offQ  = AQ_B + (mg * 16 + (lane & 15)) * 144 + (lane >> 4) * 16;
    const unsigned offK4 = (ng * 64 + ((lane >> 4) << 3) + (lane & 7)) * 144
                         + ((lane >> 3) & 1) * 16;
    const unsigned offV  = (ng * 64 + (lane & 15)) * 144 + (lane >> 4) * 16;

    const unsigned mb_full  = smem_u + AMB_B;
    const unsigned mb_empty = smem_u + AMB_B + 16;

    if (tid == 0) {
        #pragma unroll
        for (int j = 0; j < 2; j++) {
            MBAR_INIT(mb_full + j * 8, ATHREADS);
            MBAR_INIT(mb_empty + j * 8, ATHREADS);
        }
    }
    __syncthreads();

    auto fill = [&](int t) {
        const int bf = t & 1;
        const unsigned kd = smem_u + AK_B + bf * 18432;
        const unsigned vd = smem_u + AV_B + bf * 18432;
        #pragma unroll
        for (int i = 0; i < 4; i++) {
            int idx = i * ATHREADS + tid;
            int row = idx >> 3;
            int seg = idx & 7;
            CP16(kd + row * 144 + seg * 16,
                 kbase + (size_t)(t * 128 + row) * NQKV + seg * 8);
            CP16(vd + row * 144 + seg * 16,
                 vbase + (size_t)(t * 128 + row) * NQKV + seg * 8);
        }
        CP_MBAR_ARRIVE(mb_full + bf * 8);
    };

    fill(0);
    fill(1);

    // Q fill with 0.125 scale (exact in fp16)
    {
        const __half2 sc = __floats2half2_rn(0.125f, 0.125f);
        #pragma unroll
        for (int i = 0; i < 2; i++) {
            int idx = i * ATHREADS + tid;
            int row = idx >> 3;
            int seg = idx & 7;
            uint4 v = *(const uint4*)(base + (size_t)(q0 + row) * NQKV + seg * 8);
            __half2* p = (__half2*)&v;
            p[0] = __hmul2(p[0], sc);
            p[1] = __hmul2(p[1], sc);
            p[2] = __hmul2(p[2], sc);
            p[3] = __hmul2(p[3], sc);
            *(uint4*)(Qs + row * 72 + seg * 8) = v;
        }
    }
    __syncthreads();   // Q visible

    unsigned aq[4][4];
    {
        const unsigned qb = smem_u + offQ;
        #pragma unroll
        for (int kc = 0; kc < 4; kc++)
            LDSM4(aq[kc], qb + kc * 32);
    }

    float o[8][4] = {};
    float osum[4] = {};
    float m_run[2] = {-1e30f, -1e30f};

    for (int t = 0; t < NTILES; t++) {
        const int bf = t & 1;

        MBAR_WAIT_PAR(mb_full + bf * 8, (t >> 1) & 1);

        const unsigned kb = smem_u + AK_B + bf * 18432 + offK4;
        const unsigned vb = smem_u + AV_B + bf * 18432 + offV;

        float s[8][4] = {};
        #pragma unroll
        for (int kc = 0; kc < 4; kc++) {
            unsigned kf[4][4];
            #pragma unroll
            for (int p = 0; p < 4; p++)
                LDSM4(kf[p], kb + p * 2304 + kc * 32);
            #pragma unroll
            for (int nt = 0; nt < 8; nt++)
                mma_f16(s[nt], aq[kc],
                        &kf[nt >> 1][(nt & 1) * 2], s[nt]);
        }

        unsigned pf[8][2];
        #pragma unroll
        for (int hf = 0; hf < 2; hf++) {
            float v = -1e30f;
            #pragma unroll
            for (int nt = 0; nt < 8; nt++) {
                v = fmaxf(v, s[nt][hf * 2 + 0]);
                v = fmaxf(v, s[nt][hf * 2 + 1]);
            }
            v = fmaxf(v, __shfl_xor_sync(0xffffffffu, v, 1));
            v = fmaxf(v, __shfl_xor_sync(0xffffffffu, v, 2));
            float m_new = fmaxf(m_run[hf], v);
            float corr  = __expf(m_run[hf] - m_new);
            m_run[hf] = m_new;
            float mb = m_new * L2E;
            #pragma unroll
            for (int nt = 0; nt < 8; nt++) {
                float t0 = fmaf(s[nt][hf * 2 + 0], L2E, -mb);
                float t1 = fmaf(s[nt][hf * 2 + 1], L2E, -mb);
                pf[nt][hf] = exp2_h2(t0, t1);
            }
            #pragma unroll
            for (int nt = 0; nt < 8; nt++) {
                o[nt][hf * 2 + 0] *= corr;
                o[nt][hf * 2 + 1] *= corr;
            }
            osum[hf * 2 + 0] *= corr;
            osum[hf * 2 + 1] *= corr;
        }

        const unsigned ONES2 = 0x3C003C00u;
        unsigned bo[2] = {ONES2, ONES2};
        #pragma unroll
        for (int kc = 0; kc < 4; kc++) {
            unsigned a[4];
            a[0] = pf[2 * kc + 0][0];
            a[1] = pf[2 * kc + 0][1];
            a[2] = pf[2 * kc + 1][0];
            a[3] = pf[2 * kc + 1][1];
            #pragma unroll
            for (int np = 0; np < 4; np++) {
                unsigned vf[4];
                LDSM4T(vf, vb + kc * 2304 + np * 32);
                mma_f16(o[2 * np + 0], a, &vf[0], o[2 * np + 0]);
                mma_f16(o[2 * np + 1], a, &vf[2], o[2 * np + 1]);
            }
            mma_f16(osum, a, bo, osum);
        }

        MBAR_ARRIVE(mb_empty + bf * 8);

        {
            int u = t + 2;
            if (u < NTILES) {
                MBAR_WAIT_PAR(mb_empty + (u & 1) * 8, ((u >> 1) - 1) & 1);
                fill(u);
            }
        }
    }

    // epilogue: merge key-slices, normalize, store fp16 ctx
    __syncthreads();
    float* rm = (float*)(smc + ARM_B);
    float* rl = (float*)(smc + ARS_B);
    if (lr == 0) {
        int r = mg * 16 + lq;
        rm[ng * 64 + r]     = m_run[0];
        rm[ng * 64 + r + 8] = m_run[1];
        rl[ng * 64 + r]     = osum[0];
        rl[ng * 64 + r + 8] = osum[2];
    }
    __syncthreads();

    float fsc[2], linv[2];
    #pragma unroll
    for (int hf = 0; hf < 2; hf++) {
        int row = mg * 16 + hf * 8 + lq;
        float m0 = rm[row], m1 = rm[64 + row];
        float m_tot = fmaxf(m0, m1);
        float l_tot = rl[row] * __expf(m0 - m_tot)
                    + rl[64 + row] * __expf(m1 - m_tot);
        fsc[hf]  = __expf(m_run[hf] - m_tot);
        linv[hf] = 1.0f / l_tot;
    }

    float* Os = (float*)(smc + AK_B);
    if (ng == 1) {
        int r = mg * 16 + lq;
        #pragma unroll
        for (int nt = 0; nt < 8; nt++) {
            int d = nt * 8 + lr * 2;
            *(float2*)&Os[r * 68 + d] =
                make_float2(o[nt][0] * fsc[0], o[nt][1] * fsc[0]);
            *(float2*)&Os[(r + 8) * 68 + d] =
                make_float2(o[nt][2] * fsc[1], o[nt][3] * fsc[1]);
        }
    }
    __syncthreads();
    if (ng == 0) {
        int r = mg * 16 + lq;
        #pragma unroll
        for (int nt = 0; nt < 8; nt++) {
            int d = nt * 8 + lr * 2;
            float2 p0 = *(const float2*)&Os[r * 68 + d];
            float2 p1 = *(const float2*)&Os[(r + 8) * 68 + d];
            unsigned u0 = packh2((o[nt][0] * fsc[0] + p0.x) * linv[0],
                                 (o[nt][1] * fsc[0] + p0.y) * linv[0]);
            unsigned u1 = packh2((o[nt][2] * fsc[1] + p1.x) * linv[1],
                                 (o[nt][3] * fsc[1] + p1.y) * linv[1]);
            size_t g0 = ((size_t)b * NS + q0 + r) * NE + h * NHD + d;
            size_t g1 = ((size_t)b * NS + q0 + r + 8) * NE + h * NHD + d;
            *(unsigned*)&ctx[g0] = u0;
            *(unsigned*)&ctx[g1] = u1;
        }
    }
}

// ---------------------------------------------------------------------------
extern "C" void kernel_launch(void* const* d_in, const int* in_sizes, int n_in,
                              void* d_out, int out_size)
{
    const float* x     = (const float*)d_in[0];
    const float* W_qkv = (const float*)d_in[1];
    const float* b_qkv = (const float*)d_in[2];
    const float* W_out = (const float*)d_in[3];
    const float* b_out = (const float*)d_in[4];
    float* out = (float*)d_out;

    __half *qkv, *ctx, *xt, *wqkvt, *wot;
    cudaGetSymbolAddress((void**)&qkv,   g_qkv);
    cudaGetSymbolAddress((void**)&ctx,   g_ctx);
    cudaGetSymbolAddress((void**)&xt,    g_xt);
    cudaGetSymbolAddress((void**)&wqkvt, g_wqkvt);
    cudaGetSymbolAddress((void**)&wot,   g_wot);

    cudaFuncSetAttribute(gemm_h<2>,
                         cudaFuncAttributeMaxDynamicSharedMemorySize,
                         GEMM_SMEM_BYTES);
    cudaFuncSetAttribute(gemm_h<0>,
                         cudaFuncAttributeMaxDynamicSharedMemorySize,
                         GEMM_SMEM_BYTES);
    cudaFuncSetAttribute(attn_f16,
                         cudaFuncAttributeMaxDynamicSharedMemorySize,
                         ATTN_SMEM_BYTES);

    // 0) pre-convert inputs to fp16 (single merged launch)
    cvt_all<<<NCVT / 256, 256>>>((const float4*)x, (const float4*)W_qkv,
                                 (const float4*)W_out,
                                 (uint4*)xt, (uint4*)wqkvt, (uint4*)wot);

    // 1) QKV projection (fp16 math, fp32 accum, fp16 out)
    dim3 g1(NQKV / 128, NM / 128);
    gemm_h<2><<<g1, 256, GEMM_SMEM_BYTES>>>(xt, wqkvt, b_qkv, qkv,
                                            NM, NQKV, NE);

    // 2) Flash attention (fp16 tensor cores, 2 CTAs/SM)
    dim3 g2(NS / 64, NH, NB);
    attn_f16<<<g2, ATHREADS, ATTN_SMEM_BYTES>>>(qkv, ctx);

    // 3) Output projection (fp16 math, fp32 accum, fp32 out)
    dim3 g3(NE / 128, NM / 128);
    gemm_h<0><<<g3, 256, GEMM_SMEM_BYTES>>>(ctx, wot, b_out, out,
                                            NM, NE, NE);
}

// round 16
// speedup vs baseline: 8.8189x; 1.0078x over previous
#include <cuda_runtime.h>
#include <cuda_fp16.h>

// Problem constants
#define NB 2
#define NS 2048
#define NE 1024
#define NH 16
#define NHD 64
#define NM (NB * NS)      // 4096
#define NQKV (3 * NE)     // 3072

// Scratch (allocation-free rule: __device__ globals). All fp16.
__device__ __half g_qkv[(size_t)NM * NQKV];    // 24 MB
__device__ __half g_ctx[(size_t)NM * NE];      // 8 MB
__device__ __half g_xt[(size_t)NM * NE];       // 8 MB
__device__ __half g_wqkvt[(size_t)NQKV * NE];  // 6 MB
__device__ __half g_wot[(size_t)NE * NE];      // 2 MB

// ---------------------------------------------------------------------------
// helpers
// ---------------------------------------------------------------------------
__device__ __forceinline__ void mma_f16(float* d, const unsigned* a,
                                        const unsigned* b, const float* c) {
    asm volatile(
        "mma.sync.aligned.m16n8k16.row.col.f32.f16.f16.f32 "
        "{%0,%1,%2,%3}, {%4,%5,%6,%7}, {%8,%9}, {%10,%11,%12,%13};"
        : "=f"(d[0]), "=f"(d[1]), "=f"(d[2]), "=f"(d[3])
        : "r"(a[0]), "r"(a[1]), "r"(a[2]), "r"(a[3]),
          "r"(b[0]), "r"(b[1]),
          "f"(c[0]), "f"(c[1]), "f"(c[2]), "f"(c[3]));
}

#define LDSM4(r, addr) \
    asm volatile("ldmatrix.sync.aligned.m8n8.x4.shared.b16 " \
                 "{%0,%1,%2,%3}, [%4];" \
                 : "=r"((r)[0]), "=r"((r)[1]), "=r"((r)[2]), "=r"((r)[3]) \
                 : "r"(addr))
#define LDSM4T(r, addr) \
    asm volatile("ldmatrix.sync.aligned.m8n8.x4.trans.shared.b16 " \
                 "{%0,%1,%2,%3}, [%4];" \
                 : "=r"((r)[0]), "=r"((r)[1]), "=r"((r)[2]), "=r"((r)[3]) \
                 : "r"(addr))

__device__ __forceinline__ unsigned sptr(const void* p) {
    return (unsigned)__cvta_generic_to_shared(p);
}
#define CP16(dst_s, src_g) \
    asm volatile("cp.async.cg.shared.global [%0], [%1], 16;" \
                 :: "r"(dst_s), "l"(src_g))

// mbarrier ops
#define MBAR_INIT(addr, cnt) \
    asm volatile("mbarrier.init.shared.b64 [%0], %1;" \
                 :: "r"(addr), "r"(cnt) : "memory")
#define MBAR_ARRIVE(addr) \
    asm volatile("mbarrier.arrive.shared::cta.b64 _, [%0];" \
                 :: "r"(addr) : "memory")
#define CP_MBAR_ARRIVE(addr) \
    asm volatile("cp.async.mbarrier.arrive.noinc.shared::cta.b64 [%0];" \
                 :: "r"(addr) : "memory")
#define MBAR_WAIT_PAR(addr, ph) do { \
    unsigned _d = 0; \
    while (!_d) { \
        asm volatile("{\n\t.reg .pred p;\n\t" \
            "mbarrier.try_wait.parity.acquire.cta.shared::cta.b64 p, [%1], %2, 0x989680;\n\t" \
            "selp.b32 %0, 1, 0, p;\n\t}" \
            : "=r"(_d) : "r"(addr), "r"(ph) : "memory"); \
    } \
} while (0)

__device__ __forceinline__ unsigned packh2(float lo, float hi) {
    __half2 h = __floats2half2_rn(lo, hi);
    return *reinterpret_cast<unsigned*>(&h);
}

__device__ __forceinline__ unsigned exp2_h2(float t0, float t1) {
    unsigned u = packh2(t0, t1);
    asm("ex2.approx.f16x2 %0, %1;" : "=r"(u) : "r"(u));
    return u;
}

// ---------------------------------------------------------------------------
// Merged elementwise fp32 -> fp16 for x, W_qkv, W_out (one launch)
// ---------------------------------------------------------------------------
#define NX4 ((NM * NE) / 8)
#define NW4 ((NQKV * NE) / 8)
#define NO4 ((NE * NE) / 8)
#define NCVT (NX4 + NW4 + NO4)

__global__ __launch_bounds__(256) void cvt_all(
    const float4* __restrict__ x,  const float4* __restrict__ wq,
    const float4* __restrict__ wo,
    uint4* __restrict__ xt, uint4* __restrict__ wqt, uint4* __restrict__ wot)
{
    int i = blockIdx.x * 256 + threadIdx.x;
    const float4* src;
    uint4* dst;
    int j;
    if (i < NX4)            { j = i;              src = x;  dst = xt;  }
    else if (i < NX4 + NW4) { j = i - NX4;        src = wq; dst = wqt; }
    else                    { j = i - NX4 - NW4;  src = wo; dst = wot; }
    float4 v0 = src[j * 2];
    float4 v1 = src[j * 2 + 1];
    uint4 u;
    u.x = packh2(v0.x, v0.y);
    u.y = packh2(v0.z, v0.w);
    u.z = packh2(v1.x, v1.y);
    u.w = packh2(v1.z, v1.w);
    dst[j] = u;
}

// ---------------------------------------------------------------------------
// FP16 NT GEMM + bias, decoupled ring-3 mbarrier pipeline (round-15 proven).
// 128x128 CTA tile, BK=64, 256 threads, warp grid 2x4, warp tile 64x32,
// paired-x4 W fragments, __launch_bounds__(256,2).
// ---------------------------------------------------------------------------
#define GBUF 18432                           // 128 * 144 bytes
#define GA_B  0                              // A bufs [3]
#define GW_B  (3 * GBUF)                     // W bufs [3]
#define GMB_B (6 * GBUF)                     // mbarriers: full[3], empty[3]
#define GEMM_SMEM_BYTES (6 * GBUF + 128)     // 110720

template <int OUT>
__global__ __launch_bounds__(256, 2) void gemm_h(
    const __half* __restrict__ A, const __half* __restrict__ W,
    const float* __restrict__ bias, void* __restrict__ Cv,
    int Mdim, int Ndim, int Kdim)
{
    extern __shared__ __align__(16) char smg[];
    const unsigned smem_u = sptr(smg);

    const int tid  = threadIdx.x;
    const int wid  = tid >> 5;
    const int lane = tid & 31;
    const int mg   = wid >> 2;
    const int ng   = wid & 3;
    const int bm   = blockIdx.y * 128;
    const int bn   = blockIdx.x * 128;
    const int lq   = lane >> 2;
    const int lr   = lane & 3;
    const int NT   = Kdim / 64;

    const unsigned offA = (mg * 64 + (lane & 15)) * 144 + (lane >> 4) * 16;
    const unsigned offW4 = (ng * 32 + ((lane >> 4) << 3) + (lane & 7)) * 144
                         + ((lane >> 3) & 1) * 16;

    const unsigned mb_full  = smem_u + GMB_B;        // 3 x 8B
    const unsigned mb_empty = smem_u + GMB_B + 24;   // 3 x 8B

    if (tid == 0) {
        #pragma unroll
        for (int j = 0; j < 3; j++) {
            MBAR_INIT(mb_full + j * 8, 256);
            MBAR_INIT(mb_empty + j * 8, 256);
        }
    }
    __syncthreads();

    float acc[4][4][4] = {};

    auto fill = [&](int t) {
        const int bf = t % 3;
        const unsigned ad = smem_u + GA_B + bf * GBUF;
        const unsigned wd = smem_u + GW_B + bf * GBUF;
        const int kt = t * 64;
        #pragma unroll
        for (int i = 0; i < 4; i++) {
            int idx = i * 256 + tid;
            int row = idx >> 3;
            int seg = idx & 7;
            CP16(ad + row * 144 + seg * 16,
                 A + (size_t)(bm + row) * Kdim + kt + seg * 8);
            CP16(wd + row * 144 + seg * 16,
                 W + (size_t)(bn + row) * Kdim + kt + seg * 8);
        }
        CP_MBAR_ARRIVE(mb_full + bf * 8);
    };

    fill(0);
    fill(1);

    for (int t = 0; t < NT; t++) {
        const int bf = t % 3;

        {
            int u = t + 2;
            if (u < NT) {
                if (u >= 3)
                    MBAR_WAIT_PAR(mb_empty + (u % 3) * 8, (u / 3 - 1) & 1);
                fill(u);
            }
        }

        MBAR_WAIT_PAR(mb_full + bf * 8, (t / 3) & 1);

        const unsigned abase = smem_u + GA_B + bf * GBUF + offA;
        const unsigned wbase = smem_u + GW_B + bf * GBUF + offW4;
        #pragma unroll
        for (int kc = 0; kc < 4; kc++) {
            unsigned a[4][4], b4[2][4];
            #pragma unroll
            for (int mt = 0; mt < 4; mt++)
                LDSM4(a[mt], abase + mt * 2304 + kc * 32);
            #pragma unroll
            for (int p = 0; p < 2; p++)
                LDSM4(b4[p], wbase + p * 2304 + kc * 32);
            #pragma unroll
            for (int mt = 0; mt < 4; mt++)
                #pragma unroll
                for (int nt = 0; nt < 4; nt++)
                    mma_f16(acc[mt][nt], a[mt],
                            &b4[nt >> 1][(nt & 1) * 2], acc[mt][nt]);
        }

        MBAR_ARRIVE(mb_empty + bf * 8);
    }

    #pragma unroll
    for (int mt = 0; mt < 4; mt++) {
        int r0 = bm + mg * 64 + mt * 16 + lq;
        #pragma unroll
        for (int nt = 0; nt < 4; nt++) {
            int col = bn + ng * 32 + nt * 8 + lr * 2;
            float2 bv = *(const float2*)&bias[col];
            float v00 = acc[mt][nt][0] + bv.x;
            float v01 = acc[mt][nt][1] + bv.y;
            float v10 = acc[mt][nt][2] + bv.x;
            float v11 = acc[mt][nt][3] + bv.y;
            if (OUT == 2) {
                __half* C = (__half*)Cv;
                *(unsigned*)&C[(size_t)r0 * Ndim + col]       = packh2(v00, v01);
                *(unsigned*)&C[(size_t)(r0 + 8) * Ndim + col] = packh2(v10, v11);
            } else {
                float* C = (float*)Cv;
                *(float2*)&C[(size_t)r0 * Ndim + col]       = make_float2(v00, v01);
                *(float2*)&C[(size_t)(r0 + 8) * Ndim + col] = make_float2(v10, v11);
            }
        }
    }
}

// ---------------------------------------------------------------------------
// Flash attention v5: round-14 structure (2 CTAs/SM, 8 warps, 16 q-rows x
// 64 keys per warp, K/V ring of 2, hoisted Q frags, mbarrier pipeline),
// with the ones-column row-sum MMA replaced by an ALU reduction over pf
// (tensor pipe is the binding resource; FMA/ALU are idle).
// ---------------------------------------------------------------------------
#define AQ_B   0                       // Q [64][72] fp16 = 9216 B
#define AK_B   9216                    // K [2][128][72] = 36864 B
#define AV_B   46080                   // V [2][128][72] = 36864 B
#define ARM_B  82944                   // m float [2][64]
#define ARS_B  83456                   // l float [2][64]
#define AMB_B  83968                   // mbarriers: full[2], empty[2]
#define ATTN_SMEM_BYTES 84096
#define ATHREADS 256
#define NTILES (NS / 128)              // 16 key tiles
#define L2E 1.44269504f

__global__ __launch_bounds__(ATHREADS, 2) void attn_f16(
    const __half* __restrict__ qkv, __half* __restrict__ ctx)
{
    extern __shared__ __align__(16) char smc[];
    const unsigned smem_u = sptr(smc);
    __half* Qs = (__half*)(smc + AQ_B);

    const int tid  = threadIdx.x;
    const int wid  = tid >> 5;
    const int lane = tid & 31;
    const int mg   = wid >> 1;
    const int ng   = wid & 1;
    const int lq   = lane >> 2;
    const int lr   = lane & 3;
    const int q0   = blockIdx.x * 64;
    const int h    = blockIdx.y;
    const int b    = blockIdx.z;

    const __half* base  = qkv + (size_t)b * NS * NQKV + h * (3 * NHD);
    const __half* kbase = base + NHD;
    const __half* vbase = base + 2 * NHD;

    const unsigned offQ  = AQ_B + (mg * 16 + (lane & 15)) * 144 + (lane >> 4) * 16;
    const unsigned offK4 = (ng * 64 + ((lane >> 4) << 3) + (lane & 7)) * 144
                         + ((lane >> 3) & 1) * 16;
    const unsigned offV  = (ng * 64 + (lane & 15)) * 144 + (lane >> 4) * 16;

    const unsigned mb_full  = smem_u + AMB_B;
    const unsigned mb_empty = smem_u + AMB_B + 16;

    if (tid == 0) {
        #pragma unroll
        for (int j = 0; j < 2; j++) {
            MBAR_INIT(mb_full + j * 8, ATHREADS);
            MBAR_INIT(mb_empty + j * 8, ATHREADS);
        }
    }
    __syncthreads();

    auto fill = [&](int t) {
        const int bf = t & 1;
        const unsigned kd = smem_u + AK_B + bf * 18432;
        const unsigned vd = smem_u + AV_B + bf * 18432;
        #pragma unroll
        for (int i = 0; i < 4; i++) {
            int idx = i * ATHREADS + tid;
            int row = idx >> 3;
            int seg = idx & 7;
            CP16(kd + row * 144 + seg * 16,
                 kbase + (size_t)(t * 128 + row) * NQKV + seg * 8);
            CP16(vd + row * 144 + seg * 16,
                 vbase + (size_t)(t * 128 + row) * NQKV + seg * 8);
        }
        CP_MBAR_ARRIVE(mb_full + bf * 8);
    };

    fill(0);
    fill(1);

    // Q fill with 0.125 scale (exact in fp16)
    {
        const __half2 sc = __floats2half2_rn(0.125f, 0.125f);
        #pragma unroll
        for (int i = 0; i < 2; i++) {
            int idx = i * ATHREADS + tid;
            int row = idx >> 3;
            int seg = idx & 7;
            uint4 v = *(const uint4*)(base + (size_t)(q0 + row) * NQKV + seg * 8);
            __half2* p = (__half2*)&v;
            p[0] = __hmul2(p[0], sc);
            p[1] = __hmul2(p[1], sc);
            p[2] = __hmul2(p[2], sc);
            p[3] = __hmul2(p[3], sc);
            *(uint4*)(Qs + row * 72 + seg * 8) = v;
        }
    }
    __syncthreads();   // Q visible

    unsigned aq[4][4];
    {
        const unsigned qb = smem_u + offQ;
        #pragma unroll
        for (int kc = 0; kc < 4; kc++)
            LDSM4(aq[kc], qb + kc * 32);
    }

    float o[8][4] = {};
    float m_run[2] = {-1e30f, -1e30f};
    float l_run[2] = {0.f, 0.f};

    for (int t = 0; t < NTILES; t++) {
        const int bf = t & 1;

        MBAR_WAIT_PAR(mb_full + bf * 8, (t >> 1) & 1);

        const unsigned kb = smem_u + AK_B + bf * 18432 + offK4;
        const unsigned vb = smem_u + AV_B + bf * 18432 + offV;

        // ---- QK^T (fp16 k16): 16 q-rows x 64 keys per warp ----
        float s[8][4] = {};
        #pragma unroll
        for (int kc = 0; kc < 4; kc++) {
            unsigned kf[4][4];
            #pragma unroll
            for (int p = 0; p < 4; p++)
                LDSM4(kf[p], kb + p * 2304 + kc * 32);
            #pragma unroll
            for (int nt = 0; nt < 8; nt++)
                mma_f16(s[nt], aq[kc],
                        &kf[nt >> 1][(nt & 1) * 2], s[nt]);
        }

        // ---- softmax: max + fp16x2 exp2 -> packed P frags; ALU row sum ----
        unsigned pf[8][2];
        #pragma unroll
        for (int hf = 0; hf < 2; hf++) {
            float v = -1e30f;
            #pragma unroll
            for (int nt = 0; nt < 8; nt++) {
                v = fmaxf(v, s[nt][hf * 2 + 0]);
                v = fmaxf(v, s[nt][hf * 2 + 1]);
            }
            v = fmaxf(v, __shfl_xor_sync(0xffffffffu, v, 1));
            v = fmaxf(v, __shfl_xor_sync(0xffffffffu, v, 2));
            float m_new = fmaxf(m_run[hf], v);
            float corr  = __expf(m_run[hf] - m_new);
            m_run[hf] = m_new;
            float mb = m_new * L2E;
            float rs = 0.f;
            #pragma unroll
            for (int nt = 0; nt < 8; nt++) {
                float t0 = fmaf(s[nt][hf * 2 + 0], L2E, -mb);
                float t1 = fmaf(s[nt][hf * 2 + 1], L2E, -mb);
                unsigned pp = exp2_h2(t0, t1);
                pf[nt][hf] = pp;
                float2 f = __half22float2(*reinterpret_cast<__half2*>(&pp));
                rs += f.x + f.y;
            }
            rs += __shfl_xor_sync(0xffffffffu, rs, 1);
            rs += __shfl_xor_sync(0xffffffffu, rs, 2);
            l_run[hf] = l_run[hf] * corr + rs;
            #pragma unroll
            for (int nt = 0; nt < 8; nt++) {
                o[nt][hf * 2 + 0] *= corr;
                o[nt][hf * 2 + 1] *= corr;
            }
        }

        // ---- PV (fp16 k16) ----
        #pragma unroll
        for (int kc = 0; kc < 4; kc++) {
            unsigned a[4];
            a[0] = pf[2 * kc + 0][0];
            a[1] = pf[2 * kc + 0][1];
            a[2] = pf[2 * kc + 1][0];
            a[3] = pf[2 * kc + 1][1];
            #pragma unroll
            for (int np = 0; np < 4; np++) {
                unsigned vf[4];
                LDSM4T(vf, vb + kc * 2304 + np * 32);
                mma_f16(o[2 * np + 0], a, &vf[0], o[2 * np + 0]);
                mma_f16(o[2 * np + 1], a, &vf[2], o[2 * np + 1]);
            }
        }

        MBAR_ARRIVE(mb_empty + bf * 8);

        {
            int u = t + 2;
            if (u < NTILES) {
                MBAR_WAIT_PAR(mb_empty + (u & 1) * 8, ((u >> 1) - 1) & 1);
                fill(u);
            }
        }
    }

    // ---- epilogue: merge the two key-slices, normalize, store fp16 ctx ----
    __syncthreads();
    float* rm = (float*)(smc + ARM_B);   // [ng][64]
    float* rl = (float*)(smc + ARS_B);
    if (lr == 0) {
        int r = mg * 16 + lq;
        rm[ng * 64 + r]     = m_run[0];
        rm[ng * 64 + r + 8] = m_run[1];
        rl[ng * 64 + r]     = l_run[0];
        rl[ng * 64 + r + 8] = l_run[1];
    }
    __syncthreads();

    float fsc[2], linv[2];
    #pragma unroll
    for (int hf = 0; hf < 2; hf++) {
        int row = mg * 16 + hf * 8 + lq;
        float m0 = rm[row], m1 = rm[64 + row];
        float m_tot = fmaxf(m0, m1);
        float l_tot = rl[row] * __expf(m0 - m_tot)
                    + rl[64 + row] * __expf(m1 - m_tot);
        fsc[hf]  = __expf(m_run[hf] - m_tot);
        linv[hf] = 1.0f / l_tot;
    }

    float* Os = (float*)(smc + AK_B);    // [64][68] floats, aliases K buf0
    if (ng == 1) {
        int r = mg * 16 + lq;
        #pragma unroll
        for (int nt = 0; nt < 8; nt++) {
            int d = nt * 8 + lr * 2;
            *(float2*)&Os[r * 68 + d] =
                make_float2(o[nt][0] * fsc[0], o[nt][1] * fsc[0]);
            *(float2*)&Os[(r + 8) * 68 + d] =
                make_float2(o[nt][2] * fsc[1], o[nt][3] * fsc[1]);
        }
    }
    __syncthreads();
    if (ng == 0) {
        int r = mg * 16 + lq;
        #pragma unroll
        for (int nt = 0; nt < 8; nt++) {
            int d = nt * 8 + lr * 2;
            float2 p0 = *(const float2*)&Os[r * 68 + d];
            float2 p1 = *(const float2*)&Os[(r + 8) * 68 + d];
            unsigned u0 = packh2((o[nt][0] * fsc[0] + p0.x) * linv[0],
                                 (o[nt][1] * fsc[0] + p0.y) * linv[0]);
            unsigned u1 = packh2((o[nt][2] * fsc[1] + p1.x) * linv[1],
                                 (o[nt][3] * fsc[1] + p1.y) * linv[1]);
            size_t g0 = ((size_t)b * NS + q0 + r) * NE + h * NHD + d;
            size_t g1 = ((size_t)b * NS + q0 + r + 8) * NE + h * NHD + d;
            *(unsigned*)&ctx[g0] = u0;
            *(unsigned*)&ctx[g1] = u1;
        }
    }
}

// ---------------------------------------------------------------------------
extern "C" void kernel_launch(void* const* d_in, const int* in_sizes, int n_in,
                              void* d_out, int out_size)
{
    const float* x     = (const float*)d_in[0];
    const float* W_qkv = (const float*)d_in[1];
    const float* b_qkv = (const float*)d_in[2];
    const float* W_out = (const float*)d_in[3];
    const float* b_out = (const float*)d_in[4];
    float* out = (float*)d_out;

    __half *qkv, *ctx, *xt, *wqkvt, *wot;
    cudaGetSymbolAddress((void**)&qkv,   g_qkv);
    cudaGetSymbolAddress((void**)&ctx,   g_ctx);
    cudaGetSymbolAddress((void**)&xt,    g_xt);
    cudaGetSymbolAddress((void**)&wqkvt, g_wqkvt);
    cudaGetSymbolAddress((void**)&wot,   g_wot);

    cudaFuncSetAttribute(gemm_h<2>,
                         cudaFuncAttributeMaxDynamicSharedMemorySize,
                         GEMM_SMEM_BYTES);
    cudaFuncSetAttribute(gemm_h<0>,
                         cudaFuncAttributeMaxDynamicSharedMemorySize,
                         GEMM_SMEM_BYTES);
    cudaFuncSetAttribute(attn_f16,
                         cudaFuncAttributeMaxDynamicSharedMemorySize,
                         ATTN_SMEM_BYTES);

    // 0) pre-convert inputs to fp16 (single merged launch)
    cvt_all<<<NCVT / 256, 256>>>((const float4*)x, (const float4*)W_qkv,
                                 (const float4*)W_out,
                                 (uint4*)xt, (uint4*)wqkvt, (uint4*)wot);

    // 1) QKV projection (fp16 math, fp32 accum, fp16 out)
    dim3 g1(NQKV / 128, NM / 128);
    gemm_h<2><<<g1, 256, GEMM_SMEM_BYTES>>>(xt, wqkvt, b_qkv, qkv,
                                            NM, NQKV, NE);

    // 2) Flash attention (fp16 tensor cores, 2 CTAs/SM)
    dim3 g2(NS / 64, NH, NB);
    attn_f16<<<g2, ATHREADS, ATTN_SMEM_BYTES>>>(qkv, ctx);

    // 3) Output projection (fp16 math, fp32 accum, fp32 out)
    dim3 g3(NE / 128, NM / 128);
    gemm_h<0><<<g3, 256, GEMM_SMEM_BYTES>>>(ctx, wot, b_out, out,
                                            NM, NE, NE);
}